// round 8
// baseline (speedup 1.0000x reference)
#include <cuda_runtime.h>
#include <cuda_bf16.h>
#include <cstdint>

// Problem constants
#define B_   4
#define T_   2048
#define C_   1024
#define H_   16
#define HD_  64
#define M_   (B_ * T_)          // 8192
#define C3_  (3 * C_)           // 3072

// ---------------------------------------------------------------------------
// Scratch (device globals)
// ---------------------------------------------------------------------------
__device__ __nv_bfloat16 g_xh [(size_t)M_  * C_], g_xl [(size_t)M_  * C_];
__device__ __nv_bfloat16 g_wqh[(size_t)C3_ * C_], g_wql[(size_t)C3_ * C_];
__device__ __nv_bfloat16 g_woh[(size_t)C_  * C_], g_wol[(size_t)C_  * C_];
// q,k,v split hi/lo in [B,H,T,64] layout
#define QKV_N ((size_t)B_ * H_ * T_ * HD_)
__device__ __nv_bfloat16 g_qh[QKV_N], g_ql[QKV_N];
__device__ __nv_bfloat16 g_kh[QKV_N], g_kl[QKV_N];
__device__ __nv_bfloat16 g_vh[QKV_N], g_vl[QKV_N];
__device__ __nv_bfloat16 g_yh [(size_t)M_ * C_], g_yl [(size_t)M_ * C_];
__device__ int g_len[B_];

// ---------------------------------------------------------------------------
// Helpers
// ---------------------------------------------------------------------------
__device__ __forceinline__ uint32_t smem_u32(const void* p) {
    uint32_t a;
    asm("{ .reg .u64 t; cvta.to.shared.u64 t, %1; cvt.u32.u64 %0, t; }"
        : "=r"(a) : "l"(p));
    return a;
}

#define MMA16816(C, A, b0, b1)                                                \
    asm volatile(                                                             \
        "mma.sync.aligned.m16n8k16.row.col.f32.bf16.bf16.f32 "                \
        "{%0,%1,%2,%3},{%4,%5,%6,%7},{%8,%9},{%0,%1,%2,%3};"                  \
        : "+f"((C)[0]), "+f"((C)[1]), "+f"((C)[2]), "+f"((C)[3])              \
        : "r"((A)[0]), "r"((A)[1]), "r"((A)[2]), "r"((A)[3]),                 \
          "r"(b0), "r"(b1))

#define LDSM_X4(R, addr)                                                      \
    asm volatile("ldmatrix.sync.aligned.m8n8.x4.shared.b16 {%0,%1,%2,%3}, [%4];" \
        : "=r"((R)[0]), "=r"((R)[1]), "=r"((R)[2]), "=r"((R)[3]) : "r"(addr))

#define LDSM_X2(r0, r1, addr)                                                 \
    asm volatile("ldmatrix.sync.aligned.m8n8.x2.shared.b16 {%0,%1}, [%2];"    \
        : "=r"(r0), "=r"(r1) : "r"(addr))

#define LDSM_X2T(r0, r1, addr)                                                \
    asm volatile("ldmatrix.sync.aligned.m8n8.x2.trans.shared.b16 {%0,%1}, [%2];" \
        : "=r"(r0), "=r"(r1) : "r"(addr))

#define CP_ASYNC16(dst, src)                                                  \
    asm volatile("cp.async.cg.shared.global [%0], [%1], 16;"                  \
                 :: "r"(dst), "l"(src) : "memory")
#define CP_COMMIT() asm volatile("cp.async.commit_group;" ::: "memory")
#define CP_WAIT1()  asm volatile("cp.async.wait_group 1;" ::: "memory")

__device__ __forceinline__ uint32_t pack_hi(float a, float b) {
    __nv_bfloat162 v = __floats2bfloat162_rn(a, b);
    return *reinterpret_cast<uint32_t*>(&v);
}
__device__ __forceinline__ uint32_t pack_res(float a, float b, uint32_t hp) {
    __nv_bfloat162 h = *reinterpret_cast<__nv_bfloat162*>(&hp);
    __nv_bfloat162 v = __floats2bfloat162_rn(a - __bfloat162float(h.x),
                                             b - __bfloat162float(h.y));
    return *reinterpret_cast<uint32_t*>(&v);
}

// ---------------------------------------------------------------------------
// HMMA GEMM: C[M,N] = (Ah+Al)[M,K] @ (Wh+Wl)[N,K]^T + bias
// QKV=true: write hi/lo bf16 split to [B,H,T,64] q/k/v arrays.
// QKV=false: write fp32 to Cout.
// ---------------------------------------------------------------------------
#define GTILE_B    6144                    // 128*24*2
#define GSTAGE_B   (4 * GTILE_B)           // 24576
#define GEMM_SMEM  (3 * GSTAGE_B)          // 73728

template <bool QKV>
__global__ __launch_bounds__(256, 2) void gemm_bf16(
    const __nv_bfloat16* __restrict__ Ah, const __nv_bfloat16* __restrict__ Al,
    const __nv_bfloat16* __restrict__ Wh, const __nv_bfloat16* __restrict__ Wl,
    const float* __restrict__ bias, float* __restrict__ Cout,
    __nv_bfloat16* __restrict__ qh, __nv_bfloat16* __restrict__ ql,
    __nv_bfloat16* __restrict__ kh, __nv_bfloat16* __restrict__ kl,
    __nv_bfloat16* __restrict__ vh, __nv_bfloat16* __restrict__ vl,
    int M, int N, int K)
{
    extern __shared__ char sm[];
    const int tid = threadIdx.x;
    const int bm = blockIdx.y * 128;
    const int bn = blockIdx.x * 128;
    const int warp = tid >> 5, lane = tid & 31;
    const int moff = (warp >> 1) * 32;
    const int noff = (warp & 1) * 64;

    float acc[2][8][4];
    #pragma unroll
    for (int a = 0; a < 2; a++)
        #pragma unroll
        for (int b = 0; b < 8; b++)
            #pragma unroll
            for (int c = 0; c < 4; c++) acc[a][b][c] = 0.f;

    const int r_ld = tid >> 1, half8 = (tid & 1) * 8;
    auto issue = [&](int c, int s) {
        const int k0 = c << 4;
        char* st = sm + s * GSTAGE_B;
        uint32_t d = smem_u32(st + (r_ld * 24 + half8) * 2);
        CP_ASYNC16(d,               Ah + (size_t)(bm + r_ld) * K + k0 + half8);
        CP_ASYNC16(d + GTILE_B,     Al + (size_t)(bm + r_ld) * K + k0 + half8);
        CP_ASYNC16(d + 2 * GTILE_B, Wh + (size_t)(bn + r_ld) * K + k0 + half8);
        CP_ASYNC16(d + 3 * GTILE_B, Wl + (size_t)(bn + r_ld) * K + k0 + half8);
        CP_COMMIT();
    };

    const int nk = K >> 4;
    issue(0, 0);
    issue(1, 1);

    const int arow = moff + (lane & 7) + 8 * ((lane >> 3) & 1);
    const int acol = 8 * (lane >> 4);
    const int wrow_l = (lane & 7);
    const int wcol = 8 * ((lane >> 3) & 1);

    int s = 0;
    for (int c = 0; c < nk; c++) {
        CP_WAIT1();
        __syncthreads();
        if (c + 2 < nk) issue(c + 2, (s + 2 >= 3) ? s - 1 : s + 2);
        else CP_COMMIT();

        char* st = sm + s * GSTAGE_B;
        uint32_t ah[2][4], al[2][4];
        #pragma unroll
        for (int mb = 0; mb < 2; mb++) {
            LDSM_X4(ah[mb], smem_u32(st + ((arow + mb * 16) * 24 + acol) * 2));
            LDSM_X4(al[mb], smem_u32(st + GTILE_B + ((arow + mb * 16) * 24 + acol) * 2));
        }
        #pragma unroll
        for (int nb = 0; nb < 8; nb++) {
            int wr = noff + nb * 8 + wrow_l;
            uint32_t bh0, bh1, bl0, bl1;
            LDSM_X2(bh0, bh1, smem_u32(st + 2 * GTILE_B + (wr * 24 + wcol) * 2));
            LDSM_X2(bl0, bl1, smem_u32(st + 3 * GTILE_B + (wr * 24 + wcol) * 2));
            #pragma unroll
            for (int mb = 0; mb < 2; mb++) {
                MMA16816(acc[mb][nb], ah[mb], bh0, bh1);
                MMA16816(acc[mb][nb], al[mb], bh0, bh1);
                MMA16816(acc[mb][nb], ah[mb], bl0, bl1);
            }
        }
        s = (s + 1 >= 3) ? 0 : s + 1;
    }

    const int r0 = lane >> 2, c0 = (lane & 3) * 2;
    if (QKV) {
        const int which = bn >> 10;      // uniform per CTA: 0=q 1=k 2=v
        __nv_bfloat16* Oh = (which == 0) ? qh : (which == 1) ? kh : vh;
        __nv_bfloat16* Ol = (which == 0) ? ql : (which == 1) ? kl : vl;
        #pragma unroll
        for (int mb = 0; mb < 2; mb++)
            #pragma unroll
            for (int nb = 0; nb < 8; nb++) {
                int gcol = bn + noff + nb * 8 + c0;
                int hc = gcol & 1023;
                int head = hc >> 6, d = hc & 63;
                float b0v = bias[gcol], b1v = bias[gcol + 1];
                #pragma unroll
                for (int rr = 0; rr < 2; rr++) {
                    int row = bm + moff + mb * 16 + r0 + rr * 8;
                    int bb = row >> 11, t = row & 2047;
                    size_t idx = ((((size_t)bb * H_) + head) * T_ + t) * HD_ + d;
                    float v0 = acc[mb][nb][rr * 2 + 0] + b0v;
                    float v1 = acc[mb][nb][rr * 2 + 1] + b1v;
                    uint32_t hp = pack_hi(v0, v1);
                    *(uint32_t*)(Oh + idx) = hp;
                    *(uint32_t*)(Ol + idx) = pack_res(v0, v1, hp);
                }
            }
    } else {
        #pragma unroll
        for (int mb = 0; mb < 2; mb++)
            #pragma unroll
            for (int nb = 0; nb < 8; nb++) {
                int row = bm + moff + mb * 16 + r0;
                int col = bn + noff + nb * 8 + c0;
                float2 v0 = make_float2(acc[mb][nb][0] + bias[col],
                                        acc[mb][nb][1] + bias[col + 1]);
                *(float2*)(Cout + (size_t)row * N + col) = v0;
                float2 v1 = make_float2(acc[mb][nb][2] + bias[col],
                                        acc[mb][nb][3] + bias[col + 1]);
                *(float2*)(Cout + (size_t)(row + 8) * N + col) = v1;
            }
    }
}

// ---------------------------------------------------------------------------
// per-batch valid length
// ---------------------------------------------------------------------------
__global__ void compute_len(const int* __restrict__ am, int* __restrict__ out) {
    __shared__ int red[8];
    int b = blockIdx.x, acc = 0;
    for (int i = threadIdx.x; i < T_; i += 256) acc += am[b * T_ + i];
    #pragma unroll
    for (int o = 16; o; o >>= 1) acc += __shfl_xor_sync(0xffffffffu, acc, o);
    if ((threadIdx.x & 31) == 0) red[threadIdx.x >> 5] = acc;
    __syncthreads();
    if (threadIdx.x == 0) {
        int v = 0;
        #pragma unroll
        for (int i = 0; i < 8; i++) v += red[i];
        out[b] = v;
    }
}

// ---------------------------------------------------------------------------
// fp32 -> bf16 hi/lo split
// ---------------------------------------------------------------------------
__global__ __launch_bounds__(256) void split_hl(
    const float* __restrict__ s, __nv_bfloat16* __restrict__ h,
    __nv_bfloat16* __restrict__ l, int n)
{
    int i = (blockIdx.x * 256 + threadIdx.x) * 4;
    if (i >= n) return;
    float4 v = *(const float4*)(s + i);
    uint32_t h01 = pack_hi(v.x, v.y), h23 = pack_hi(v.z, v.w);
    uint32_t l01 = pack_res(v.x, v.y, h01), l23 = pack_res(v.z, v.w, h23);
    *(uint32_t*)(h + i) = h01; *(uint32_t*)(h + i + 2) = h23;
    *(uint32_t*)(l + i) = l01; *(uint32_t*)(l + i + 2) = l23;
}

// ---------------------------------------------------------------------------
// Tensor-core flash attention consuming pre-split bf16 q/k/v [B,H,T,64].
// 128 q-rows/CTA, 8 warps x 16 rows, 64-key tiles, depth-2 cp.async pipeline.
// Uniform pipeline: exactly one kv group issued per step (index clamped), so
// CP_WAIT1 at each loop top guarantees tile kt is resident.
// ---------------------------------------------------------------------------
#define PITCH 72
#define OPB   (64 * PITCH * 2)         // 9216 bytes per operand tile
#define BUF_B (4 * OPB)                // 36864
#define ATTN_SMEM (2 * BUF_B)          // 73728

__global__ __launch_bounds__(256, 1) void flash_attn_tc(
    const __nv_bfloat16* __restrict__ qh, const __nv_bfloat16* __restrict__ ql,
    const __nv_bfloat16* __restrict__ kh, const __nv_bfloat16* __restrict__ kl,
    const __nv_bfloat16* __restrict__ vh, const __nv_bfloat16* __restrict__ vl,
    const int* __restrict__ lenp,
    __nv_bfloat16* __restrict__ yh, __nv_bfloat16* __restrict__ yl)
{
    extern __shared__ char smdyn[];

    const int b = blockIdx.z, h = blockIdx.y, qt = blockIdx.x;
    const int q0 = qt * 128;
    const int tid = threadIdx.x;
    const int warp = tid >> 5, lane = tid & 31;
    const int len = lenp[b];
    const size_t bh = ((size_t)b * H_ + h) * T_ * HD_;

    const int kt_len = (len + 63) >> 6;
    const int kt_max = min(2 * qt + 1, kt_len - 1);

    // tile kt lives in buffer (kt+1)&1 ; Q staged in buffer 0
    auto issue_kv = [&](int kt, int buf) {
        char* st = smdyn + buf * BUF_B;
        const size_t kbase = bh + (size_t)(kt * 64) * HD_;
        #pragma unroll
        for (int t = 0; t < 8; t++) {
            int e = tid + t * 256;            // 0..2047
            int op = e >> 9;                  // 0..3 : Kh,Kl,Vh,Vl
            int idx = e & 511;
            int r = idx >> 3, c16 = idx & 7;
            const __nv_bfloat16* src =
                (op == 0) ? kh : (op == 1) ? kl : (op == 2) ? vh : vl;
            CP_ASYNC16(smem_u32(st + op * OPB + (r * PITCH + c16 * 8) * 2),
                       src + kbase + (size_t)r * HD_ + c16 * 8);
        }
        CP_COMMIT();
    };

    // stage Q hi/lo (128 rows) into buffer 0: Qh at 0, Ql at 2*OPB
    {
        char* st = smdyn;
        const size_t qbase = bh + (size_t)q0 * HD_;
        #pragma unroll
        for (int t = 0; t < 8; t++) {
            int e = tid + t * 256;            // 0..2047
            int part = e >> 10;               // 0=hi 1=lo
            int idx = e & 1023;
            int r = idx >> 3, c16 = idx & 7;
            const __nv_bfloat16* src = part ? ql : qh;
            CP_ASYNC16(smem_u32(st + part * 2 * OPB + (r * PITCH + c16 * 8) * 2),
                       src + qbase + (size_t)r * HD_ + c16 * 8);
        }
        CP_COMMIT();                           // group: Q
    }
    issue_kv(0, 1);                            // group: kv0 -> buf1
    CP_WAIT1();                                // Q arrived
    __syncthreads();

    uint32_t qfh[4][4], qfl[4][4];
    {
        __nv_bfloat16* Qh = (__nv_bfloat16*)smdyn;
        __nv_bfloat16* Ql = (__nv_bfloat16*)(smdyn + 2 * OPB);
        int row = warp * 16 + (lane & 7) + 8 * ((lane >> 3) & 1);
        #pragma unroll
        for (int ks = 0; ks < 4; ks++) {
            int col = ks * 16 + 8 * (lane >> 4);
            LDSM_X4(qfh[ks], smem_u32(Qh + row * PITCH + col));
            LDSM_X4(qfl[ks], smem_u32(Ql + row * PITCH + col));
        }
    }
    __syncthreads();                           // buf0 free
    issue_kv(min(1, kt_max), 0);               // group: kv1 -> buf0 (clamped)

    float m_[2] = {-1e30f, -1e30f}, l_[2] = {0.f, 0.f};
    float O[8][4] = {};

    const int wrow_max = q0 + warp * 16 + 15;
    const int r0 = lane >> 2, cb = (lane & 3) * 2;
    const int row0 = q0 + warp * 16 + r0, row1 = row0 + 8;

    for (int kt = 0; kt <= kt_max; kt++) {
        const int k0 = kt * 64;
        CP_WAIT1();                            // tile kt resident
        __syncthreads();

        char* st = smdyn + ((kt + 1) & 1) * BUF_B;
        __nv_bfloat16* Kh = (__nv_bfloat16*)st;
        __nv_bfloat16* Kl = (__nv_bfloat16*)(st + OPB);
        __nv_bfloat16* Vh = (__nv_bfloat16*)(st + 2 * OPB);
        __nv_bfloat16* Vl = (__nv_bfloat16*)(st + 3 * OPB);

        if (k0 <= wrow_max) {
            // ---- S = Q K^T (3 split terms) ----
            float S[8][4] = {};
            {
                int krow = (lane & 7);
                int kcol8 = 8 * ((lane >> 3) & 1);
                #pragma unroll
                for (int nb = 0; nb < 8; nb++) {
                    #pragma unroll
                    for (int ks = 0; ks < 4; ks++) {
                        uint32_t bh0, bh1, bl0, bl1;
                        LDSM_X2(bh0, bh1, smem_u32(Kh + (nb * 8 + krow) * PITCH + ks * 16 + kcol8));
                        LDSM_X2(bl0, bl1, smem_u32(Kl + (nb * 8 + krow) * PITCH + ks * 16 + kcol8));
                        MMA16816(S[nb], qfh[ks], bh0, bh1);
                        MMA16816(S[nb], qfl[ks], bh0, bh1);
                        MMA16816(S[nb], qfh[ks], bl0, bl1);
                    }
                }
            }

            // ---- mask + online softmax ----
            float ml0 = -1e30f, ml1 = -1e30f;
            #pragma unroll
            for (int nb = 0; nb < 8; nb++) {
                int c0 = k0 + nb * 8 + cb;
                S[nb][0] = (c0     <= row0 && c0     < len) ? S[nb][0] * 0.125f : -1e30f;
                S[nb][1] = (c0 + 1 <= row0 && c0 + 1 < len) ? S[nb][1] * 0.125f : -1e30f;
                S[nb][2] = (c0     <= row1 && c0     < len) ? S[nb][2] * 0.125f : -1e30f;
                S[nb][3] = (c0 + 1 <= row1 && c0 + 1 < len) ? S[nb][3] * 0.125f : -1e30f;
                ml0 = fmaxf(ml0, fmaxf(S[nb][0], S[nb][1]));
                ml1 = fmaxf(ml1, fmaxf(S[nb][2], S[nb][3]));
            }
            ml0 = fmaxf(ml0, __shfl_xor_sync(0xffffffffu, ml0, 1));
            ml0 = fmaxf(ml0, __shfl_xor_sync(0xffffffffu, ml0, 2));
            ml1 = fmaxf(ml1, __shfl_xor_sync(0xffffffffu, ml1, 1));
            ml1 = fmaxf(ml1, __shfl_xor_sync(0xffffffffu, ml1, 2));
            float mn0 = fmaxf(m_[0], ml0), mn1 = fmaxf(m_[1], ml1);
            float corr0 = __expf(m_[0] - mn0), corr1 = __expf(m_[1] - mn1);
            float ls0 = 0.f, ls1 = 0.f;
            #pragma unroll
            for (int nb = 0; nb < 8; nb++) {
                S[nb][0] = __expf(S[nb][0] - mn0); ls0 += S[nb][0];
                S[nb][1] = __expf(S[nb][1] - mn0); ls0 += S[nb][1];
                S[nb][2] = __expf(S[nb][2] - mn1); ls1 += S[nb][2];
                S[nb][3] = __expf(S[nb][3] - mn1); ls1 += S[nb][3];
            }
            ls0 += __shfl_xor_sync(0xffffffffu, ls0, 1);
            ls0 += __shfl_xor_sync(0xffffffffu, ls0, 2);
            ls1 += __shfl_xor_sync(0xffffffffu, ls1, 1);
            ls1 += __shfl_xor_sync(0xffffffffu, ls1, 2);
            l_[0] = l_[0] * corr0 + ls0;
            l_[1] = l_[1] * corr1 + ls1;
            m_[0] = mn0; m_[1] = mn1;
            #pragma unroll
            for (int nb = 0; nb < 8; nb++) {
                O[nb][0] *= corr0; O[nb][1] *= corr0;
                O[nb][2] *= corr1; O[nb][3] *= corr1;
            }

            // ---- O += P V (3 split terms) ----
            {
                int vrow8 = (lane & 7) + 8 * ((lane >> 3) & 1);
                #pragma unroll
                for (int ks = 0; ks < 4; ks++) {
                    uint32_t ph[4], pl[4];
                    ph[0] = pack_hi(S[2 * ks][0], S[2 * ks][1]);
                    ph[1] = pack_hi(S[2 * ks][2], S[2 * ks][3]);
                    ph[2] = pack_hi(S[2 * ks + 1][0], S[2 * ks + 1][1]);
                    ph[3] = pack_hi(S[2 * ks + 1][2], S[2 * ks + 1][3]);
                    pl[0] = pack_res(S[2 * ks][0], S[2 * ks][1], ph[0]);
                    pl[1] = pack_res(S[2 * ks][2], S[2 * ks][3], ph[1]);
                    pl[2] = pack_res(S[2 * ks + 1][0], S[2 * ks + 1][1], ph[2]);
                    pl[3] = pack_res(S[2 * ks + 1][2], S[2 * ks + 1][3], ph[3]);
                    #pragma unroll
                    for (int nb = 0; nb < 8; nb++) {
                        uint32_t vh0, vh1, vl0, vl1;
                        LDSM_X2T(vh0, vh1, smem_u32(Vh + (ks * 16 + vrow8) * PITCH + nb * 8));
                        LDSM_X2T(vl0, vl1, smem_u32(Vl + (ks * 16 + vrow8) * PITCH + nb * 8));
                        MMA16816(O[nb], ph, vh0, vh1);
                        MMA16816(O[nb], pl, vh0, vh1);
                        MMA16816(O[nb], ph, vl0, vl1);
                    }
                }
            }
        }

        __syncthreads();                       // all warps done with this buffer
        // uniform: one group per step, clamped index, into just-freed buffer
        issue_kv(min(kt + 2, kt_max), (kt + 1) & 1);
    }

    // ---- epilogue: normalize, split hi/lo, store ----
    float inv0 = (row0 < len && l_[0] > 0.f) ? (1.f / l_[0]) : 0.f;
    float inv1 = (row1 < len && l_[1] > 0.f) ? (1.f / l_[1]) : 0.f;
    size_t rb0 = ((size_t)b * T_ + row0) * C_;
    size_t rb1 = ((size_t)b * T_ + row1) * C_;
    #pragma unroll
    for (int nb = 0; nb < 8; nb++) {
        int hcol = h * HD_ + nb * 8 + cb;
        uint32_t h0 = pack_hi(O[nb][0] * inv0, O[nb][1] * inv0);
        uint32_t l0 = pack_res(O[nb][0] * inv0, O[nb][1] * inv0, h0);
        uint32_t h1 = pack_hi(O[nb][2] * inv1, O[nb][3] * inv1);
        uint32_t l1 = pack_res(O[nb][2] * inv1, O[nb][3] * inv1, h1);
        *(uint32_t*)(yh + rb0 + hcol) = h0;
        *(uint32_t*)(yl + rb0 + hcol) = l0;
        *(uint32_t*)(yh + rb1 + hcol) = h1;
        *(uint32_t*)(yl + rb1 + hcol) = l1;
    }
}

// ---------------------------------------------------------------------------
extern "C" void kernel_launch(void* const* d_in, const int* in_sizes, int n_in,
                              void* d_out, int out_size)
{
    const float* x    = (const float*)d_in[0];
    const int*   am   = (const int*)  d_in[1];
    const float* Wqkv = (const float*)d_in[2];
    const float* bqkv = (const float*)d_in[3];
    const float* Wo   = (const float*)d_in[4];
    const float* bo   = (const float*)d_in[5];
    float* out = (float*)d_out;

    __nv_bfloat16 *xh, *xl, *wqh, *wql, *woh, *wol, *yh, *yl;
    __nv_bfloat16 *qh, *ql, *kh, *kl, *vh, *vl;
    int* lenp;
    cudaGetSymbolAddress((void**)&xh, g_xh);   cudaGetSymbolAddress((void**)&xl, g_xl);
    cudaGetSymbolAddress((void**)&wqh, g_wqh); cudaGetSymbolAddress((void**)&wql, g_wql);
    cudaGetSymbolAddress((void**)&woh, g_woh); cudaGetSymbolAddress((void**)&wol, g_wol);
    cudaGetSymbolAddress((void**)&yh, g_yh);   cudaGetSymbolAddress((void**)&yl, g_yl);
    cudaGetSymbolAddress((void**)&qh, g_qh);   cudaGetSymbolAddress((void**)&ql, g_ql);
    cudaGetSymbolAddress((void**)&kh, g_kh);   cudaGetSymbolAddress((void**)&kl, g_kl);
    cudaGetSymbolAddress((void**)&vh, g_vh);   cudaGetSymbolAddress((void**)&vl, g_vl);
    cudaGetSymbolAddress((void**)&lenp, g_len);

    cudaFuncSetAttribute(gemm_bf16<true>,  cudaFuncAttributeMaxDynamicSharedMemorySize, GEMM_SMEM);
    cudaFuncSetAttribute(gemm_bf16<false>, cudaFuncAttributeMaxDynamicSharedMemorySize, GEMM_SMEM);
    cudaFuncSetAttribute(flash_attn_tc, cudaFuncAttributeMaxDynamicSharedMemorySize, ATTN_SMEM);

    int nx = M_ * C_, nwq = C3_ * C_, nwo = C_ * C_;
    compute_len<<<B_, 256>>>(am, lenp);
    split_hl<<<nx  / 1024, 256>>>(x,    xh,  xl,  nx);
    split_hl<<<nwq / 1024, 256>>>(Wqkv, wqh, wql, nwq);
    split_hl<<<nwo / 1024, 256>>>(Wo,   woh, wol, nwo);

    gemm_bf16<true><<<dim3(C3_ / 128, M_ / 128), 256, GEMM_SMEM>>>(
        xh, xl, wqh, wql, bqkv, nullptr,
        qh, ql, kh, kl, vh, vl, M_, C3_, C_);
    flash_attn_tc<<<dim3(T_ / 128, H_, B_), 256, ATTN_SMEM>>>(
        qh, ql, kh, kl, vh, vl, lenp, yh, yl);
    gemm_bf16<false><<<dim3(C_ / 128, M_ / 128), 256, GEMM_SMEM>>>(
        yh, yl, woh, wol, bo, out,
        nullptr, nullptr, nullptr, nullptr, nullptr, nullptr, M_, C_, C_);
}

// round 9
// speedup vs baseline: 1.4681x; 1.4681x over previous
#include <cuda_runtime.h>
#include <cuda_bf16.h>
#include <cstdint>

// Problem constants
#define B_   4
#define T_   2048
#define C_   1024
#define H_   16
#define HD_  64
#define M_   (B_ * T_)          // 8192
#define C3_  (3 * C_)           // 3072

// ---------------------------------------------------------------------------
// Scratch (device globals)
// ---------------------------------------------------------------------------
__device__ float g_qkv[(size_t)M_ * C3_];
__device__ __nv_bfloat16 g_xh [(size_t)M_  * C_], g_xl [(size_t)M_  * C_];
__device__ __nv_bfloat16 g_wqh[(size_t)C3_ * C_], g_wql[(size_t)C3_ * C_];
__device__ __nv_bfloat16 g_woh[(size_t)C_  * C_], g_wol[(size_t)C_  * C_];
__device__ __nv_bfloat16 g_yh [(size_t)M_ * C_], g_yl [(size_t)M_ * C_];
__device__ int g_len[B_];

// ---------------------------------------------------------------------------
// Helpers
// ---------------------------------------------------------------------------
__device__ __forceinline__ uint32_t smem_u32(const void* p) {
    uint32_t a;
    asm("{ .reg .u64 t; cvta.to.shared.u64 t, %1; cvt.u32.u64 %0, t; }"
        : "=r"(a) : "l"(p));
    return a;
}

#define MMA16816(C, A, b0, b1)                                                \
    asm volatile(                                                             \
        "mma.sync.aligned.m16n8k16.row.col.f32.bf16.bf16.f32 "                \
        "{%0,%1,%2,%3},{%4,%5,%6,%7},{%8,%9},{%0,%1,%2,%3};"                  \
        : "+f"((C)[0]), "+f"((C)[1]), "+f"((C)[2]), "+f"((C)[3])              \
        : "r"((A)[0]), "r"((A)[1]), "r"((A)[2]), "r"((A)[3]),                 \
          "r"(b0), "r"(b1))

#define LDSM_X4(R, addr)                                                      \
    asm volatile("ldmatrix.sync.aligned.m8n8.x4.shared.b16 {%0,%1,%2,%3}, [%4];" \
        : "=r"((R)[0]), "=r"((R)[1]), "=r"((R)[2]), "=r"((R)[3]) : "r"(addr))

#define LDSM_X2(r0, r1, addr)                                                 \
    asm volatile("ldmatrix.sync.aligned.m8n8.x2.shared.b16 {%0,%1}, [%2];"    \
        : "=r"(r0), "=r"(r1) : "r"(addr))

#define LDSM_X2T(r0, r1, addr)                                                \
    asm volatile("ldmatrix.sync.aligned.m8n8.x2.trans.shared.b16 {%0,%1}, [%2];" \
        : "=r"(r0), "=r"(r1) : "r"(addr))

#define CP_ASYNC16(dst, src)                                                  \
    asm volatile("cp.async.cg.shared.global [%0], [%1], 16;"                  \
                 :: "r"(dst), "l"(src) : "memory")
#define CP_COMMIT() asm volatile("cp.async.commit_group;" ::: "memory")
#define CP_WAIT1()  asm volatile("cp.async.wait_group 1;" ::: "memory")

__device__ __forceinline__ uint32_t pack_hi(float a, float b) {
    __nv_bfloat162 v = __floats2bfloat162_rn(a, b);
    return *reinterpret_cast<uint32_t*>(&v);
}
__device__ __forceinline__ uint32_t pack_res(float a, float b, uint32_t hp) {
    __nv_bfloat162 h = *reinterpret_cast<__nv_bfloat162*>(&hp);
    __nv_bfloat162 v = __floats2bfloat162_rn(a - __bfloat162float(h.x),
                                             b - __bfloat162float(h.y));
    return *reinterpret_cast<uint32_t*>(&v);
}

// ---------------------------------------------------------------------------
// HMMA GEMM: Cout[M,N] = (Ah+Al)[M,K] @ (Wh+Wl)[N,K]^T + bias  (fp32 out)
// CTA tile 256x128, warp tile 64x64 (4 mb x 8 nb), k-chunk 16,
// 3-stage cp.async pipeline, 1 CTA/SM (no reg cap -> no spills).
// Stage layout: Ah(12K) | Al(12K) | Bh(6K) | Bl(6K), pitch 24 bf16.
// ---------------------------------------------------------------------------
#define GA_B      12288                    // 256*24*2
#define GB_B      6144                     // 128*24*2
#define GSTAGE_B  (2 * GA_B + 2 * GB_B)    // 36864
#define GEMM_SMEM (3 * GSTAGE_B)           // 110592

__global__ __launch_bounds__(256, 1) void gemm_bf16(
    const __nv_bfloat16* __restrict__ Ah, const __nv_bfloat16* __restrict__ Al,
    const __nv_bfloat16* __restrict__ Wh, const __nv_bfloat16* __restrict__ Wl,
    const float* __restrict__ bias, float* __restrict__ Cout,
    int M, int N, int K)
{
    extern __shared__ char sm[];
    const int tid = threadIdx.x;
    const int bm = blockIdx.y * 256;
    const int bn = blockIdx.x * 128;
    const int warp = tid >> 5, lane = tid & 31;
    const int moff = (warp >> 1) * 64;     // 4 warps over M (64 rows)
    const int noff = (warp & 1) * 64;      // 2 warps over N (64 cols)

    float acc[4][8][4];
    #pragma unroll
    for (int a = 0; a < 4; a++)
        #pragma unroll
        for (int b = 0; b < 8; b++)
            #pragma unroll
            for (int c = 0; c < 4; c++) acc[a][b][c] = 0.f;

    // loads: 1536 16B-chunks per stage, 6 per thread
    auto issue = [&](int c, int s) {
        const int k0 = c << 4;
        char* st = sm + s * GSTAGE_B;
        #pragma unroll
        for (int t = 0; t < 2; t++) {          // Ah: 512 chunks
            int e = tid + t * 256;
            int r = e >> 1, h8 = (e & 1) * 8;
            CP_ASYNC16(smem_u32(st + (r * 24 + h8) * 2),
                       Ah + (size_t)(bm + r) * K + k0 + h8);
        }
        #pragma unroll
        for (int t = 0; t < 2; t++) {          // Al
            int e = tid + t * 256;
            int r = e >> 1, h8 = (e & 1) * 8;
            CP_ASYNC16(smem_u32(st + GA_B + (r * 24 + h8) * 2),
                       Al + (size_t)(bm + r) * K + k0 + h8);
        }
        {                                      // Bh: 256 chunks
            int r = tid >> 1, h8 = (tid & 1) * 8;
            CP_ASYNC16(smem_u32(st + 2 * GA_B + (r * 24 + h8) * 2),
                       Wh + (size_t)(bn + r) * K + k0 + h8);
            CP_ASYNC16(smem_u32(st + 2 * GA_B + GB_B + (r * 24 + h8) * 2),
                       Wl + (size_t)(bn + r) * K + k0 + h8);
        }
        CP_COMMIT();
    };

    const int nk = K >> 4;     // 64
    issue(0, 0);
    issue(1, 1);

    const int arow = moff + (lane & 7) + 8 * ((lane >> 3) & 1);
    const int acol = 8 * (lane >> 4);
    const int wrow_l = (lane & 7);
    const int wcol = 8 * ((lane >> 3) & 1);

    int s = 0;
    for (int c = 0; c < nk; c++) {
        CP_WAIT1();
        __syncthreads();
        if (c + 2 < nk) issue(c + 2, (s + 2 >= 3) ? s - 1 : s + 2);
        else CP_COMMIT();

        char* st = sm + s * GSTAGE_B;
        uint32_t ah[4][4], al[4][4];
        #pragma unroll
        for (int mb = 0; mb < 4; mb++) {
            LDSM_X4(ah[mb], smem_u32(st + ((arow + mb * 16) * 24 + acol) * 2));
            LDSM_X4(al[mb], smem_u32(st + GA_B + ((arow + mb * 16) * 24 + acol) * 2));
        }
        #pragma unroll
        for (int nb = 0; nb < 8; nb++) {
            int wr = noff + nb * 8 + wrow_l;
            uint32_t bh0, bh1, bl0, bl1;
            LDSM_X2(bh0, bh1, smem_u32(st + 2 * GA_B + (wr * 24 + wcol) * 2));
            LDSM_X2(bl0, bl1, smem_u32(st + 2 * GA_B + GB_B + (wr * 24 + wcol) * 2));
            #pragma unroll
            for (int mb = 0; mb < 4; mb++) {
                MMA16816(acc[mb][nb], ah[mb], bh0, bh1);
                MMA16816(acc[mb][nb], al[mb], bh0, bh1);
                MMA16816(acc[mb][nb], ah[mb], bl0, bl1);
            }
        }
        s = (s + 1 >= 3) ? 0 : s + 1;
    }

    const int r0 = lane >> 2, c0 = (lane & 3) * 2;
    #pragma unroll
    for (int mb = 0; mb < 4; mb++)
        #pragma unroll
        for (int nb = 0; nb < 8; nb++) {
            int row = bm + moff + mb * 16 + r0;
            int col = bn + noff + nb * 8 + c0;
            float2 v0 = make_float2(acc[mb][nb][0] + bias[col],
                                    acc[mb][nb][1] + bias[col + 1]);
            *(float2*)(Cout + (size_t)row * N + col) = v0;
            float2 v1 = make_float2(acc[mb][nb][2] + bias[col],
                                    acc[mb][nb][3] + bias[col + 1]);
            *(float2*)(Cout + (size_t)(row + 8) * N + col) = v1;
        }
}

// ---------------------------------------------------------------------------
// per-batch valid length
// ---------------------------------------------------------------------------
__global__ void compute_len(const int* __restrict__ am, int* __restrict__ out) {
    __shared__ int red[8];
    int b = blockIdx.x, acc = 0;
    for (int i = threadIdx.x; i < T_; i += 256) acc += am[b * T_ + i];
    #pragma unroll
    for (int o = 16; o; o >>= 1) acc += __shfl_xor_sync(0xffffffffu, acc, o);
    if ((threadIdx.x & 31) == 0) red[threadIdx.x >> 5] = acc;
    __syncthreads();
    if (threadIdx.x == 0) {
        int v = 0;
        #pragma unroll
        for (int i = 0; i < 8; i++) v += red[i];
        out[b] = v;
    }
}

// ---------------------------------------------------------------------------
// fp32 -> bf16 hi/lo split
// ---------------------------------------------------------------------------
__global__ __launch_bounds__(256) void split_hl(
    const float* __restrict__ s, __nv_bfloat16* __restrict__ h,
    __nv_bfloat16* __restrict__ l, int n)
{
    int i = (blockIdx.x * 256 + threadIdx.x) * 4;
    if (i >= n) return;
    float4 v = *(const float4*)(s + i);
    uint32_t h01 = pack_hi(v.x, v.y), h23 = pack_hi(v.z, v.w);
    uint32_t l01 = pack_res(v.x, v.y, h01), l23 = pack_res(v.z, v.w, h23);
    *(uint32_t*)(h + i) = h01; *(uint32_t*)(h + i + 2) = h23;
    *(uint32_t*)(l + i) = l01; *(uint32_t*)(l + i + 2) = l23;
}

// ---------------------------------------------------------------------------
// Tensor-core flash attention (measured R4/R5 structure: inline conversion,
// static SMEM). 128 q-rows/CTA, 8 warps x 16 rows, 64-key tiles.
// Epilogue writes separate yh/yl.
// ---------------------------------------------------------------------------
#define PITCH 72

__global__ __launch_bounds__(256, 1) void flash_attn_tc(
    const float* __restrict__ qkv, const int* __restrict__ lenp,
    __nv_bfloat16* __restrict__ yh, __nv_bfloat16* __restrict__ yl)
{
    __shared__ __nv_bfloat16 sbuf[4 * 64 * PITCH];
    __nv_bfloat16* Kh = sbuf;
    __nv_bfloat16* Kl = sbuf + 64 * PITCH;
    __nv_bfloat16* Vh = sbuf + 2 * 64 * PITCH;
    __nv_bfloat16* Vl = sbuf + 3 * 64 * PITCH;
    __nv_bfloat16* Qh = sbuf;                    // staging alias (pre-loop)
    __nv_bfloat16* Ql = sbuf + 128 * PITCH;

    const int b = blockIdx.z, h = blockIdx.y, qt = blockIdx.x;
    const int q0 = qt * 128;
    const int tid = threadIdx.x;
    const int warp = tid >> 5, lane = tid & 31;
    const int len = lenp[b];
    const float* base = qkv + (size_t)b * T_ * C3_ + h * HD_;

    // ---- stage Q fp32 -> hi/lo bf16 ----
    #pragma unroll
    for (int t = 0; t < 8; t++) {
        int e = tid + t * 256;
        int r = e >> 4, c4 = (e & 15) * 4;
        float4 v = *(const float4*)(base + (size_t)(q0 + r) * C3_ + c4);
        uint32_t h01 = pack_hi(v.x, v.y), h23 = pack_hi(v.z, v.w);
        *(uint32_t*)(Qh + r * PITCH + c4)     = h01;
        *(uint32_t*)(Qh + r * PITCH + c4 + 2) = h23;
        *(uint32_t*)(Ql + r * PITCH + c4)     = pack_res(v.x, v.y, h01);
        *(uint32_t*)(Ql + r * PITCH + c4 + 2) = pack_res(v.z, v.w, h23);
    }
    __syncthreads();

    uint32_t qfh[4][4], qfl[4][4];
    {
        int row = warp * 16 + (lane & 7) + 8 * ((lane >> 3) & 1);
        #pragma unroll
        for (int ks = 0; ks < 4; ks++) {
            int col = ks * 16 + 8 * (lane >> 4);
            LDSM_X4(qfh[ks], smem_u32(Qh + row * PITCH + col));
            LDSM_X4(qfl[ks], smem_u32(Ql + row * PITCH + col));
        }
    }
    __syncthreads();

    float m_[2] = {-1e30f, -1e30f}, l_[2] = {0.f, 0.f};
    float O[8][4] = {};

    const int kt_len = (len + 63) >> 6;
    const int kt_max = min(2 * qt + 1, kt_len - 1);
    const int wrow_max = q0 + warp * 16 + 15;
    const int r0 = lane >> 2, cb = (lane & 3) * 2;
    const int row0 = q0 + warp * 16 + r0, row1 = row0 + 8;

    for (int kt = 0; kt <= kt_max; kt++) {
        const int k0 = kt * 64;
        __syncthreads();
        // load K,V tiles (64x64 fp32 each) -> hi/lo bf16 smem
        #pragma unroll
        for (int t = 0; t < 4; t++) {
            int e = tid + t * 256;
            int r = e >> 4, c4 = (e & 15) * 4;
            float4 kv = *(const float4*)(base + C_ + (size_t)(k0 + r) * C3_ + c4);
            float4 vv = *(const float4*)(base + 2 * C_ + (size_t)(k0 + r) * C3_ + c4);
            uint32_t kh01 = pack_hi(kv.x, kv.y), kh23 = pack_hi(kv.z, kv.w);
            *(uint32_t*)(Kh + r * PITCH + c4)     = kh01;
            *(uint32_t*)(Kh + r * PITCH + c4 + 2) = kh23;
            *(uint32_t*)(Kl + r * PITCH + c4)     = pack_res(kv.x, kv.y, kh01);
            *(uint32_t*)(Kl + r * PITCH + c4 + 2) = pack_res(kv.z, kv.w, kh23);
            uint32_t vh01 = pack_hi(vv.x, vv.y), vh23 = pack_hi(vv.z, vv.w);
            *(uint32_t*)(Vh + r * PITCH + c4)     = vh01;
            *(uint32_t*)(Vh + r * PITCH + c4 + 2) = vh23;
            *(uint32_t*)(Vl + r * PITCH + c4)     = pack_res(vv.x, vv.y, vh01);
            *(uint32_t*)(Vl + r * PITCH + c4 + 2) = pack_res(vv.z, vv.w, vh23);
        }
        __syncthreads();
        if (k0 > wrow_max) continue;

        // ---- S = Q K^T (3 split terms) ----
        float S[8][4] = {};
        {
            int krow = (lane & 7);
            int kcol8 = 8 * ((lane >> 3) & 1);
            #pragma unroll
            for (int nb = 0; nb < 8; nb++) {
                #pragma unroll
                for (int ks = 0; ks < 4; ks++) {
                    uint32_t bh0, bh1, bl0, bl1;
                    LDSM_X2(bh0, bh1, smem_u32(Kh + (nb * 8 + krow) * PITCH + ks * 16 + kcol8));
                    LDSM_X2(bl0, bl1, smem_u32(Kl + (nb * 8 + krow) * PITCH + ks * 16 + kcol8));
                    MMA16816(S[nb], qfh[ks], bh0, bh1);
                    MMA16816(S[nb], qfl[ks], bh0, bh1);
                    MMA16816(S[nb], qfh[ks], bl0, bl1);
                }
            }
        }

        // ---- mask + online softmax ----
        float ml0 = -1e30f, ml1 = -1e30f;
        #pragma unroll
        for (int nb = 0; nb < 8; nb++) {
            int c0 = k0 + nb * 8 + cb;
            S[nb][0] = (c0     <= row0 && c0     < len) ? S[nb][0] * 0.125f : -1e30f;
            S[nb][1] = (c0 + 1 <= row0 && c0 + 1 < len) ? S[nb][1] * 0.125f : -1e30f;
            S[nb][2] = (c0     <= row1 && c0     < len) ? S[nb][2] * 0.125f : -1e30f;
            S[nb][3] = (c0 + 1 <= row1 && c0 + 1 < len) ? S[nb][3] * 0.125f : -1e30f;
            ml0 = fmaxf(ml0, fmaxf(S[nb][0], S[nb][1]));
            ml1 = fmaxf(ml1, fmaxf(S[nb][2], S[nb][3]));
        }
        ml0 = fmaxf(ml0, __shfl_xor_sync(0xffffffffu, ml0, 1));
        ml0 = fmaxf(ml0, __shfl_xor_sync(0xffffffffu, ml0, 2));
        ml1 = fmaxf(ml1, __shfl_xor_sync(0xffffffffu, ml1, 1));
        ml1 = fmaxf(ml1, __shfl_xor_sync(0xffffffffu, ml1, 2));
        float mn0 = fmaxf(m_[0], ml0), mn1 = fmaxf(m_[1], ml1);
        float corr0 = __expf(m_[0] - mn0), corr1 = __expf(m_[1] - mn1);
        float ls0 = 0.f, ls1 = 0.f;
        #pragma unroll
        for (int nb = 0; nb < 8; nb++) {
            S[nb][0] = __expf(S[nb][0] - mn0); ls0 += S[nb][0];
            S[nb][1] = __expf(S[nb][1] - mn0); ls0 += S[nb][1];
            S[nb][2] = __expf(S[nb][2] - mn1); ls1 += S[nb][2];
            S[nb][3] = __expf(S[nb][3] - mn1); ls1 += S[nb][3];
        }
        ls0 += __shfl_xor_sync(0xffffffffu, ls0, 1);
        ls0 += __shfl_xor_sync(0xffffffffu, ls0, 2);
        ls1 += __shfl_xor_sync(0xffffffffu, ls1, 1);
        ls1 += __shfl_xor_sync(0xffffffffu, ls1, 2);
        l_[0] = l_[0] * corr0 + ls0;
        l_[1] = l_[1] * corr1 + ls1;
        m_[0] = mn0; m_[1] = mn1;
        #pragma unroll
        for (int nb = 0; nb < 8; nb++) {
            O[nb][0] *= corr0; O[nb][1] *= corr0;
            O[nb][2] *= corr1; O[nb][3] *= corr1;
        }

        // ---- O += P V (3 split terms) ----
        {
            int vrow8 = (lane & 7) + 8 * ((lane >> 3) & 1);
            #pragma unroll
            for (int ks = 0; ks < 4; ks++) {
                uint32_t ph[4], pl[4];
                ph[0] = pack_hi(S[2 * ks][0], S[2 * ks][1]);
                ph[1] = pack_hi(S[2 * ks][2], S[2 * ks][3]);
                ph[2] = pack_hi(S[2 * ks + 1][0], S[2 * ks + 1][1]);
                ph[3] = pack_hi(S[2 * ks + 1][2], S[2 * ks + 1][3]);
                pl[0] = pack_res(S[2 * ks][0], S[2 * ks][1], ph[0]);
                pl[1] = pack_res(S[2 * ks][2], S[2 * ks][3], ph[1]);
                pl[2] = pack_res(S[2 * ks + 1][0], S[2 * ks + 1][1], ph[2]);
                pl[3] = pack_res(S[2 * ks + 1][2], S[2 * ks + 1][3], ph[3]);
                #pragma unroll
                for (int nb = 0; nb < 8; nb++) {
                    uint32_t vh0, vh1, vl0, vl1;
                    LDSM_X2T(vh0, vh1, smem_u32(Vh + (ks * 16 + vrow8) * PITCH + nb * 8));
                    LDSM_X2T(vl0, vl1, smem_u32(Vl + (ks * 16 + vrow8) * PITCH + nb * 8));
                    MMA16816(O[nb], ph, vh0, vh1);
                    MMA16816(O[nb], pl, vh0, vh1);
                    MMA16816(O[nb], ph, vl0, vl1);
                }
            }
        }
    }

    // ---- epilogue: normalize, split hi/lo, store ----
    float inv0 = (row0 < len && l_[0] > 0.f) ? (1.f / l_[0]) : 0.f;
    float inv1 = (row1 < len && l_[1] > 0.f) ? (1.f / l_[1]) : 0.f;
    size_t rb0 = ((size_t)b * T_ + row0) * C_;
    size_t rb1 = ((size_t)b * T_ + row1) * C_;
    #pragma unroll
    for (int nb = 0; nb < 8; nb++) {
        int hcol = h * HD_ + nb * 8 + cb;
        uint32_t h0 = pack_hi(O[nb][0] * inv0, O[nb][1] * inv0);
        uint32_t l0 = pack_res(O[nb][0] * inv0, O[nb][1] * inv0, h0);
        uint32_t h1 = pack_hi(O[nb][2] * inv1, O[nb][3] * inv1);
        uint32_t l1 = pack_res(O[nb][2] * inv1, O[nb][3] * inv1, h1);
        *(uint32_t*)(yh + rb0 + hcol) = h0;
        *(uint32_t*)(yl + rb0 + hcol) = l0;
        *(uint32_t*)(yh + rb1 + hcol) = h1;
        *(uint32_t*)(yl + rb1 + hcol) = l1;
    }
}

// ---------------------------------------------------------------------------
extern "C" void kernel_launch(void* const* d_in, const int* in_sizes, int n_in,
                              void* d_out, int out_size)
{
    const float* x    = (const float*)d_in[0];
    const int*   am   = (const int*)  d_in[1];
    const float* Wqkv = (const float*)d_in[2];
    const float* bqkv = (const float*)d_in[3];
    const float* Wo   = (const float*)d_in[4];
    const float* bo   = (const float*)d_in[5];
    float* out = (float*)d_out;

    float* qkv;
    __nv_bfloat16 *xh, *xl, *wqh, *wql, *woh, *wol, *yh, *yl;
    int* lenp;
    cudaGetSymbolAddress((void**)&qkv, g_qkv);
    cudaGetSymbolAddress((void**)&xh, g_xh);   cudaGetSymbolAddress((void**)&xl, g_xl);
    cudaGetSymbolAddress((void**)&wqh, g_wqh); cudaGetSymbolAddress((void**)&wql, g_wql);
    cudaGetSymbolAddress((void**)&woh, g_woh); cudaGetSymbolAddress((void**)&wol, g_wol);
    cudaGetSymbolAddress((void**)&yh, g_yh);   cudaGetSymbolAddress((void**)&yl, g_yl);
    cudaGetSymbolAddress((void**)&lenp, g_len);

    cudaFuncSetAttribute(gemm_bf16, cudaFuncAttributeMaxDynamicSharedMemorySize, GEMM_SMEM);

    int nx = M_ * C_, nwq = C3_ * C_, nwo = C_ * C_;
    compute_len<<<B_, 256>>>(am, lenp);
    split_hl<<<nx  / 1024, 256>>>(x,    xh,  xl,  nx);
    split_hl<<<nwq / 1024, 256>>>(Wqkv, wqh, wql, nwq);
    split_hl<<<nwo / 1024, 256>>>(Wo,   woh, wol, nwo);

    gemm_bf16<<<dim3(C3_ / 128, M_ / 256), 256, GEMM_SMEM>>>(
        xh, xl, wqh, wql, bqkv, qkv, M_, C3_, C_);
    flash_attn_tc<<<dim3(T_ / 128, H_, B_), 256>>>(qkv, lenp, yh, yl);
    gemm_bf16<<<dim3(C_ / 128, M_ / 256), 256, GEMM_SMEM>>>(
        yh, yl, woh, wol, bo, out, M_, C_, C_);
}

// round 10
// speedup vs baseline: 1.5118x; 1.0297x over previous
#include <cuda_runtime.h>
#include <cuda_bf16.h>
#include <cstdint>

// Problem constants
#define B_   4
#define T_   2048
#define C_   1024
#define H_   16
#define HD_  64
#define M_   (B_ * T_)          // 8192
#define C3_  (3 * C_)           // 3072

// ---------------------------------------------------------------------------
// Scratch (device globals)
// ---------------------------------------------------------------------------
__device__ float g_qkv[(size_t)M_ * C3_];
__device__ __nv_bfloat16 g_xh [(size_t)M_  * C_], g_xl [(size_t)M_  * C_];
__device__ __nv_bfloat16 g_wqh[(size_t)C3_ * C_], g_wql[(size_t)C3_ * C_];
__device__ __nv_bfloat16 g_woh[(size_t)C_  * C_], g_wol[(size_t)C_  * C_];
#define QKV_N ((size_t)B_ * H_ * T_ * HD_)
__device__ __nv_bfloat16 g_qh[QKV_N], g_ql[QKV_N];
__device__ __nv_bfloat16 g_kh[QKV_N], g_kl[QKV_N];
__device__ __nv_bfloat16 g_vh[QKV_N], g_vl[QKV_N];
__device__ __nv_bfloat16 g_yh [(size_t)M_ * C_], g_yl [(size_t)M_ * C_];
__device__ int g_len[B_];

// ---------------------------------------------------------------------------
// Helpers
// ---------------------------------------------------------------------------
__device__ __forceinline__ uint32_t smem_u32(const void* p) {
    uint32_t a;
    asm("{ .reg .u64 t; cvta.to.shared.u64 t, %1; cvt.u32.u64 %0, t; }"
        : "=r"(a) : "l"(p));
    return a;
}

#define MMA16816(C, A, b0, b1)                                                \
    asm volatile(                                                             \
        "mma.sync.aligned.m16n8k16.row.col.f32.bf16.bf16.f32 "                \
        "{%0,%1,%2,%3},{%4,%5,%6,%7},{%8,%9},{%0,%1,%2,%3};"                  \
        : "+f"((C)[0]), "+f"((C)[1]), "+f"((C)[2]), "+f"((C)[3])              \
        : "r"((A)[0]), "r"((A)[1]), "r"((A)[2]), "r"((A)[3]),                 \
          "r"(b0), "r"(b1))

#define LDSM_X4(R, addr)                                                      \
    asm volatile("ldmatrix.sync.aligned.m8n8.x4.shared.b16 {%0,%1,%2,%3}, [%4];" \
        : "=r"((R)[0]), "=r"((R)[1]), "=r"((R)[2]), "=r"((R)[3]) : "r"(addr))

#define LDSM_X2(r0, r1, addr)                                                 \
    asm volatile("ldmatrix.sync.aligned.m8n8.x2.shared.b16 {%0,%1}, [%2];"    \
        : "=r"(r0), "=r"(r1) : "r"(addr))

#define LDSM_X2T(r0, r1, addr)                                                \
    asm volatile("ldmatrix.sync.aligned.m8n8.x2.trans.shared.b16 {%0,%1}, [%2];" \
        : "=r"(r0), "=r"(r1) : "r"(addr))

#define CP_ASYNC16(dst, src)                                                  \
    asm volatile("cp.async.cg.shared.global [%0], [%1], 16;"                  \
                 :: "r"(dst), "l"(src) : "memory")
#define CP_COMMIT() asm volatile("cp.async.commit_group;" ::: "memory")
#define CP_WAIT1()  asm volatile("cp.async.wait_group 1;" ::: "memory")

__device__ __forceinline__ uint32_t pack_hi(float a, float b) {
    __nv_bfloat162 v = __floats2bfloat162_rn(a, b);
    return *reinterpret_cast<uint32_t*>(&v);
}
__device__ __forceinline__ uint32_t pack_res(float a, float b, uint32_t hp) {
    __nv_bfloat162 h = *reinterpret_cast<__nv_bfloat162*>(&hp);
    __nv_bfloat162 v = __floats2bfloat162_rn(a - __bfloat162float(h.x),
                                             b - __bfloat162float(h.y));
    return *reinterpret_cast<uint32_t*>(&v);
}

// ---------------------------------------------------------------------------
// HMMA GEMM (R6 measured-best): Cout[M,N] = (Ah+Al)@(Wh+Wl)^T + bias, fp32 out
// 128x128 tile, k-chunk 16, 3-stage cp.async, 2 CTAs/SM, lean epilogue.
// ---------------------------------------------------------------------------
#define GTILE_B    6144
#define GSTAGE_B   (4 * GTILE_B)
#define GEMM_SMEM  (3 * GSTAGE_B)

__global__ __launch_bounds__(256, 2) void gemm_bf16(
    const __nv_bfloat16* __restrict__ Ah, const __nv_bfloat16* __restrict__ Al,
    const __nv_bfloat16* __restrict__ Wh, const __nv_bfloat16* __restrict__ Wl,
    const float* __restrict__ bias, float* __restrict__ Cout,
    int M, int N, int K)
{
    extern __shared__ char sm[];
    const int tid = threadIdx.x;
    const int bm = blockIdx.y * 128;
    const int bn = blockIdx.x * 128;
    const int warp = tid >> 5, lane = tid & 31;
    const int moff = (warp >> 1) * 32;
    const int noff = (warp & 1) * 64;

    float acc[2][8][4];
    #pragma unroll
    for (int a = 0; a < 2; a++)
        #pragma unroll
        for (int b = 0; b < 8; b++)
            #pragma unroll
            for (int c = 0; c < 4; c++) acc[a][b][c] = 0.f;

    const int r_ld = tid >> 1, half8 = (tid & 1) * 8;
    auto issue = [&](int c, int s) {
        const int k0 = c << 4;
        char* st = sm + s * GSTAGE_B;
        uint32_t d = smem_u32(st + (r_ld * 24 + half8) * 2);
        CP_ASYNC16(d,               Ah + (size_t)(bm + r_ld) * K + k0 + half8);
        CP_ASYNC16(d + GTILE_B,     Al + (size_t)(bm + r_ld) * K + k0 + half8);
        CP_ASYNC16(d + 2 * GTILE_B, Wh + (size_t)(bn + r_ld) * K + k0 + half8);
        CP_ASYNC16(d + 3 * GTILE_B, Wl + (size_t)(bn + r_ld) * K + k0 + half8);
        CP_COMMIT();
    };

    const int nk = K >> 4;
    issue(0, 0);
    issue(1, 1);

    const int arow = moff + (lane & 7) + 8 * ((lane >> 3) & 1);
    const int acol = 8 * (lane >> 4);
    const int wrow_l = (lane & 7);
    const int wcol = 8 * ((lane >> 3) & 1);

    int s = 0;
    for (int c = 0; c < nk; c++) {
        CP_WAIT1();
        __syncthreads();
        if (c + 2 < nk) issue(c + 2, (s + 2 >= 3) ? s - 1 : s + 2);
        else CP_COMMIT();

        char* st = sm + s * GSTAGE_B;
        uint32_t ah[2][4], al[2][4];
        #pragma unroll
        for (int mb = 0; mb < 2; mb++) {
            LDSM_X4(ah[mb], smem_u32(st + ((arow + mb * 16) * 24 + acol) * 2));
            LDSM_X4(al[mb], smem_u32(st + GTILE_B + ((arow + mb * 16) * 24 + acol) * 2));
        }
        #pragma unroll
        for (int nb = 0; nb < 8; nb++) {
            int wr = noff + nb * 8 + wrow_l;
            uint32_t bh0, bh1, bl0, bl1;
            LDSM_X2(bh0, bh1, smem_u32(st + 2 * GTILE_B + (wr * 24 + wcol) * 2));
            LDSM_X2(bl0, bl1, smem_u32(st + 3 * GTILE_B + (wr * 24 + wcol) * 2));
            #pragma unroll
            for (int mb = 0; mb < 2; mb++) {
                MMA16816(acc[mb][nb], ah[mb], bh0, bh1);
                MMA16816(acc[mb][nb], al[mb], bh0, bh1);
                MMA16816(acc[mb][nb], ah[mb], bl0, bl1);
            }
        }
        s = (s + 1 >= 3) ? 0 : s + 1;
    }

    const int r0 = lane >> 2, c0 = (lane & 3) * 2;
    #pragma unroll
    for (int mb = 0; mb < 2; mb++)
        #pragma unroll
        for (int nb = 0; nb < 8; nb++) {
            int row = bm + moff + mb * 16 + r0;
            int col = bn + noff + nb * 8 + c0;
            float2 v0 = make_float2(acc[mb][nb][0] + bias[col],
                                    acc[mb][nb][1] + bias[col + 1]);
            *(float2*)(Cout + (size_t)row * N + col) = v0;
            float2 v1 = make_float2(acc[mb][nb][2] + bias[col],
                                    acc[mb][nb][3] + bias[col + 1]);
            *(float2*)(Cout + (size_t)(row + 8) * N + col) = v1;
        }
}

// ---------------------------------------------------------------------------
// per-batch valid length
// ---------------------------------------------------------------------------
__global__ void compute_len(const int* __restrict__ am, int* __restrict__ out) {
    __shared__ int red[8];
    int b = blockIdx.x, acc = 0;
    for (int i = threadIdx.x; i < T_; i += 256) acc += am[b * T_ + i];
    #pragma unroll
    for (int o = 16; o; o >>= 1) acc += __shfl_xor_sync(0xffffffffu, acc, o);
    if ((threadIdx.x & 31) == 0) red[threadIdx.x >> 5] = acc;
    __syncthreads();
    if (threadIdx.x == 0) {
        int v = 0;
        #pragma unroll
        for (int i = 0; i < 8; i++) v += red[i];
        out[b] = v;
    }
}

// ---------------------------------------------------------------------------
// fp32 -> bf16 hi/lo split (flat arrays)
// ---------------------------------------------------------------------------
__global__ __launch_bounds__(256) void split_hl(
    const float* __restrict__ s, __nv_bfloat16* __restrict__ h,
    __nv_bfloat16* __restrict__ l, int n)
{
    int i = (blockIdx.x * 256 + threadIdx.x) * 4;
    if (i >= n) return;
    float4 v = *(const float4*)(s + i);
    uint32_t h01 = pack_hi(v.x, v.y), h23 = pack_hi(v.z, v.w);
    uint32_t l01 = pack_res(v.x, v.y, h01), l23 = pack_res(v.z, v.w, h23);
    *(uint32_t*)(h + i) = h01; *(uint32_t*)(h + i + 2) = h23;
    *(uint32_t*)(l + i) = l01; *(uint32_t*)(l + i + 2) = l23;
}

// ---------------------------------------------------------------------------
// qkv fp32 [M, 3C] -> q/k/v hi/lo bf16 [B,H,T,64]
// Thread handles 4 consecutive cols (never crosses a 64-col head group).
// ---------------------------------------------------------------------------
__global__ __launch_bounds__(256) void qkv_split(
    const float* __restrict__ qkv,
    __nv_bfloat16* __restrict__ qh, __nv_bfloat16* __restrict__ ql,
    __nv_bfloat16* __restrict__ kh, __nv_bfloat16* __restrict__ kl,
    __nv_bfloat16* __restrict__ vh, __nv_bfloat16* __restrict__ vl)
{
    size_t i = ((size_t)blockIdx.x * 256 + threadIdx.x) * 4;
    int row = (int)(i / C3_), col = (int)(i % C3_);
    float4 v = *(const float4*)(qkv + i);
    int which = col >> 10;
    int hc = col & 1023;
    int head = hc >> 6, d = hc & 63;
    int b = row >> 11, t = row & 2047;
    __nv_bfloat16* Oh = (which == 0) ? qh : (which == 1) ? kh : vh;
    __nv_bfloat16* Ol = (which == 0) ? ql : (which == 1) ? kl : vl;
    size_t idx = ((((size_t)b * H_) + head) * T_ + t) * HD_ + d;
    uint2 hh, ll;
    hh.x = pack_hi(v.x, v.y); hh.y = pack_hi(v.z, v.w);
    ll.x = pack_res(v.x, v.y, hh.x); ll.y = pack_res(v.z, v.w, hh.y);
    *(uint2*)(Oh + idx) = hh;
    *(uint2*)(Ol + idx) = ll;
}

// ---------------------------------------------------------------------------
// Tensor-core flash attention consuming pre-split bf16 q/k/v [B,H,T,64].
// 128 q-rows/CTA, 8 warps x 16 rows, 64-key tiles, uniform depth-2 pipeline.
// ---------------------------------------------------------------------------
#define PITCH 72
#define OPB   (64 * PITCH * 2)         // 9216 bytes per operand tile
#define BUF_B (4 * OPB)                // 36864
#define ATTN_SMEM (2 * BUF_B)          // 73728

__global__ __launch_bounds__(256, 1) void flash_attn_tc(
    const __nv_bfloat16* __restrict__ qh, const __nv_bfloat16* __restrict__ ql,
    const __nv_bfloat16* __restrict__ kh, const __nv_bfloat16* __restrict__ kl,
    const __nv_bfloat16* __restrict__ vh, const __nv_bfloat16* __restrict__ vl,
    const int* __restrict__ lenp,
    __nv_bfloat16* __restrict__ yh, __nv_bfloat16* __restrict__ yl)
{
    extern __shared__ char smdyn[];

    const int b = blockIdx.z, h = blockIdx.y, qt = blockIdx.x;
    const int q0 = qt * 128;
    const int tid = threadIdx.x;
    const int warp = tid >> 5, lane = tid & 31;
    const int len = lenp[b];
    const size_t bh = ((size_t)b * H_ + h) * T_ * HD_;

    const int kt_len = (len + 63) >> 6;
    const int kt_max = min(2 * qt + 1, kt_len - 1);

    // tile kt lives in buffer (kt+1)&1 ; Q staged in buffer 0
    auto issue_kv = [&](int kt, int buf) {
        char* st = smdyn + buf * BUF_B;
        const size_t kbase = bh + (size_t)(kt * 64) * HD_;
        #pragma unroll
        for (int t = 0; t < 8; t++) {
            int e = tid + t * 256;            // 0..2047
            int op = e >> 9;                  // 0..3 : Kh,Kl,Vh,Vl
            int idx = e & 511;
            int r = idx >> 3, c16 = idx & 7;
            const __nv_bfloat16* src =
                (op == 0) ? kh : (op == 1) ? kl : (op == 2) ? vh : vl;
            CP_ASYNC16(smem_u32(st + op * OPB + (r * PITCH + c16 * 8) * 2),
                       src + kbase + (size_t)r * HD_ + c16 * 8);
        }
        CP_COMMIT();
    };

    // stage Q hi/lo (128 rows) into buffer 0: Qh at 0, Ql at 2*OPB
    {
        char* st = smdyn;
        const size_t qbase = bh + (size_t)q0 * HD_;
        #pragma unroll
        for (int t = 0; t < 8; t++) {
            int e = tid + t * 256;
            int part = e >> 10;               // 0=hi 1=lo
            int idx = e & 1023;
            int r = idx >> 3, c16 = idx & 7;
            const __nv_bfloat16* src = part ? ql : qh;
            CP_ASYNC16(smem_u32(st + part * 2 * OPB + (r * PITCH + c16 * 8) * 2),
                       src + qbase + (size_t)r * HD_ + c16 * 8);
        }
        CP_COMMIT();                           // group: Q
    }
    issue_kv(0, 1);                            // group: kv0 -> buf1
    CP_WAIT1();                                // Q arrived
    __syncthreads();

    uint32_t qfh[4][4], qfl[4][4];
    {
        __nv_bfloat16* Qh = (__nv_bfloat16*)smdyn;
        __nv_bfloat16* Ql = (__nv_bfloat16*)(smdyn + 2 * OPB);
        int row = warp * 16 + (lane & 7) + 8 * ((lane >> 3) & 1);
        #pragma unroll
        for (int ks = 0; ks < 4; ks++) {
            int col = ks * 16 + 8 * (lane >> 4);
            LDSM_X4(qfh[ks], smem_u32(Qh + row * PITCH + col));
            LDSM_X4(qfl[ks], smem_u32(Ql + row * PITCH + col));
        }
    }
    __syncthreads();                           // buf0 free
    issue_kv(min(1, kt_max), 0);               // group: kv1 -> buf0 (clamped)

    float m_[2] = {-1e30f, -1e30f}, l_[2] = {0.f, 0.f};
    float O[8][4] = {};

    const int wrow_max = q0 + warp * 16 + 15;
    const int r0 = lane >> 2, cb = (lane & 3) * 2;
    const int row0 = q0 + warp * 16 + r0, row1 = row0 + 8;

    for (int kt = 0; kt <= kt_max; kt++) {
        const int k0 = kt * 64;
        CP_WAIT1();                            // tile kt resident
        __syncthreads();

        char* st = smdyn + ((kt + 1) & 1) * BUF_B;
        __nv_bfloat16* Kh = (__nv_bfloat16*)st;
        __nv_bfloat16* Kl = (__nv_bfloat16*)(st + OPB);
        __nv_bfloat16* Vh = (__nv_bfloat16*)(st + 2 * OPB);
        __nv_bfloat16* Vl = (__nv_bfloat16*)(st + 3 * OPB);

        if (k0 <= wrow_max) {
            // ---- S = Q K^T (3 split terms) ----
            float S[8][4] = {};
            {
                int krow = (lane & 7);
                int kcol8 = 8 * ((lane >> 3) & 1);
                #pragma unroll
                for (int nb = 0; nb < 8; nb++) {
                    #pragma unroll
                    for (int ks = 0; ks < 4; ks++) {
                        uint32_t bh0, bh1, bl0, bl1;
                        LDSM_X2(bh0, bh1, smem_u32(Kh + (nb * 8 + krow) * PITCH + ks * 16 + kcol8));
                        LDSM_X2(bl0, bl1, smem_u32(Kl + (nb * 8 + krow) * PITCH + ks * 16 + kcol8));
                        MMA16816(S[nb], qfh[ks], bh0, bh1);
                        MMA16816(S[nb], qfl[ks], bh0, bh1);
                        MMA16816(S[nb], qfh[ks], bl0, bl1);
                    }
                }
            }

            // ---- mask + online softmax ----
            float ml0 = -1e30f, ml1 = -1e30f;
            #pragma unroll
            for (int nb = 0; nb < 8; nb++) {
                int c0 = k0 + nb * 8 + cb;
                S[nb][0] = (c0     <= row0 && c0     < len) ? S[nb][0] * 0.125f : -1e30f;
                S[nb][1] = (c0 + 1 <= row0 && c0 + 1 < len) ? S[nb][1] * 0.125f : -1e30f;
                S[nb][2] = (c0     <= row1 && c0     < len) ? S[nb][2] * 0.125f : -1e30f;
                S[nb][3] = (c0 + 1 <= row1 && c0 + 1 < len) ? S[nb][3] * 0.125f : -1e30f;
                ml0 = fmaxf(ml0, fmaxf(S[nb][0], S[nb][1]));
                ml1 = fmaxf(ml1, fmaxf(S[nb][2], S[nb][3]));
            }
            ml0 = fmaxf(ml0, __shfl_xor_sync(0xffffffffu, ml0, 1));
            ml0 = fmaxf(ml0, __shfl_xor_sync(0xffffffffu, ml0, 2));
            ml1 = fmaxf(ml1, __shfl_xor_sync(0xffffffffu, ml1, 1));
            ml1 = fmaxf(ml1, __shfl_xor_sync(0xffffffffu, ml1, 2));
            float mn0 = fmaxf(m_[0], ml0), mn1 = fmaxf(m_[1], ml1);
            float corr0 = __expf(m_[0] - mn0), corr1 = __expf(m_[1] - mn1);
            float ls0 = 0.f, ls1 = 0.f;
            #pragma unroll
            for (int nb = 0; nb < 8; nb++) {
                S[nb][0] = __expf(S[nb][0] - mn0); ls0 += S[nb][0];
                S[nb][1] = __expf(S[nb][1] - mn0); ls0 += S[nb][1];
                S[nb][2] = __expf(S[nb][2] - mn1); ls1 += S[nb][2];
                S[nb][3] = __expf(S[nb][3] - mn1); ls1 += S[nb][3];
            }
            ls0 += __shfl_xor_sync(0xffffffffu, ls0, 1);
            ls0 += __shfl_xor_sync(0xffffffffu, ls0, 2);
            ls1 += __shfl_xor_sync(0xffffffffu, ls1, 1);
            ls1 += __shfl_xor_sync(0xffffffffu, ls1, 2);
            l_[0] = l_[0] * corr0 + ls0;
            l_[1] = l_[1] * corr1 + ls1;
            m_[0] = mn0; m_[1] = mn1;
            #pragma unroll
            for (int nb = 0; nb < 8; nb++) {
                O[nb][0] *= corr0; O[nb][1] *= corr0;
                O[nb][2] *= corr1; O[nb][3] *= corr1;
            }

            // ---- O += P V (3 split terms) ----
            {
                int vrow8 = (lane & 7) + 8 * ((lane >> 3) & 1);
                #pragma unroll
                for (int ks = 0; ks < 4; ks++) {
                    uint32_t ph[4], pl[4];
                    ph[0] = pack_hi(S[2 * ks][0], S[2 * ks][1]);
                    ph[1] = pack_hi(S[2 * ks][2], S[2 * ks][3]);
                    ph[2] = pack_hi(S[2 * ks + 1][0], S[2 * ks + 1][1]);
                    ph[3] = pack_hi(S[2 * ks + 1][2], S[2 * ks + 1][3]);
                    pl[0] = pack_res(S[2 * ks][0], S[2 * ks][1], ph[0]);
                    pl[1] = pack_res(S[2 * ks][2], S[2 * ks][3], ph[1]);
                    pl[2] = pack_res(S[2 * ks + 1][0], S[2 * ks + 1][1], ph[2]);
                    pl[3] = pack_res(S[2 * ks + 1][2], S[2 * ks + 1][3], ph[3]);
                    #pragma unroll
                    for (int nb = 0; nb < 8; nb++) {
                        uint32_t vh0, vh1, vl0, vl1;
                        LDSM_X2T(vh0, vh1, smem_u32(Vh + (ks * 16 + vrow8) * PITCH + nb * 8));
                        LDSM_X2T(vl0, vl1, smem_u32(Vl + (ks * 16 + vrow8) * PITCH + nb * 8));
                        MMA16816(O[nb], ph, vh0, vh1);
                        MMA16816(O[nb], pl, vh0, vh1);
                        MMA16816(O[nb], ph, vl0, vl1);
                    }
                }
            }
        }

        __syncthreads();                       // all warps done with this buffer
        issue_kv(min(kt + 2, kt_max), (kt + 1) & 1);   // uniform, clamped
    }

    // ---- epilogue: normalize, split hi/lo, store ----
    float inv0 = (row0 < len && l_[0] > 0.f) ? (1.f / l_[0]) : 0.f;
    float inv1 = (row1 < len && l_[1] > 0.f) ? (1.f / l_[1]) : 0.f;
    size_t rb0 = ((size_t)b * T_ + row0) * C_;
    size_t rb1 = ((size_t)b * T_ + row1) * C_;
    #pragma unroll
    for (int nb = 0; nb < 8; nb++) {
        int hcol = h * HD_ + nb * 8 + cb;
        uint32_t h0 = pack_hi(O[nb][0] * inv0, O[nb][1] * inv0);
        uint32_t l0 = pack_res(O[nb][0] * inv0, O[nb][1] * inv0, h0);
        uint32_t h1 = pack_hi(O[nb][2] * inv1, O[nb][3] * inv1);
        uint32_t l1 = pack_res(O[nb][2] * inv1, O[nb][3] * inv1, h1);
        *(uint32_t*)(yh + rb0 + hcol) = h0;
        *(uint32_t*)(yl + rb0 + hcol) = l0;
        *(uint32_t*)(yh + rb1 + hcol) = h1;
        *(uint32_t*)(yl + rb1 + hcol) = l1;
    }
}

// ---------------------------------------------------------------------------
extern "C" void kernel_launch(void* const* d_in, const int* in_sizes, int n_in,
                              void* d_out, int out_size)
{
    const float* x    = (const float*)d_in[0];
    const int*   am   = (const int*)  d_in[1];
    const float* Wqkv = (const float*)d_in[2];
    const float* bqkv = (const float*)d_in[3];
    const float* Wo   = (const float*)d_in[4];
    const float* bo   = (const float*)d_in[5];
    float* out = (float*)d_out;

    float* qkv;
    __nv_bfloat16 *xh, *xl, *wqh, *wql, *woh, *wol, *yh, *yl;
    __nv_bfloat16 *qh, *ql, *kh, *kl, *vh, *vl;
    int* lenp;
    cudaGetSymbolAddress((void**)&qkv, g_qkv);
    cudaGetSymbolAddress((void**)&xh, g_xh);   cudaGetSymbolAddress((void**)&xl, g_xl);
    cudaGetSymbolAddress((void**)&wqh, g_wqh); cudaGetSymbolAddress((void**)&wql, g_wql);
    cudaGetSymbolAddress((void**)&woh, g_woh); cudaGetSymbolAddress((void**)&wol, g_wol);
    cudaGetSymbolAddress((void**)&yh, g_yh);   cudaGetSymbolAddress((void**)&yl, g_yl);
    cudaGetSymbolAddress((void**)&qh, g_qh);   cudaGetSymbolAddress((void**)&ql, g_ql);
    cudaGetSymbolAddress((void**)&kh, g_kh);   cudaGetSymbolAddress((void**)&kl, g_kl);
    cudaGetSymbolAddress((void**)&vh, g_vh);   cudaGetSymbolAddress((void**)&vl, g_vl);
    cudaGetSymbolAddress((void**)&lenp, g_len);

    cudaFuncSetAttribute(gemm_bf16, cudaFuncAttributeMaxDynamicSharedMemorySize, GEMM_SMEM);
    cudaFuncSetAttribute(flash_attn_tc, cudaFuncAttributeMaxDynamicSharedMemorySize, ATTN_SMEM);

    int nx = M_ * C_, nwq = C3_ * C_, nwo = C_ * C_;
    compute_len<<<B_, 256>>>(am, lenp);
    split_hl<<<nx  / 1024, 256>>>(x,    xh,  xl,  nx);
    split_hl<<<nwq / 1024, 256>>>(Wqkv, wqh, wql, nwq);
    split_hl<<<nwo / 1024, 256>>>(Wo,   woh, wol, nwo);

    gemm_bf16<<<dim3(C3_ / 128, M_ / 128), 256, GEMM_SMEM>>>(
        xh, xl, wqh, wql, bqkv, qkv, M_, C3_, C_);
    qkv_split<<<(int)((size_t)M_ * C3_ / 1024), 256>>>(
        qkv, qh, ql, kh, kl, vh, vl);
    flash_attn_tc<<<dim3(T_ / 128, H_, B_), 256, ATTN_SMEM>>>(
        qh, ql, kh, kl, vh, vl, lenp, yh, yl);
    gemm_bf16<<<dim3(C_ / 128, M_ / 128), 256, GEMM_SMEM>>>(
        yh, yl, woh, wol, bo, out, M_, C_, C_);
}

// round 12
// speedup vs baseline: 1.5653x; 1.0354x over previous
#include <cuda_runtime.h>
#include <cuda_bf16.h>
#include <cstdint>

// Problem constants
#define B_   4
#define T_   2048
#define C_   1024
#define H_   16
#define HD_  64
#define M_   (B_ * T_)          // 8192
#define C3_  (3 * C_)           // 3072

// ---------------------------------------------------------------------------
// Scratch (device globals)
// ---------------------------------------------------------------------------
__device__ float g_qkv[(size_t)M_ * C3_];
__device__ __nv_bfloat16 g_xh [(size_t)M_  * C_], g_xl [(size_t)M_  * C_];
__device__ __nv_bfloat16 g_wqh[(size_t)C3_ * C_], g_wql[(size_t)C3_ * C_];
__device__ __nv_bfloat16 g_woh[(size_t)C_  * C_], g_wol[(size_t)C_  * C_];
#define QKV_N ((size_t)B_ * H_ * T_ * HD_)
__device__ __nv_bfloat16 g_qh[QKV_N], g_ql[QKV_N];
__device__ __nv_bfloat16 g_kh[QKV_N], g_kl[QKV_N];
__device__ __nv_bfloat16 g_vh[QKV_N], g_vl[QKV_N];
__device__ __nv_bfloat16 g_yh [(size_t)M_ * C_], g_yl [(size_t)M_ * C_];
__device__ int g_len[B_];

// ---------------------------------------------------------------------------
// Helpers
// ---------------------------------------------------------------------------
__device__ __forceinline__ uint32_t smem_u32(const void* p) {
    uint32_t a;
    asm("{ .reg .u64 t; cvta.to.shared.u64 t, %1; cvt.u32.u64 %0, t; }"
        : "=r"(a) : "l"(p));
    return a;
}

#define MMA16816(C, A, b0, b1)                                                \
    asm volatile(                                                             \
        "mma.sync.aligned.m16n8k16.row.col.f32.bf16.bf16.f32 "                \
        "{%0,%1,%2,%3},{%4,%5,%6,%7},{%8,%9},{%0,%1,%2,%3};"                  \
        : "+f"((C)[0]), "+f"((C)[1]), "+f"((C)[2]), "+f"((C)[3])              \
        : "r"((A)[0]), "r"((A)[1]), "r"((A)[2]), "r"((A)[3]),                 \
          "r"(b0), "r"(b1))

#define LDSM_X4(R, addr)                                                      \
    asm volatile("ldmatrix.sync.aligned.m8n8.x4.shared.b16 {%0,%1,%2,%3}, [%4];" \
        : "=r"((R)[0]), "=r"((R)[1]), "=r"((R)[2]), "=r"((R)[3]) : "r"(addr))

#define LDSM_X2(r0, r1, addr)                                                 \
    asm volatile("ldmatrix.sync.aligned.m8n8.x2.shared.b16 {%0,%1}, [%2];"    \
        : "=r"(r0), "=r"(r1) : "r"(addr))

#define LDSM_X2T(r0, r1, addr)                                                \
    asm volatile("ldmatrix.sync.aligned.m8n8.x2.trans.shared.b16 {%0,%1}, [%2];" \
        : "=r"(r0), "=r"(r1) : "r"(addr))

#define CP_ASYNC16(dst, src)                                                  \
    asm volatile("cp.async.cg.shared.global [%0], [%1], 16;"                  \
                 :: "r"(dst), "l"(src) : "memory")
#define CP_COMMIT() asm volatile("cp.async.commit_group;" ::: "memory")
#define CP_WAIT1()  asm volatile("cp.async.wait_group 1;" ::: "memory")

__device__ __forceinline__ uint32_t pack_hi(float a, float b) {
    __nv_bfloat162 v = __floats2bfloat162_rn(a, b);
    return *reinterpret_cast<uint32_t*>(&v);
}
__device__ __forceinline__ uint32_t pack_res(float a, float b, uint32_t hp) {
    __nv_bfloat162 h = *reinterpret_cast<__nv_bfloat162*>(&hp);
    __nv_bfloat162 v = __floats2bfloat162_rn(a - __bfloat162float(h.x),
                                             b - __bfloat162float(h.y));
    return *reinterpret_cast<uint32_t*>(&v);
}

// ---------------------------------------------------------------------------
// HMMA GEMM (R6 measured-best): Cout[M,N] = (Ah+Al)@(Wh+Wl)^T + bias, fp32 out
// 128x128 tile, k-chunk 16, 3-stage cp.async, 2 CTAs/SM, lean epilogue.
// ---------------------------------------------------------------------------
#define GTILE_B    6144
#define GSTAGE_B   (4 * GTILE_B)
#define GEMM_SMEM  (3 * GSTAGE_B)

__global__ __launch_bounds__(256, 2) void gemm_bf16(
    const __nv_bfloat16* __restrict__ Ah, const __nv_bfloat16* __restrict__ Al,
    const __nv_bfloat16* __restrict__ Wh, const __nv_bfloat16* __restrict__ Wl,
    const float* __restrict__ bias, float* __restrict__ Cout,
    int M, int N, int K)
{
    extern __shared__ char sm[];
    const int tid = threadIdx.x;
    const int bm = blockIdx.y * 128;
    const int bn = blockIdx.x * 128;
    const int warp = tid >> 5, lane = tid & 31;
    const int moff = (warp >> 1) * 32;
    const int noff = (warp & 1) * 64;

    float acc[2][8][4];
    #pragma unroll
    for (int a = 0; a < 2; a++)
        #pragma unroll
        for (int b = 0; b < 8; b++)
            #pragma unroll
            for (int c = 0; c < 4; c++) acc[a][b][c] = 0.f;

    const int r_ld = tid >> 1, half8 = (tid & 1) * 8;
    auto issue = [&](int c, int s) {
        const int k0 = c << 4;
        char* st = sm + s * GSTAGE_B;
        uint32_t d = smem_u32(st + (r_ld * 24 + half8) * 2);
        CP_ASYNC16(d,               Ah + (size_t)(bm + r_ld) * K + k0 + half8);
        CP_ASYNC16(d + GTILE_B,     Al + (size_t)(bm + r_ld) * K + k0 + half8);
        CP_ASYNC16(d + 2 * GTILE_B, Wh + (size_t)(bn + r_ld) * K + k0 + half8);
        CP_ASYNC16(d + 3 * GTILE_B, Wl + (size_t)(bn + r_ld) * K + k0 + half8);
        CP_COMMIT();
    };

    const int nk = K >> 4;
    issue(0, 0);
    issue(1, 1);

    const int arow = moff + (lane & 7) + 8 * ((lane >> 3) & 1);
    const int acol = 8 * (lane >> 4);
    const int wrow_l = (lane & 7);
    const int wcol = 8 * ((lane >> 3) & 1);

    int s = 0;
    for (int c = 0; c < nk; c++) {
        CP_WAIT1();
        __syncthreads();
        if (c + 2 < nk) issue(c + 2, (s + 2 >= 3) ? s - 1 : s + 2);
        else CP_COMMIT();

        char* st = sm + s * GSTAGE_B;
        uint32_t ah[2][4], al[2][4];
        #pragma unroll
        for (int mb = 0; mb < 2; mb++) {
            LDSM_X4(ah[mb], smem_u32(st + ((arow + mb * 16) * 24 + acol) * 2));
            LDSM_X4(al[mb], smem_u32(st + GTILE_B + ((arow + mb * 16) * 24 + acol) * 2));
        }
        #pragma unroll
        for (int nb = 0; nb < 8; nb++) {
            int wr = noff + nb * 8 + wrow_l;
            uint32_t bh0, bh1, bl0, bl1;
            LDSM_X2(bh0, bh1, smem_u32(st + 2 * GTILE_B + (wr * 24 + wcol) * 2));
            LDSM_X2(bl0, bl1, smem_u32(st + 3 * GTILE_B + (wr * 24 + wcol) * 2));
            #pragma unroll
            for (int mb = 0; mb < 2; mb++) {
                MMA16816(acc[mb][nb], ah[mb], bh0, bh1);
                MMA16816(acc[mb][nb], al[mb], bh0, bh1);
                MMA16816(acc[mb][nb], ah[mb], bl0, bl1);
            }
        }
        s = (s + 1 >= 3) ? 0 : s + 1;
    }

    const int r0 = lane >> 2, c0 = (lane & 3) * 2;
    #pragma unroll
    for (int mb = 0; mb < 2; mb++)
        #pragma unroll
        for (int nb = 0; nb < 8; nb++) {
            int row = bm + moff + mb * 16 + r0;
            int col = bn + noff + nb * 8 + c0;
            float2 v0 = make_float2(acc[mb][nb][0] + bias[col],
                                    acc[mb][nb][1] + bias[col + 1]);
            *(float2*)(Cout + (size_t)row * N + col) = v0;
            float2 v1 = make_float2(acc[mb][nb][2] + bias[col],
                                    acc[mb][nb][3] + bias[col + 1]);
            *(float2*)(Cout + (size_t)(row + 8) * N + col) = v1;
        }
}

// ---------------------------------------------------------------------------
// per-batch valid length
// ---------------------------------------------------------------------------
__global__ void compute_len(const int* __restrict__ am, int* __restrict__ out) {
    __shared__ int red[8];
    int b = blockIdx.x, acc = 0;
    for (int i = threadIdx.x; i < T_; i += 256) acc += am[b * T_ + i];
    #pragma unroll
    for (int o = 16; o; o >>= 1) acc += __shfl_xor_sync(0xffffffffu, acc, o);
    if ((threadIdx.x & 31) == 0) red[threadIdx.x >> 5] = acc;
    __syncthreads();
    if (threadIdx.x == 0) {
        int v = 0;
        #pragma unroll
        for (int i = 0; i < 8; i++) v += red[i];
        out[b] = v;
    }
}

// ---------------------------------------------------------------------------
// fp32 -> bf16 hi/lo split (flat arrays)
// ---------------------------------------------------------------------------
__global__ __launch_bounds__(256) void split_hl(
    const float* __restrict__ s, __nv_bfloat16* __restrict__ h,
    __nv_bfloat16* __restrict__ l, int n)
{
    int i = (blockIdx.x * 256 + threadIdx.x) * 4;
    if (i >= n) return;
    float4 v = *(const float4*)(s + i);
    uint32_t h01 = pack_hi(v.x, v.y), h23 = pack_hi(v.z, v.w);
    uint32_t l01 = pack_res(v.x, v.y, h01), l23 = pack_res(v.z, v.w, h23);
    *(uint32_t*)(h + i) = h01; *(uint32_t*)(h + i + 2) = h23;
    *(uint32_t*)(l + i) = l01; *(uint32_t*)(l + i + 2) = l23;
}

// ---------------------------------------------------------------------------
// qkv fp32 [M, 3C] -> q/k/v hi/lo bf16 [B,H,T,64]
// ---------------------------------------------------------------------------
__global__ __launch_bounds__(256) void qkv_split(
    const float* __restrict__ qkv,
    __nv_bfloat16* __restrict__ qh, __nv_bfloat16* __restrict__ ql,
    __nv_bfloat16* __restrict__ kh, __nv_bfloat16* __restrict__ kl,
    __nv_bfloat16* __restrict__ vh, __nv_bfloat16* __restrict__ vl)
{
    size_t i = ((size_t)blockIdx.x * 256 + threadIdx.x) * 4;
    int row = (int)(i / C3_), col = (int)(i % C3_);
    float4 v = *(const float4*)(qkv + i);
    int which = col >> 10;
    int hc = col & 1023;
    int head = hc >> 6, d = hc & 63;
    int b = row >> 11, t = row & 2047;
    __nv_bfloat16* Oh = (which == 0) ? qh : (which == 1) ? kh : vh;
    __nv_bfloat16* Ol = (which == 0) ? ql : (which == 1) ? kl : vl;
    size_t idx = ((((size_t)b * H_) + head) * T_ + t) * HD_ + d;
    uint2 hh, ll;
    hh.x = pack_hi(v.x, v.y); hh.y = pack_hi(v.z, v.w);
    ll.x = pack_res(v.x, v.y, hh.x); ll.y = pack_res(v.z, v.w, hh.y);
    *(uint2*)(Oh + idx) = hh;
    *(uint2*)(Ol + idx) = ll;
}

// ---------------------------------------------------------------------------
// Tensor-core flash attention consuming pre-split bf16 q/k/v [B,H,T,64].
// 128 q-rows/CTA, 8 warps x 16 rows, 64-key tiles, uniform depth-2 pipeline.
// R11: reversed qt (LPT: heavy CTAs first) + early-exit fully-masked q-tiles.
// ---------------------------------------------------------------------------
#define PITCH 72
#define OPB   (64 * PITCH * 2)         // 9216 bytes per operand tile
#define BUF_B (4 * OPB)                // 36864
#define ATTN_SMEM (2 * BUF_B)          // 73728

__global__ __launch_bounds__(256, 1) void flash_attn_tc(
    const __nv_bfloat16* __restrict__ qh, const __nv_bfloat16* __restrict__ ql,
    const __nv_bfloat16* __restrict__ kh, const __nv_bfloat16* __restrict__ kl,
    const __nv_bfloat16* __restrict__ vh, const __nv_bfloat16* __restrict__ vl,
    const int* __restrict__ lenp,
    __nv_bfloat16* __restrict__ yh, __nv_bfloat16* __restrict__ yl)
{
    extern __shared__ char smdyn[];

    const int b = blockIdx.z, h = blockIdx.y;
    const int qt = (int)(gridDim.x - 1 - blockIdx.x);   // LPT: heavy first
    const int q0 = qt * 128;
    const int tid = threadIdx.x;
    const int warp = tid >> 5, lane = tid & 31;
    const int len = lenp[b];
    const size_t bh = ((size_t)b * H_ + h) * T_ * HD_;

    // fully-masked q-tile: write zeros, skip all compute
    if (q0 >= len) {
        const size_t ybase = ((size_t)b * T_ + q0) * C_ + h * HD_;
        const uint2 z = make_uint2(0u, 0u);
        #pragma unroll
        for (int t = 0; t < 8; t++) {
            int e = tid + t * 256;            // 0..2047 uint2 slots
            int r = e >> 4, c4 = (e & 15) * 4;
            *(uint2*)(yh + ybase + (size_t)r * C_ + c4) = z;
            *(uint2*)(yl + ybase + (size_t)r * C_ + c4) = z;
        }
        return;
    }

    const int kt_len = (len + 63) >> 6;
    const int kt_max = min(2 * qt + 1, kt_len - 1);

    // tile kt lives in buffer (kt+1)&1 ; Q staged in buffer 0
    auto issue_kv = [&](int kt, int buf) {
        char* st = smdyn + buf * BUF_B;
        const size_t kbase = bh + (size_t)(kt * 64) * HD_;
        #pragma unroll
        for (int t = 0; t < 8; t++) {
            int e = tid + t * 256;            // 0..2047
            int op = e >> 9;                  // 0..3 : Kh,Kl,Vh,Vl
            int idx = e & 511;
            int r = idx >> 3, c16 = idx & 7;
            const __nv_bfloat16* src =
                (op == 0) ? kh : (op == 1) ? kl : (op == 2) ? vh : vl;
            CP_ASYNC16(smem_u32(st + op * OPB + (r * PITCH + c16 * 8) * 2),
                       src + kbase + (size_t)r * HD_ + c16 * 8);
        }
        CP_COMMIT();
    };

    // stage Q hi/lo (128 rows) into buffer 0: Qh at 0, Ql at 2*OPB
    {
        char* st = smdyn;
        const size_t qbase = bh + (size_t)q0 * HD_;
        #pragma unroll
        for (int t = 0; t < 8; t++) {
            int e = tid + t * 256;
            int part = e >> 10;               // 0=hi 1=lo
            int idx = e & 1023;
            int r = idx >> 3, c16 = idx & 7;
            const __nv_bfloat16* src = part ? ql : qh;
            CP_ASYNC16(smem_u32(st + part * 2 * OPB + (r * PITCH + c16 * 8) * 2),
                       src + qbase + (size_t)r * HD_ + c16 * 8);
        }
        CP_COMMIT();                           // group: Q
    }
    issue_kv(0, 1);                            // group: kv0 -> buf1
    CP_WAIT1();                                // Q arrived
    __syncthreads();

    uint32_t qfh[4][4], qfl[4][4];
    {
        __nv_bfloat16* Qh = (__nv_bfloat16*)smdyn;
        __nv_bfloat16* Ql = (__nv_bfloat16*)(smdyn + 2 * OPB);
        int row = warp * 16 + (lane & 7) + 8 * ((lane >> 3) & 1);
        #pragma unroll
        for (int ks = 0; ks < 4; ks++) {
            int col = ks * 16 + 8 * (lane >> 4);
            LDSM_X4(qfh[ks], smem_u32(Qh + row * PITCH + col));
            LDSM_X4(qfl[ks], smem_u32(Ql + row * PITCH + col));
        }
    }
    __syncthreads();                           // buf0 free
    issue_kv(min(1, kt_max), 0);               // group: kv1 -> buf0 (clamped)

    float m_[2] = {-1e30f, -1e30f}, l_[2] = {0.f, 0.f};
    float O[8][4] = {};

    const int wrow_max = q0 + warp * 16 + 15;
    const int r0 = lane >> 2, cb = (lane & 3) * 2;
    const int row0 = q0 + warp * 16 + r0, row1 = row0 + 8;

    for (int kt = 0; kt <= kt_max; kt++) {
        const int k0 = kt * 64;
        CP_WAIT1();                            // tile kt resident
        __syncthreads();

        char* st = smdyn + ((kt + 1) & 1) * BUF_B;
        __nv_bfloat16* Kh = (__nv_bfloat16*)st;
        __nv_bfloat16* Kl = (__nv_bfloat16*)(st + OPB);
        __nv_bfloat16* Vh = (__nv_bfloat16*)(st + 2 * OPB);
        __nv_bfloat16* Vl = (__nv_bfloat16*)(st + 3 * OPB);

        if (k0 <= wrow_max) {
            // ---- S = Q K^T (3 split terms) ----
            float S[8][4] = {};
            {
                int krow = (lane & 7);
                int kcol8 = 8 * ((lane >> 3) & 1);
                #pragma unroll
                for (int nb = 0; nb < 8; nb++) {
                    #pragma unroll
                    for (int ks = 0; ks < 4; ks++) {
                        uint32_t bh0, bh1, bl0, bl1;
                        LDSM_X2(bh0, bh1, smem_u32(Kh + (nb * 8 + krow) * PITCH + ks * 16 + kcol8));
                        LDSM_X2(bl0, bl1, smem_u32(Kl + (nb * 8 + krow) * PITCH + ks * 16 + kcol8));
                        MMA16816(S[nb], qfh[ks], bh0, bh1);
                        MMA16816(S[nb], qfl[ks], bh0, bh1);
                        MMA16816(S[nb], qfh[ks], bl0, bl1);
                    }
                }
            }

            // ---- mask + online softmax ----
            float ml0 = -1e30f, ml1 = -1e30f;
            #pragma unroll
            for (int nb = 0; nb < 8; nb++) {
                int c0 = k0 + nb * 8 + cb;
                S[nb][0] = (c0     <= row0 && c0     < len) ? S[nb][0] * 0.125f : -1e30f;
                S[nb][1] = (c0 + 1 <= row0 && c0 + 1 < len) ? S[nb][1] * 0.125f : -1e30f;
                S[nb][2] = (c0     <= row1 && c0     < len) ? S[nb][2] * 0.125f : -1e30f;
                S[nb][3] = (c0 + 1 <= row1 && c0 + 1 < len) ? S[nb][3] * 0.125f : -1e30f;
                ml0 = fmaxf(ml0, fmaxf(S[nb][0], S[nb][1]));
                ml1 = fmaxf(ml1, fmaxf(S[nb][2], S[nb][3]));
            }
            ml0 = fmaxf(ml0, __shfl_xor_sync(0xffffffffu, ml0, 1));
            ml0 = fmaxf(ml0, __shfl_xor_sync(0xffffffffu, ml0, 2));
            ml1 = fmaxf(ml1, __shfl_xor_sync(0xffffffffu, ml1, 1));
            ml1 = fmaxf(ml1, __shfl_xor_sync(0xffffffffu, ml1, 2));
            float mn0 = fmaxf(m_[0], ml0), mn1 = fmaxf(m_[1], ml1);
            float corr0 = __expf(m_[0] - mn0), corr1 = __expf(m_[1] - mn1);
            float ls0 = 0.f, ls1 = 0.f;
            #pragma unroll
            for (int nb = 0; nb < 8; nb++) {
                S[nb][0] = __expf(S[nb][0] - mn0); ls0 += S[nb][0];
                S[nb][1] = __expf(S[nb][1] - mn0); ls0 += S[nb][1];
                S[nb][2] = __expf(S[nb][2] - mn1); ls1 += S[nb][2];
                S[nb][3] = __expf(S[nb][3] - mn1); ls1 += S[nb][3];
            }
            ls0 += __shfl_xor_sync(0xffffffffu, ls0, 1);
            ls0 += __shfl_xor_sync(0xffffffffu, ls0, 2);
            ls1 += __shfl_xor_sync(0xffffffffu, ls1, 1);
            ls1 += __shfl_xor_sync(0xffffffffu, ls1, 2);
            l_[0] = l_[0] * corr0 + ls0;
            l_[1] = l_[1] * corr1 + ls1;
            m_[0] = mn0; m_[1] = mn1;
            #pragma unroll
            for (int nb = 0; nb < 8; nb++) {
                O[nb][0] *= corr0; O[nb][1] *= corr0;
                O[nb][2] *= corr1; O[nb][3] *= corr1;
            }

            // ---- O += P V (3 split terms) ----
            {
                int vrow8 = (lane & 7) + 8 * ((lane >> 3) & 1);
                #pragma unroll
                for (int ks = 0; ks < 4; ks++) {
                    uint32_t ph[4], pl[4];
                    ph[0] = pack_hi(S[2 * ks][0], S[2 * ks][1]);
                    ph[1] = pack_hi(S[2 * ks][2], S[2 * ks][3]);
                    ph[2] = pack_hi(S[2 * ks + 1][0], S[2 * ks + 1][1]);
                    ph[3] = pack_hi(S[2 * ks + 1][2], S[2 * ks + 1][3]);
                    pl[0] = pack_res(S[2 * ks][0], S[2 * ks][1], ph[0]);
                    pl[1] = pack_res(S[2 * ks][2], S[2 * ks][3], ph[1]);
                    pl[2] = pack_res(S[2 * ks + 1][0], S[2 * ks + 1][1], ph[2]);
                    pl[3] = pack_res(S[2 * ks + 1][2], S[2 * ks + 1][3], ph[3]);
                    #pragma unroll
                    for (int nb = 0; nb < 8; nb++) {
                        uint32_t vh0, vh1, vl0, vl1;
                        LDSM_X2T(vh0, vh1, smem_u32(Vh + (ks * 16 + vrow8) * PITCH + nb * 8));
                        LDSM_X2T(vl0, vl1, smem_u32(Vl + (ks * 16 + vrow8) * PITCH + nb * 8));
                        MMA16816(O[nb], ph, vh0, vh1);
                        MMA16816(O[nb], pl, vh0, vh1);
                        MMA16816(O[nb], ph, vl0, vl1);
                    }
                }
            }
        }

        __syncthreads();                       // all warps done with this buffer
        issue_kv(min(kt + 2, kt_max), (kt + 1) & 1);   // uniform, clamped
    }

    // ---- epilogue: normalize, split hi/lo, store ----
    float inv0 = (row0 < len && l_[0] > 0.f) ? (1.f / l_[0]) : 0.f;
    float inv1 = (row1 < len && l_[1] > 0.f) ? (1.f / l_[1]) : 0.f;
    size_t rb0 = ((size_t)b * T_ + row0) * C_;
    size_t rb1 = ((size_t)b * T_ + row1) * C_;
    #pragma unroll
    for (int nb = 0; nb < 8; nb++) {
        int hcol = h * HD_ + nb * 8 + cb;
        uint32_t h0 = pack_hi(O[nb][0] * inv0, O[nb][1] * inv0);
        uint32_t l0 = pack_res(O[nb][0] * inv0, O[nb][1] * inv0, h0);
        uint32_t h1 = pack_hi(O[nb][2] * inv1, O[nb][3] * inv1);
        uint32_t l1 = pack_res(O[nb][2] * inv1, O[nb][3] * inv1, h1);
        *(uint32_t*)(yh + rb0 + hcol) = h0;
        *(uint32_t*)(yl + rb0 + hcol) = l0;
        *(uint32_t*)(yh + rb1 + hcol) = h1;
        *(uint32_t*)(yl + rb1 + hcol) = l1;
    }
}

// ---------------------------------------------------------------------------
extern "C" void kernel_launch(void* const* d_in, const int* in_sizes, int n_in,
                              void* d_out, int out_size)
{
    const float* x    = (const float*)d_in[0];
    const int*   am   = (const int*)  d_in[1];
    const float* Wqkv = (const float*)d_in[2];
    const float* bqkv = (const float*)d_in[3];
    const float* Wo   = (const float*)d_in[4];
    const float* bo   = (const float*)d_in[5];
    float* out = (float*)d_out;

    float* qkv;
    __nv_bfloat16 *xh, *xl, *wqh, *wql, *woh, *wol, *yh, *yl;
    __nv_bfloat16 *qh, *ql, *kh, *kl, *vh, *vl;
    int* lenp;
    cudaGetSymbolAddress((void**)&qkv, g_qkv);
    cudaGetSymbolAddress((void**)&xh, g_xh);   cudaGetSymbolAddress((void**)&xl, g_xl);
    cudaGetSymbolAddress((void**)&wqh, g_wqh); cudaGetSymbolAddress((void**)&wql, g_wql);
    cudaGetSymbolAddress((void**)&woh, g_woh); cudaGetSymbolAddress((void**)&wol, g_wol);
    cudaGetSymbolAddress((void**)&yh, g_yh);   cudaGetSymbolAddress((void**)&yl, g_yl);
    cudaGetSymbolAddress((void**)&qh, g_qh);   cudaGetSymbolAddress((void**)&ql, g_ql);
    cudaGetSymbolAddress((void**)&kh, g_kh);   cudaGetSymbolAddress((void**)&kl, g_kl);
    cudaGetSymbolAddress((void**)&vh, g_vh);   cudaGetSymbolAddress((void**)&vl, g_vl);
    cudaGetSymbolAddress((void**)&lenp, g_len);

    cudaFuncSetAttribute(gemm_bf16, cudaFuncAttributeMaxDynamicSharedMemorySize, GEMM_SMEM);
    cudaFuncSetAttribute(flash_attn_tc, cudaFuncAttributeMaxDynamicSharedMemorySize, ATTN_SMEM);

    int nx = M_ * C_, nwq = C3_ * C_, nwo = C_ * C_;
    compute_len<<<B_, 256>>>(am, lenp);
    split_hl<<<nx  / 1024, 256>>>(x,    xh,  xl,  nx);
    split_hl<<<nwq / 1024, 256>>>(Wqkv, wqh, wql, nwq);
    split_hl<<<nwo / 1024, 256>>>(Wo,   woh, wol, nwo);

    gemm_bf16<<<dim3(C3_ / 128, M_ / 128), 256, GEMM_SMEM>>>(
        xh, xl, wqh, wql, bqkv, qkv, M_, C3_, C_);
    qkv_split<<<(int)((size_t)M_ * C3_ / 1024), 256>>>(
        qkv, qh, ql, kh, kl, vh, vl);
    flash_attn_tc<<<dim3(T_ / 128, H_, B_), 256, ATTN_SMEM>>>(
        qh, ql, kh, kl, vh, vl, lenp, yh, yl);
    gemm_bf16<<<dim3(C_ / 128, M_ / 128), 256, GEMM_SMEM>>>(
        yh, yl, woh, wol, bo, out, M_, C_, C_);
}

// round 13
// speedup vs baseline: 1.6821x; 1.0747x over previous
#include <cuda_runtime.h>
#include <cuda_bf16.h>
#include <cstdint>

// Problem constants
#define B_   4
#define T_   2048
#define C_   1024
#define H_   16
#define HD_  64
#define M_   (B_ * T_)          // 8192
#define C3_  (3 * C_)           // 3072

// ---------------------------------------------------------------------------
// Scratch (device globals)
// ---------------------------------------------------------------------------
__device__ float g_qkv[(size_t)M_ * C3_];
__device__ __nv_bfloat16 g_xh [(size_t)M_  * C_], g_xl [(size_t)M_  * C_];
__device__ __nv_bfloat16 g_wqh[(size_t)C3_ * C_], g_wql[(size_t)C3_ * C_];
__device__ __nv_bfloat16 g_woh[(size_t)C_  * C_], g_wol[(size_t)C_  * C_];
#define QKV_N ((size_t)B_ * H_ * T_ * HD_)
__device__ __nv_bfloat16 g_qh[QKV_N], g_ql[QKV_N];
__device__ __nv_bfloat16 g_kh[QKV_N], g_kl[QKV_N];
__device__ __nv_bfloat16 g_vh[QKV_N], g_vl[QKV_N];
__device__ __nv_bfloat16 g_yh [(size_t)M_ * C_], g_yl [(size_t)M_ * C_];
__device__ int g_len[B_];

// ---------------------------------------------------------------------------
// Helpers
// ---------------------------------------------------------------------------
__device__ __forceinline__ uint32_t smem_u32(const void* p) {
    uint32_t a;
    asm("{ .reg .u64 t; cvta.to.shared.u64 t, %1; cvt.u32.u64 %0, t; }"
        : "=r"(a) : "l"(p));
    return a;
}

#define MMA16816(C, A, b0, b1)                                                \
    asm volatile(                                                             \
        "mma.sync.aligned.m16n8k16.row.col.f32.bf16.bf16.f32 "                \
        "{%0,%1,%2,%3},{%4,%5,%6,%7},{%8,%9},{%0,%1,%2,%3};"                  \
        : "+f"((C)[0]), "+f"((C)[1]), "+f"((C)[2]), "+f"((C)[3])              \
        : "r"((A)[0]), "r"((A)[1]), "r"((A)[2]), "r"((A)[3]),                 \
          "r"(b0), "r"(b1))

#define LDSM_X4(R, addr)                                                      \
    asm volatile("ldmatrix.sync.aligned.m8n8.x4.shared.b16 {%0,%1,%2,%3}, [%4];" \
        : "=r"((R)[0]), "=r"((R)[1]), "=r"((R)[2]), "=r"((R)[3]) : "r"(addr))

#define LDSM_X2(r0, r1, addr)                                                 \
    asm volatile("ldmatrix.sync.aligned.m8n8.x2.shared.b16 {%0,%1}, [%2];"    \
        : "=r"(r0), "=r"(r1) : "r"(addr))

#define LDSM_X2T(r0, r1, addr)                                                \
    asm volatile("ldmatrix.sync.aligned.m8n8.x2.trans.shared.b16 {%0,%1}, [%2];" \
        : "=r"(r0), "=r"(r1) : "r"(addr))

#define CP_ASYNC16(dst, src)                                                  \
    asm volatile("cp.async.cg.shared.global [%0], [%1], 16;"                  \
                 :: "r"(dst), "l"(src) : "memory")
#define CP_COMMIT() asm volatile("cp.async.commit_group;" ::: "memory")
#define CP_WAIT1()  asm volatile("cp.async.wait_group 1;" ::: "memory")

__device__ __forceinline__ uint32_t pack_hi(float a, float b) {
    __nv_bfloat162 v = __floats2bfloat162_rn(a, b);
    return *reinterpret_cast<uint32_t*>(&v);
}
__device__ __forceinline__ uint32_t pack_res(float a, float b, uint32_t hp) {
    __nv_bfloat162 h = *reinterpret_cast<__nv_bfloat162*>(&hp);
    __nv_bfloat162 v = __floats2bfloat162_rn(a - __bfloat162float(h.x),
                                             b - __bfloat162float(h.y));
    return *reinterpret_cast<uint32_t*>(&v);
}

// ---------------------------------------------------------------------------
// HMMA GEMM: Cout[M,N] = (Ah+Al)@(Wh+Wl)^T + bias, fp32 out
// 128x128 tile, k-chunk 16, 3-stage cp.async, 2 CTAs/SM, lean epilogue.
// MODE 0: plain. MODE 1 (QKV): skip M-tiles fully beyond round_up(len,128).
// MODE 2 (proj): for such tiles write bias rows and exit.
// ---------------------------------------------------------------------------
#define GTILE_B    6144
#define GSTAGE_B   (4 * GTILE_B)
#define GEMM_SMEM  (3 * GSTAGE_B)

template <int MODE>
__global__ __launch_bounds__(256, 2) void gemm_bf16(
    const __nv_bfloat16* __restrict__ Ah, const __nv_bfloat16* __restrict__ Al,
    const __nv_bfloat16* __restrict__ Wh, const __nv_bfloat16* __restrict__ Wl,
    const float* __restrict__ bias, float* __restrict__ Cout,
    const int* __restrict__ lenp,
    int M, int N, int K)
{
    extern __shared__ char sm[];
    const int tid = threadIdx.x;
    const int bm = blockIdx.y * 128;
    const int bn = blockIdx.x * 128;

    if (MODE != 0) {
        const int len = lenp[bm >> 11];            // batch of this M-tile
        const int lim = (len + 127) & ~127;
        if ((bm & 2047) >= lim) {
            if (MODE == 2) {
                // output rows beyond len are exactly bias
                const int c4 = (tid & 31) * 4;     // 32 threads cover 128 cols
                const int rb = tid >> 5;           // 8 row-groups of 16
                float4 bv = *(const float4*)(bias + bn + c4);
                #pragma unroll
                for (int rr = 0; rr < 16; rr++) {
                    int row = bm + rb * 16 + rr;
                    *(float4*)(Cout + (size_t)row * N + bn + c4) = bv;
                }
            }
            return;
        }
    }

    const int warp = tid >> 5, lane = tid & 31;
    const int moff = (warp >> 1) * 32;
    const int noff = (warp & 1) * 64;

    float acc[2][8][4];
    #pragma unroll
    for (int a = 0; a < 2; a++)
        #pragma unroll
        for (int b = 0; b < 8; b++)
            #pragma unroll
            for (int c = 0; c < 4; c++) acc[a][b][c] = 0.f;

    const int r_ld = tid >> 1, half8 = (tid & 1) * 8;
    auto issue = [&](int c, int s) {
        const int k0 = c << 4;
        char* st = sm + s * GSTAGE_B;
        uint32_t d = smem_u32(st + (r_ld * 24 + half8) * 2);
        CP_ASYNC16(d,               Ah + (size_t)(bm + r_ld) * K + k0 + half8);
        CP_ASYNC16(d + GTILE_B,     Al + (size_t)(bm + r_ld) * K + k0 + half8);
        CP_ASYNC16(d + 2 * GTILE_B, Wh + (size_t)(bn + r_ld) * K + k0 + half8);
        CP_ASYNC16(d + 3 * GTILE_B, Wl + (size_t)(bn + r_ld) * K + k0 + half8);
        CP_COMMIT();
    };

    const int nk = K >> 4;
    issue(0, 0);
    issue(1, 1);

    const int arow = moff + (lane & 7) + 8 * ((lane >> 3) & 1);
    const int acol = 8 * (lane >> 4);
    const int wrow_l = (lane & 7);
    const int wcol = 8 * ((lane >> 3) & 1);

    int s = 0;
    for (int c = 0; c < nk; c++) {
        CP_WAIT1();
        __syncthreads();
        if (c + 2 < nk) issue(c + 2, (s + 2 >= 3) ? s - 1 : s + 2);
        else CP_COMMIT();

        char* st = sm + s * GSTAGE_B;
        uint32_t ah[2][4], al[2][4];
        #pragma unroll
        for (int mb = 0; mb < 2; mb++) {
            LDSM_X4(ah[mb], smem_u32(st + ((arow + mb * 16) * 24 + acol) * 2));
            LDSM_X4(al[mb], smem_u32(st + GTILE_B + ((arow + mb * 16) * 24 + acol) * 2));
        }
        #pragma unroll
        for (int nb = 0; nb < 8; nb++) {
            int wr = noff + nb * 8 + wrow_l;
            uint32_t bh0, bh1, bl0, bl1;
            LDSM_X2(bh0, bh1, smem_u32(st + 2 * GTILE_B + (wr * 24 + wcol) * 2));
            LDSM_X2(bl0, bl1, smem_u32(st + 3 * GTILE_B + (wr * 24 + wcol) * 2));
            #pragma unroll
            for (int mb = 0; mb < 2; mb++) {
                MMA16816(acc[mb][nb], ah[mb], bh0, bh1);
                MMA16816(acc[mb][nb], al[mb], bh0, bh1);
                MMA16816(acc[mb][nb], ah[mb], bl0, bl1);
            }
        }
        s = (s + 1 >= 3) ? 0 : s + 1;
    }

    const int r0 = lane >> 2, c0 = (lane & 3) * 2;
    #pragma unroll
    for (int mb = 0; mb < 2; mb++)
        #pragma unroll
        for (int nb = 0; nb < 8; nb++) {
            int row = bm + moff + mb * 16 + r0;
            int col = bn + noff + nb * 8 + c0;
            float2 v0 = make_float2(acc[mb][nb][0] + bias[col],
                                    acc[mb][nb][1] + bias[col + 1]);
            *(float2*)(Cout + (size_t)row * N + col) = v0;
            float2 v1 = make_float2(acc[mb][nb][2] + bias[col],
                                    acc[mb][nb][3] + bias[col + 1]);
            *(float2*)(Cout + (size_t)(row + 8) * N + col) = v1;
        }
}

// ---------------------------------------------------------------------------
// per-batch valid length
// ---------------------------------------------------------------------------
__global__ void compute_len(const int* __restrict__ am, int* __restrict__ out) {
    __shared__ int red[8];
    int b = blockIdx.x, acc = 0;
    for (int i = threadIdx.x; i < T_; i += 256) acc += am[b * T_ + i];
    #pragma unroll
    for (int o = 16; o; o >>= 1) acc += __shfl_xor_sync(0xffffffffu, acc, o);
    if ((threadIdx.x & 31) == 0) red[threadIdx.x >> 5] = acc;
    __syncthreads();
    if (threadIdx.x == 0) {
        int v = 0;
        #pragma unroll
        for (int i = 0; i < 8; i++) v += red[i];
        out[b] = v;
    }
}

// ---------------------------------------------------------------------------
// fp32 -> bf16 hi/lo split (flat arrays)
// ---------------------------------------------------------------------------
__global__ __launch_bounds__(256) void split_hl(
    const float* __restrict__ s, __nv_bfloat16* __restrict__ h,
    __nv_bfloat16* __restrict__ l, int n)
{
    int i = (blockIdx.x * 256 + threadIdx.x) * 4;
    if (i >= n) return;
    float4 v = *(const float4*)(s + i);
    uint32_t h01 = pack_hi(v.x, v.y), h23 = pack_hi(v.z, v.w);
    uint32_t l01 = pack_res(v.x, v.y, h01), l23 = pack_res(v.z, v.w, h23);
    *(uint32_t*)(h + i) = h01; *(uint32_t*)(h + i + 2) = h23;
    *(uint32_t*)(l + i) = l01; *(uint32_t*)(l + i + 2) = l23;
}

// ---------------------------------------------------------------------------
// qkv fp32 [M, 3C] -> q/k/v hi/lo bf16 [B,H,T,64]; skips dead rows
// ---------------------------------------------------------------------------
__global__ __launch_bounds__(256) void qkv_split(
    const float* __restrict__ qkv, const int* __restrict__ lenp,
    __nv_bfloat16* __restrict__ qh, __nv_bfloat16* __restrict__ ql,
    __nv_bfloat16* __restrict__ kh, __nv_bfloat16* __restrict__ kl,
    __nv_bfloat16* __restrict__ vh, __nv_bfloat16* __restrict__ vl)
{
    size_t i = ((size_t)blockIdx.x * 256 + threadIdx.x) * 4;
    int row = (int)(i / C3_), col = (int)(i % C3_);
    int b = row >> 11, t = row & 2047;
    int len = lenp[b];
    if (t >= ((len + 127) & ~127)) return;     // dead rows: never consumed
    float4 v = *(const float4*)(qkv + i);
    int which = col >> 10;
    int hc = col & 1023;
    int head = hc >> 6, d = hc & 63;
    __nv_bfloat16* Oh = (which == 0) ? qh : (which == 1) ? kh : vh;
    __nv_bfloat16* Ol = (which == 0) ? ql : (which == 1) ? kl : vl;
    size_t idx = ((((size_t)b * H_) + head) * T_ + t) * HD_ + d;
    uint2 hh, ll;
    hh.x = pack_hi(v.x, v.y); hh.y = pack_hi(v.z, v.w);
    ll.x = pack_res(v.x, v.y, hh.x); ll.y = pack_res(v.z, v.w, hh.y);
    *(uint2*)(Oh + idx) = hh;
    *(uint2*)(Ol + idx) = ll;
}

// ---------------------------------------------------------------------------
// Tensor-core flash attention (R12): pre-split bf16 q/k/v, LPT order,
// early-exit masked q-tiles, uniform depth-2 cp.async pipeline.
// ---------------------------------------------------------------------------
#define PITCH 72
#define OPB   (64 * PITCH * 2)
#define BUF_B (4 * OPB)
#define ATTN_SMEM (2 * BUF_B)

__global__ __launch_bounds__(256, 1) void flash_attn_tc(
    const __nv_bfloat16* __restrict__ qh, const __nv_bfloat16* __restrict__ ql,
    const __nv_bfloat16* __restrict__ kh, const __nv_bfloat16* __restrict__ kl,
    const __nv_bfloat16* __restrict__ vh, const __nv_bfloat16* __restrict__ vl,
    const int* __restrict__ lenp,
    __nv_bfloat16* __restrict__ yh, __nv_bfloat16* __restrict__ yl)
{
    extern __shared__ char smdyn[];

    const int b = blockIdx.z, h = blockIdx.y;
    const int qt = (int)(gridDim.x - 1 - blockIdx.x);   // LPT: heavy first
    const int q0 = qt * 128;
    const int tid = threadIdx.x;
    const int warp = tid >> 5, lane = tid & 31;
    const int len = lenp[b];
    const size_t bh = ((size_t)b * H_ + h) * T_ * HD_;

    if (q0 >= len) {
        const size_t ybase = ((size_t)b * T_ + q0) * C_ + h * HD_;
        const uint2 z = make_uint2(0u, 0u);
        #pragma unroll
        for (int t = 0; t < 8; t++) {
            int e = tid + t * 256;
            int r = e >> 4, c4 = (e & 15) * 4;
            *(uint2*)(yh + ybase + (size_t)r * C_ + c4) = z;
            *(uint2*)(yl + ybase + (size_t)r * C_ + c4) = z;
        }
        return;
    }

    const int kt_len = (len + 63) >> 6;
    const int kt_max = min(2 * qt + 1, kt_len - 1);

    auto issue_kv = [&](int kt, int buf) {
        char* st = smdyn + buf * BUF_B;
        const size_t kbase = bh + (size_t)(kt * 64) * HD_;
        #pragma unroll
        for (int t = 0; t < 8; t++) {
            int e = tid + t * 256;
            int op = e >> 9;
            int idx = e & 511;
            int r = idx >> 3, c16 = idx & 7;
            const __nv_bfloat16* src =
                (op == 0) ? kh : (op == 1) ? kl : (op == 2) ? vh : vl;
            CP_ASYNC16(smem_u32(st + op * OPB + (r * PITCH + c16 * 8) * 2),
                       src + kbase + (size_t)r * HD_ + c16 * 8);
        }
        CP_COMMIT();
    };

    {
        char* st = smdyn;
        const size_t qbase = bh + (size_t)q0 * HD_;
        #pragma unroll
        for (int t = 0; t < 8; t++) {
            int e = tid + t * 256;
            int part = e >> 10;
            int idx = e & 1023;
            int r = idx >> 3, c16 = idx & 7;
            const __nv_bfloat16* src = part ? ql : qh;
            CP_ASYNC16(smem_u32(st + part * 2 * OPB + (r * PITCH + c16 * 8) * 2),
                       src + qbase + (size_t)r * HD_ + c16 * 8);
        }
        CP_COMMIT();
    }
    issue_kv(0, 1);
    CP_WAIT1();
    __syncthreads();

    uint32_t qfh[4][4], qfl[4][4];
    {
        __nv_bfloat16* Qh = (__nv_bfloat16*)smdyn;
        __nv_bfloat16* Ql = (__nv_bfloat16*)(smdyn + 2 * OPB);
        int row = warp * 16 + (lane & 7) + 8 * ((lane >> 3) & 1);
        #pragma unroll
        for (int ks = 0; ks < 4; ks++) {
            int col = ks * 16 + 8 * (lane >> 4);
            LDSM_X4(qfh[ks], smem_u32(Qh + row * PITCH + col));
            LDSM_X4(qfl[ks], smem_u32(Ql + row * PITCH + col));
        }
    }
    __syncthreads();
    issue_kv(min(1, kt_max), 0);

    float m_[2] = {-1e30f, -1e30f}, l_[2] = {0.f, 0.f};
    float O[8][4] = {};

    const int wrow_max = q0 + warp * 16 + 15;
    const int r0 = lane >> 2, cb = (lane & 3) * 2;
    const int row0 = q0 + warp * 16 + r0, row1 = row0 + 8;

    for (int kt = 0; kt <= kt_max; kt++) {
        const int k0 = kt * 64;
        CP_WAIT1();
        __syncthreads();

        char* st = smdyn + ((kt + 1) & 1) * BUF_B;
        __nv_bfloat16* Kh = (__nv_bfloat16*)st;
        __nv_bfloat16* Kl = (__nv_bfloat16*)(st + OPB);
        __nv_bfloat16* Vh = (__nv_bfloat16*)(st + 2 * OPB);
        __nv_bfloat16* Vl = (__nv_bfloat16*)(st + 3 * OPB);

        if (k0 <= wrow_max) {
            float S[8][4] = {};
            {
                int krow = (lane & 7);
                int kcol8 = 8 * ((lane >> 3) & 1);
                #pragma unroll
                for (int nb = 0; nb < 8; nb++) {
                    #pragma unroll
                    for (int ks = 0; ks < 4; ks++) {
                        uint32_t bh0, bh1, bl0, bl1;
                        LDSM_X2(bh0, bh1, smem_u32(Kh + (nb * 8 + krow) * PITCH + ks * 16 + kcol8));
                        LDSM_X2(bl0, bl1, smem_u32(Kl + (nb * 8 + krow) * PITCH + ks * 16 + kcol8));
                        MMA16816(S[nb], qfh[ks], bh0, bh1);
                        MMA16816(S[nb], qfl[ks], bh0, bh1);
                        MMA16816(S[nb], qfh[ks], bl0, bl1);
                    }
                }
            }

            float ml0 = -1e30f, ml1 = -1e30f;
            #pragma unroll
            for (int nb = 0; nb < 8; nb++) {
                int c0 = k0 + nb * 8 + cb;
                S[nb][0] = (c0     <= row0 && c0     < len) ? S[nb][0] * 0.125f : -1e30f;
                S[nb][1] = (c0 + 1 <= row0 && c0 + 1 < len) ? S[nb][1] * 0.125f : -1e30f;
                S[nb][2] = (c0     <= row1 && c0     < len) ? S[nb][2] * 0.125f : -1e30f;
                S[nb][3] = (c0 + 1 <= row1 && c0 + 1 < len) ? S[nb][3] * 0.125f : -1e30f;
                ml0 = fmaxf(ml0, fmaxf(S[nb][0], S[nb][1]));
                ml1 = fmaxf(ml1, fmaxf(S[nb][2], S[nb][3]));
            }
            ml0 = fmaxf(ml0, __shfl_xor_sync(0xffffffffu, ml0, 1));
            ml0 = fmaxf(ml0, __shfl_xor_sync(0xffffffffu, ml0, 2));
            ml1 = fmaxf(ml1, __shfl_xor_sync(0xffffffffu, ml1, 1));
            ml1 = fmaxf(ml1, __shfl_xor_sync(0xffffffffu, ml1, 2));
            float mn0 = fmaxf(m_[0], ml0), mn1 = fmaxf(m_[1], ml1);
            float corr0 = __expf(m_[0] - mn0), corr1 = __expf(m_[1] - mn1);
            float ls0 = 0.f, ls1 = 0.f;
            #pragma unroll
            for (int nb = 0; nb < 8; nb++) {
                S[nb][0] = __expf(S[nb][0] - mn0); ls0 += S[nb][0];
                S[nb][1] = __expf(S[nb][1] - mn0); ls0 += S[nb][1];
                S[nb][2] = __expf(S[nb][2] - mn1); ls1 += S[nb][2];
                S[nb][3] = __expf(S[nb][3] - mn1); ls1 += S[nb][3];
            }
            ls0 += __shfl_xor_sync(0xffffffffu, ls0, 1);
            ls0 += __shfl_xor_sync(0xffffffffu, ls0, 2);
            ls1 += __shfl_xor_sync(0xffffffffu, ls1, 1);
            ls1 += __shfl_xor_sync(0xffffffffu, ls1, 2);
            l_[0] = l_[0] * corr0 + ls0;
            l_[1] = l_[1] * corr1 + ls1;
            m_[0] = mn0; m_[1] = mn1;
            #pragma unroll
            for (int nb = 0; nb < 8; nb++) {
                O[nb][0] *= corr0; O[nb][1] *= corr0;
                O[nb][2] *= corr1; O[nb][3] *= corr1;
            }

            {
                int vrow8 = (lane & 7) + 8 * ((lane >> 3) & 1);
                #pragma unroll
                for (int ks = 0; ks < 4; ks++) {
                    uint32_t ph[4], pl[4];
                    ph[0] = pack_hi(S[2 * ks][0], S[2 * ks][1]);
                    ph[1] = pack_hi(S[2 * ks][2], S[2 * ks][3]);
                    ph[2] = pack_hi(S[2 * ks + 1][0], S[2 * ks + 1][1]);
                    ph[3] = pack_hi(S[2 * ks + 1][2], S[2 * ks + 1][3]);
                    pl[0] = pack_res(S[2 * ks][0], S[2 * ks][1], ph[0]);
                    pl[1] = pack_res(S[2 * ks][2], S[2 * ks][3], ph[1]);
                    pl[2] = pack_res(S[2 * ks + 1][0], S[2 * ks + 1][1], ph[2]);
                    pl[3] = pack_res(S[2 * ks + 1][2], S[2 * ks + 1][3], ph[3]);
                    #pragma unroll
                    for (int nb = 0; nb < 8; nb++) {
                        uint32_t vh0, vh1, vl0, vl1;
                        LDSM_X2T(vh0, vh1, smem_u32(Vh + (ks * 16 + vrow8) * PITCH + nb * 8));
                        LDSM_X2T(vl0, vl1, smem_u32(Vl + (ks * 16 + vrow8) * PITCH + nb * 8));
                        MMA16816(O[nb], ph, vh0, vh1);
                        MMA16816(O[nb], pl, vh0, vh1);
                        MMA16816(O[nb], ph, vl0, vl1);
                    }
                }
            }
        }

        __syncthreads();
        issue_kv(min(kt + 2, kt_max), (kt + 1) & 1);
    }

    float inv0 = (row0 < len && l_[0] > 0.f) ? (1.f / l_[0]) : 0.f;
    float inv1 = (row1 < len && l_[1] > 0.f) ? (1.f / l_[1]) : 0.f;
    size_t rb0 = ((size_t)b * T_ + row0) * C_;
    size_t rb1 = ((size_t)b * T_ + row1) * C_;
    #pragma unroll
    for (int nb = 0; nb < 8; nb++) {
        int hcol = h * HD_ + nb * 8 + cb;
        uint32_t h0 = pack_hi(O[nb][0] * inv0, O[nb][1] * inv0);
        uint32_t l0 = pack_res(O[nb][0] * inv0, O[nb][1] * inv0, h0);
        uint32_t h1 = pack_hi(O[nb][2] * inv1, O[nb][3] * inv1);
        uint32_t l1 = pack_res(O[nb][2] * inv1, O[nb][3] * inv1, h1);
        *(uint32_t*)(yh + rb0 + hcol) = h0;
        *(uint32_t*)(yl + rb0 + hcol) = l0;
        *(uint32_t*)(yh + rb1 + hcol) = h1;
        *(uint32_t*)(yl + rb1 + hcol) = l1;
    }
}

// ---------------------------------------------------------------------------
extern "C" void kernel_launch(void* const* d_in, const int* in_sizes, int n_in,
                              void* d_out, int out_size)
{
    const float* x    = (const float*)d_in[0];
    const int*   am   = (const int*)  d_in[1];
    const float* Wqkv = (const float*)d_in[2];
    const float* bqkv = (const float*)d_in[3];
    const float* Wo   = (const float*)d_in[4];
    const float* bo   = (const float*)d_in[5];
    float* out = (float*)d_out;

    float* qkv;
    __nv_bfloat16 *xh, *xl, *wqh, *wql, *woh, *wol, *yh, *yl;
    __nv_bfloat16 *qh, *ql, *kh, *kl, *vh, *vl;
    int* lenp;
    cudaGetSymbolAddress((void**)&qkv, g_qkv);
    cudaGetSymbolAddress((void**)&xh, g_xh);   cudaGetSymbolAddress((void**)&xl, g_xl);
    cudaGetSymbolAddress((void**)&wqh, g_wqh); cudaGetSymbolAddress((void**)&wql, g_wql);
    cudaGetSymbolAddress((void**)&woh, g_woh); cudaGetSymbolAddress((void**)&wol, g_wol);
    cudaGetSymbolAddress((void**)&yh, g_yh);   cudaGetSymbolAddress((void**)&yl, g_yl);
    cudaGetSymbolAddress((void**)&qh, g_qh);   cudaGetSymbolAddress((void**)&ql, g_ql);
    cudaGetSymbolAddress((void**)&kh, g_kh);   cudaGetSymbolAddress((void**)&kl, g_kl);
    cudaGetSymbolAddress((void**)&vh, g_vh);   cudaGetSymbolAddress((void**)&vl, g_vl);
    cudaGetSymbolAddress((void**)&lenp, g_len);

    cudaFuncSetAttribute(gemm_bf16<1>, cudaFuncAttributeMaxDynamicSharedMemorySize, GEMM_SMEM);
    cudaFuncSetAttribute(gemm_bf16<2>, cudaFuncAttributeMaxDynamicSharedMemorySize, GEMM_SMEM);
    cudaFuncSetAttribute(flash_attn_tc, cudaFuncAttributeMaxDynamicSharedMemorySize, ATTN_SMEM);

    int nx = M_ * C_, nwq = C3_ * C_, nwo = C_ * C_;
    compute_len<<<B_, 256>>>(am, lenp);
    split_hl<<<nx  / 1024, 256>>>(x,    xh,  xl,  nx);
    split_hl<<<nwq / 1024, 256>>>(Wqkv, wqh, wql, nwq);
    split_hl<<<nwo / 1024, 256>>>(Wo,   woh, wol, nwo);

    gemm_bf16<1><<<dim3(C3_ / 128, M_ / 128), 256, GEMM_SMEM>>>(
        xh, xl, wqh, wql, bqkv, qkv, lenp, M_, C3_, C_);
    qkv_split<<<(int)((size_t)M_ * C3_ / 1024), 256>>>(
        qkv, lenp, qh, ql, kh, kl, vh, vl);
    flash_attn_tc<<<dim3(T_ / 128, H_, B_), 256, ATTN_SMEM>>>(
        qh, ql, kh, kl, vh, vl, lenp, yh, yl);
    gemm_bf16<2><<<dim3(C_ / 128, M_ / 128), 256, GEMM_SMEM>>>(
        yh, yl, woh, wol, bo, out, lenp, M_, C_, C_);
}

// round 14
// speedup vs baseline: 2.3165x; 1.3771x over previous
#include <cuda_runtime.h>
#include <cuda_fp16.h>
#include <cstdint>

// Problem constants
#define B_   4
#define T_   2048
#define C_   1024
#define H_   16
#define HD_  64
#define M_   (B_ * T_)          // 8192
#define C3_  (3 * C_)           // 3072

// ---------------------------------------------------------------------------
// Scratch (device globals)
// ---------------------------------------------------------------------------
__device__ float g_qkv[(size_t)M_ * C3_];
__device__ __half g_xh [(size_t)M_  * C_], g_xl [(size_t)M_  * C_];
__device__ __half g_wqh[(size_t)C3_ * C_];
__device__ __half g_woh[(size_t)C_  * C_];
#define QKV_N ((size_t)B_ * H_ * T_ * HD_)
__device__ __half g_qh[QKV_N], g_ql[QKV_N];
__device__ __half g_kh[QKV_N], g_kl[QKV_N];
__device__ __half g_vh[QKV_N], g_vl[QKV_N];
__device__ __half g_yh [(size_t)M_ * C_], g_yl [(size_t)M_ * C_];
__device__ int g_len[B_];

// ---------------------------------------------------------------------------
// Helpers
// ---------------------------------------------------------------------------
__device__ __forceinline__ uint32_t smem_u32(const void* p) {
    uint32_t a;
    asm("{ .reg .u64 t; cvta.to.shared.u64 t, %1; cvt.u32.u64 %0, t; }"
        : "=r"(a) : "l"(p));
    return a;
}

#define MMA16816(C, A, b0, b1)                                                \
    asm volatile(                                                             \
        "mma.sync.aligned.m16n8k16.row.col.f32.f16.f16.f32 "                  \
        "{%0,%1,%2,%3},{%4,%5,%6,%7},{%8,%9},{%0,%1,%2,%3};"                  \
        : "+f"((C)[0]), "+f"((C)[1]), "+f"((C)[2]), "+f"((C)[3])              \
        : "r"((A)[0]), "r"((A)[1]), "r"((A)[2]), "r"((A)[3]),                 \
          "r"(b0), "r"(b1))

#define LDSM_X4(R, addr)                                                      \
    asm volatile("ldmatrix.sync.aligned.m8n8.x4.shared.b16 {%0,%1,%2,%3}, [%4];" \
        : "=r"((R)[0]), "=r"((R)[1]), "=r"((R)[2]), "=r"((R)[3]) : "r"(addr))

#define LDSM_X2(r0, r1, addr)                                                 \
    asm volatile("ldmatrix.sync.aligned.m8n8.x2.shared.b16 {%0,%1}, [%2];"    \
        : "=r"(r0), "=r"(r1) : "r"(addr))

#define LDSM_X2T(r0, r1, addr)                                                \
    asm volatile("ldmatrix.sync.aligned.m8n8.x2.trans.shared.b16 {%0,%1}, [%2];" \
        : "=r"(r0), "=r"(r1) : "r"(addr))

#define CP_ASYNC16(dst, src)                                                  \
    asm volatile("cp.async.cg.shared.global [%0], [%1], 16;"                  \
                 :: "r"(dst), "l"(src) : "memory")
#define CP_COMMIT() asm volatile("cp.async.commit_group;" ::: "memory")
#define CP_WAIT1()  asm volatile("cp.async.wait_group 1;" ::: "memory")

__device__ __forceinline__ uint32_t pack_hi(float a, float b) {
    __half2 v = __floats2half2_rn(a, b);
    return *reinterpret_cast<uint32_t*>(&v);
}
__device__ __forceinline__ uint32_t pack_res(float a, float b, uint32_t hp) {
    __half2 h = *reinterpret_cast<__half2*>(&hp);
    __half2 v = __floats2half2_rn(a - __half2float(h.x),
                                  b - __half2float(h.y));
    return *reinterpret_cast<uint32_t*>(&v);
}

// ---------------------------------------------------------------------------
// HMMA GEMM (2-term fp16, exact activation): Cout = (Ah+Al) @ Wh^T + bias
//   = A @ Wh^T exactly; only W is fp16-quantized.
// 128x128 tile, k-chunk 16, 3-stage cp.async (Ah|Al|Wh), 2 CTAs/SM.
// MODE 1 (QKV): skip M-tiles fully beyond round_up(len,128).
// MODE 2 (proj): for such tiles write bias rows and exit.
// ---------------------------------------------------------------------------
#define GTILE_B    6144                 // 128 rows x 24 halves x 2B
#define GSTAGE_B   (3 * GTILE_B)        // Ah | Al | Wh = 18432
#define GEMM_SMEM  (3 * GSTAGE_B)       // 55296

template <int MODE>
__global__ __launch_bounds__(256, 2) void gemm_fp16(
    const __half* __restrict__ Ah, const __half* __restrict__ Al,
    const __half* __restrict__ Wh,
    const float* __restrict__ bias, float* __restrict__ Cout,
    const int* __restrict__ lenp,
    int M, int N, int K)
{
    extern __shared__ char sm[];
    const int tid = threadIdx.x;
    const int bm = blockIdx.y * 128;
    const int bn = blockIdx.x * 128;

    if (MODE != 0) {
        const int len = lenp[bm >> 11];
        const int lim = (len + 127) & ~127;
        if ((bm & 2047) >= lim) {
            if (MODE == 2) {
                const int c4 = (tid & 31) * 4;
                const int rb = tid >> 5;
                float4 bv = *(const float4*)(bias + bn + c4);
                #pragma unroll
                for (int rr = 0; rr < 16; rr++) {
                    int row = bm + rb * 16 + rr;
                    *(float4*)(Cout + (size_t)row * N + bn + c4) = bv;
                }
            }
            return;
        }
    }

    const int warp = tid >> 5, lane = tid & 31;
    const int moff = (warp >> 1) * 32;
    const int noff = (warp & 1) * 64;

    float acc[2][8][4];
    #pragma unroll
    for (int a = 0; a < 2; a++)
        #pragma unroll
        for (int b = 0; b < 8; b++)
            #pragma unroll
            for (int c = 0; c < 4; c++) acc[a][b][c] = 0.f;

    const int r_ld = tid >> 1, half8 = (tid & 1) * 8;
    auto issue = [&](int c, int s) {
        const int k0 = c << 4;
        char* st = sm + s * GSTAGE_B;
        uint32_t d = smem_u32(st + (r_ld * 24 + half8) * 2);
        CP_ASYNC16(d,               Ah + (size_t)(bm + r_ld) * K + k0 + half8);
        CP_ASYNC16(d + GTILE_B,     Al + (size_t)(bm + r_ld) * K + k0 + half8);
        CP_ASYNC16(d + 2 * GTILE_B, Wh + (size_t)(bn + r_ld) * K + k0 + half8);
        CP_COMMIT();
    };

    const int nk = K >> 4;
    issue(0, 0);
    issue(1, 1);

    const int arow = moff + (lane & 7) + 8 * ((lane >> 3) & 1);
    const int acol = 8 * (lane >> 4);
    const int wrow_l = (lane & 7);
    const int wcol = 8 * ((lane >> 3) & 1);

    int s = 0;
    for (int c = 0; c < nk; c++) {
        CP_WAIT1();
        __syncthreads();
        if (c + 2 < nk) issue(c + 2, (s + 2 >= 3) ? s - 1 : s + 2);
        else CP_COMMIT();

        char* st = sm + s * GSTAGE_B;
        uint32_t ah[2][4], al[2][4];
        #pragma unroll
        for (int mb = 0; mb < 2; mb++) {
            LDSM_X4(ah[mb], smem_u32(st + ((arow + mb * 16) * 24 + acol) * 2));
            LDSM_X4(al[mb], smem_u32(st + GTILE_B + ((arow + mb * 16) * 24 + acol) * 2));
        }
        #pragma unroll
        for (int nb = 0; nb < 8; nb++) {
            int wr = noff + nb * 8 + wrow_l;
            uint32_t bh0, bh1;
            LDSM_X2(bh0, bh1, smem_u32(st + 2 * GTILE_B + (wr * 24 + wcol) * 2));
            #pragma unroll
            for (int mb = 0; mb < 2; mb++) {
                MMA16816(acc[mb][nb], ah[mb], bh0, bh1);
                MMA16816(acc[mb][nb], al[mb], bh0, bh1);
            }
        }
        s = (s + 1 >= 3) ? 0 : s + 1;
    }

    const int r0 = lane >> 2, c0 = (lane & 3) * 2;
    #pragma unroll
    for (int mb = 0; mb < 2; mb++)
        #pragma unroll
        for (int nb = 0; nb < 8; nb++) {
            int row = bm + moff + mb * 16 + r0;
            int col = bn + noff + nb * 8 + c0;
            float2 v0 = make_float2(acc[mb][nb][0] + bias[col],
                                    acc[mb][nb][1] + bias[col + 1]);
            *(float2*)(Cout + (size_t)row * N + col) = v0;
            float2 v1 = make_float2(acc[mb][nb][2] + bias[col],
                                    acc[mb][nb][3] + bias[col + 1]);
            *(float2*)(Cout + (size_t)(row + 8) * N + col) = v1;
        }
}

// ---------------------------------------------------------------------------
// per-batch valid length
// ---------------------------------------------------------------------------
__global__ void compute_len(const int* __restrict__ am, int* __restrict__ out) {
    __shared__ int red[8];
    int b = blockIdx.x, acc = 0;
    for (int i = threadIdx.x; i < T_; i += 256) acc += am[b * T_ + i];
    #pragma unroll
    for (int o = 16; o; o >>= 1) acc += __shfl_xor_sync(0xffffffffu, acc, o);
    if ((threadIdx.x & 31) == 0) red[threadIdx.x >> 5] = acc;
    __syncthreads();
    if (threadIdx.x == 0) {
        int v = 0;
        #pragma unroll
        for (int i = 0; i < 8; i++) v += red[i];
        out[b] = v;
    }
}

// ---------------------------------------------------------------------------
// fp32 -> fp16 hi/lo split (activations)
// ---------------------------------------------------------------------------
__global__ __launch_bounds__(256) void split_hl(
    const float* __restrict__ s, __half* __restrict__ h,
    __half* __restrict__ l, int n)
{
    int i = (blockIdx.x * 256 + threadIdx.x) * 4;
    if (i >= n) return;
    float4 v = *(const float4*)(s + i);
    uint32_t h01 = pack_hi(v.x, v.y), h23 = pack_hi(v.z, v.w);
    uint32_t l01 = pack_res(v.x, v.y, h01), l23 = pack_res(v.z, v.w, h23);
    *(uint32_t*)(h + i) = h01; *(uint32_t*)(h + i + 2) = h23;
    *(uint32_t*)(l + i) = l01; *(uint32_t*)(l + i + 2) = l23;
}

// fp32 -> fp16 (weights: hi only)
__global__ __launch_bounds__(256) void conv_h(
    const float* __restrict__ s, __half* __restrict__ h, int n)
{
    int i = (blockIdx.x * 256 + threadIdx.x) * 4;
    if (i >= n) return;
    float4 v = *(const float4*)(s + i);
    *(uint32_t*)(h + i)     = pack_hi(v.x, v.y);
    *(uint32_t*)(h + i + 2) = pack_hi(v.z, v.w);
}

// ---------------------------------------------------------------------------
// qkv fp32 [M, 3C] -> q/k/v hi/lo fp16 [B,H,T,64]; skips dead rows
// ---------------------------------------------------------------------------
__global__ __launch_bounds__(256) void qkv_split(
    const float* __restrict__ qkv, const int* __restrict__ lenp,
    __half* __restrict__ qh, __half* __restrict__ ql,
    __half* __restrict__ kh, __half* __restrict__ kl,
    __half* __restrict__ vh, __half* __restrict__ vl)
{
    size_t i = ((size_t)blockIdx.x * 256 + threadIdx.x) * 4;
    int row = (int)(i / C3_), col = (int)(i % C3_);
    int b = row >> 11, t = row & 2047;
    int len = lenp[b];
    if (t >= ((len + 127) & ~127)) return;
    float4 v = *(const float4*)(qkv + i);
    int which = col >> 10;
    int hc = col & 1023;
    int head = hc >> 6, d = hc & 63;
    __half* Oh = (which == 0) ? qh : (which == 1) ? kh : vh;
    __half* Ol = (which == 0) ? ql : (which == 1) ? kl : vl;
    size_t idx = ((((size_t)b * H_) + head) * T_ + t) * HD_ + d;
    uint2 hh, ll;
    hh.x = pack_hi(v.x, v.y); hh.y = pack_hi(v.z, v.w);
    ll.x = pack_res(v.x, v.y, hh.x); ll.y = pack_res(v.z, v.w, hh.y);
    *(uint2*)(Oh + idx) = hh;
    *(uint2*)(Ol + idx) = ll;
}

// ---------------------------------------------------------------------------
// Tensor-core flash attention (3-term fp16 split, fp32 accum).
// Pre-split q/k/v [B,H,T,64], LPT order, masked-tile early exit,
// uniform depth-2 cp.async pipeline.
// ---------------------------------------------------------------------------
#define PITCH 72
#define OPB   (64 * PITCH * 2)
#define BUF_B (4 * OPB)
#define ATTN_SMEM (2 * BUF_B)

__global__ __launch_bounds__(256, 1) void flash_attn_tc(
    const __half* __restrict__ qh, const __half* __restrict__ ql,
    const __half* __restrict__ kh, const __half* __restrict__ kl,
    const __half* __restrict__ vh, const __half* __restrict__ vl,
    const int* __restrict__ lenp,
    __half* __restrict__ yh, __half* __restrict__ yl)
{
    extern __shared__ char smdyn[];

    const int b = blockIdx.z, h = blockIdx.y;
    const int qt = (int)(gridDim.x - 1 - blockIdx.x);   // LPT: heavy first
    const int q0 = qt * 128;
    const int tid = threadIdx.x;
    const int warp = tid >> 5, lane = tid & 31;
    const int len = lenp[b];
    const size_t bh = ((size_t)b * H_ + h) * T_ * HD_;

    if (q0 >= len) {
        const size_t ybase = ((size_t)b * T_ + q0) * C_ + h * HD_;
        const uint2 z = make_uint2(0u, 0u);
        #pragma unroll
        for (int t = 0; t < 8; t++) {
            int e = tid + t * 256;
            int r = e >> 4, c4 = (e & 15) * 4;
            *(uint2*)(yh + ybase + (size_t)r * C_ + c4) = z;
            *(uint2*)(yl + ybase + (size_t)r * C_ + c4) = z;
        }
        return;
    }

    const int kt_len = (len + 63) >> 6;
    const int kt_max = min(2 * qt + 1, kt_len - 1);

    auto issue_kv = [&](int kt, int buf) {
        char* st = smdyn + buf * BUF_B;
        const size_t kbase = bh + (size_t)(kt * 64) * HD_;
        #pragma unroll
        for (int t = 0; t < 8; t++) {
            int e = tid + t * 256;
            int op = e >> 9;
            int idx = e & 511;
            int r = idx >> 3, c16 = idx & 7;
            const __half* src =
                (op == 0) ? kh : (op == 1) ? kl : (op == 2) ? vh : vl;
            CP_ASYNC16(smem_u32(st + op * OPB + (r * PITCH + c16 * 8) * 2),
                       src + kbase + (size_t)r * HD_ + c16 * 8);
        }
        CP_COMMIT();
    };

    {
        char* st = smdyn;
        const size_t qbase = bh + (size_t)q0 * HD_;
        #pragma unroll
        for (int t = 0; t < 8; t++) {
            int e = tid + t * 256;
            int part = e >> 10;
            int idx = e & 1023;
            int r = idx >> 3, c16 = idx & 7;
            const __half* src = part ? ql : qh;
            CP_ASYNC16(smem_u32(st + part * 2 * OPB + (r * PITCH + c16 * 8) * 2),
                       src + qbase + (size_t)r * HD_ + c16 * 8);
        }
        CP_COMMIT();
    }
    issue_kv(0, 1);
    CP_WAIT1();
    __syncthreads();

    uint32_t qfh[4][4], qfl[4][4];
    {
        __half* Qh = (__half*)smdyn;
        __half* Ql = (__half*)(smdyn + 2 * OPB);
        int row = warp * 16 + (lane & 7) + 8 * ((lane >> 3) & 1);
        #pragma unroll
        for (int ks = 0; ks < 4; ks++) {
            int col = ks * 16 + 8 * (lane >> 4);
            LDSM_X4(qfh[ks], smem_u32(Qh + row * PITCH + col));
            LDSM_X4(qfl[ks], smem_u32(Ql + row * PITCH + col));
        }
    }
    __syncthreads();
    issue_kv(min(1, kt_max), 0);

    float m_[2] = {-1e30f, -1e30f}, l_[2] = {0.f, 0.f};
    float O[8][4] = {};

    const int wrow_max = q0 + warp * 16 + 15;
    const int r0 = lane >> 2, cb = (lane & 3) * 2;
    const int row0 = q0 + warp * 16 + r0, row1 = row0 + 8;

    for (int kt = 0; kt <= kt_max; kt++) {
        const int k0 = kt * 64;
        CP_WAIT1();
        __syncthreads();

        char* st = smdyn + ((kt + 1) & 1) * BUF_B;
        __half* Kh = (__half*)st;
        __half* Kl = (__half*)(st + OPB);
        __half* Vh = (__half*)(st + 2 * OPB);
        __half* Vl = (__half*)(st + 3 * OPB);

        if (k0 <= wrow_max) {
            float S[8][4] = {};
            {
                int krow = (lane & 7);
                int kcol8 = 8 * ((lane >> 3) & 1);
                #pragma unroll
                for (int nb = 0; nb < 8; nb++) {
                    #pragma unroll
                    for (int ks = 0; ks < 4; ks++) {
                        uint32_t bh0, bh1, bl0, bl1;
                        LDSM_X2(bh0, bh1, smem_u32(Kh + (nb * 8 + krow) * PITCH + ks * 16 + kcol8));
                        LDSM_X2(bl0, bl1, smem_u32(Kl + (nb * 8 + krow) * PITCH + ks * 16 + kcol8));
                        MMA16816(S[nb], qfh[ks], bh0, bh1);
                        MMA16816(S[nb], qfl[ks], bh0, bh1);
                        MMA16816(S[nb], qfh[ks], bl0, bl1);
                    }
                }
            }

            float ml0 = -1e30f, ml1 = -1e30f;
            #pragma unroll
            for (int nb = 0; nb < 8; nb++) {
                int c0 = k0 + nb * 8 + cb;
                S[nb][0] = (c0     <= row0 && c0     < len) ? S[nb][0] * 0.125f : -1e30f;
                S[nb][1] = (c0 + 1 <= row0 && c0 + 1 < len) ? S[nb][1] * 0.125f : -1e30f;
                S[nb][2] = (c0     <= row1 && c0     < len) ? S[nb][2] * 0.125f : -1e30f;
                S[nb][3] = (c0 + 1 <= row1 && c0 + 1 < len) ? S[nb][3] * 0.125f : -1e30f;
                ml0 = fmaxf(ml0, fmaxf(S[nb][0], S[nb][1]));
                ml1 = fmaxf(ml1, fmaxf(S[nb][2], S[nb][3]));
            }
            ml0 = fmaxf(ml0, __shfl_xor_sync(0xffffffffu, ml0, 1));
            ml0 = fmaxf(ml0, __shfl_xor_sync(0xffffffffu, ml0, 2));
            ml1 = fmaxf(ml1, __shfl_xor_sync(0xffffffffu, ml1, 1));
            ml1 = fmaxf(ml1, __shfl_xor_sync(0xffffffffu, ml1, 2));
            float mn0 = fmaxf(m_[0], ml0), mn1 = fmaxf(m_[1], ml1);
            float corr0 = __expf(m_[0] - mn0), corr1 = __expf(m_[1] - mn1);
            float ls0 = 0.f, ls1 = 0.f;
            #pragma unroll
            for (int nb = 0; nb < 8; nb++) {
                S[nb][0] = __expf(S[nb][0] - mn0); ls0 += S[nb][0];
                S[nb][1] = __expf(S[nb][1] - mn0); ls0 += S[nb][1];
                S[nb][2] = __expf(S[nb][2] - mn1); ls1 += S[nb][2];
                S[nb][3] = __expf(S[nb][3] - mn1); ls1 += S[nb][3];
            }
            ls0 += __shfl_xor_sync(0xffffffffu, ls0, 1);
            ls0 += __shfl_xor_sync(0xffffffffu, ls0, 2);
            ls1 += __shfl_xor_sync(0xffffffffu, ls1, 1);
            ls1 += __shfl_xor_sync(0xffffffffu, ls1, 2);
            l_[0] = l_[0] * corr0 + ls0;
            l_[1] = l_[1] * corr1 + ls1;
            m_[0] = mn0; m_[1] = mn1;
            #pragma unroll
            for (int nb = 0; nb < 8; nb++) {
                O[nb][0] *= corr0; O[nb][1] *= corr0;
                O[nb][2] *= corr1; O[nb][3] *= corr1;
            }

            {
                int vrow8 = (lane & 7) + 8 * ((lane >> 3) & 1);
                #pragma unroll
                for (int ks = 0; ks < 4; ks++) {
                    uint32_t ph[4], pl[4];
                    ph[0] = pack_hi(S[2 * ks][0], S[2 * ks][1]);
                    ph[1] = pack_hi(S[2 * ks][2], S[2 * ks][3]);
                    ph[2] = pack_hi(S[2 * ks + 1][0], S[2 * ks + 1][1]);
                    ph[3] = pack_hi(S[2 * ks + 1][2], S[2 * ks + 1][3]);
                    pl[0] = pack_res(S[2 * ks][0], S[2 * ks][1], ph[0]);
                    pl[1] = pack_res(S[2 * ks][2], S[2 * ks][3], ph[1]);
                    pl[2] = pack_res(S[2 * ks + 1][0], S[2 * ks + 1][1], ph[2]);
                    pl[3] = pack_res(S[2 * ks + 1][2], S[2 * ks + 1][3], ph[3]);
                    #pragma unroll
                    for (int nb = 0; nb < 8; nb++) {
                        uint32_t vh0, vh1, vl0, vl1;
                        LDSM_X2T(vh0, vh1, smem_u32(Vh + (ks * 16 + vrow8) * PITCH + nb * 8));
                        LDSM_X2T(vl0, vl1, smem_u32(Vl + (ks * 16 + vrow8) * PITCH + nb * 8));
                        MMA16816(O[nb], ph, vh0, vh1);
                        MMA16816(O[nb], pl, vh0, vh1);
                        MMA16816(O[nb], ph, vl0, vl1);
                    }
                }
            }
        }

        __syncthreads();
        issue_kv(min(kt + 2, kt_max), (kt + 1) & 1);
    }

    float inv0 = (row0 < len && l_[0] > 0.f) ? (1.f / l_[0]) : 0.f;
    float inv1 = (row1 < len && l_[1] > 0.f) ? (1.f / l_[1]) : 0.f;
    size_t rb0 = ((size_t)b * T_ + row0) * C_;
    size_t rb1 = ((size_t)b * T_ + row1) * C_;
    #pragma unroll
    for (int nb = 0; nb < 8; nb++) {
        int hcol = h * HD_ + nb * 8 + cb;
        uint32_t h0 = pack_hi(O[nb][0] * inv0, O[nb][1] * inv0);
        uint32_t l0 = pack_res(O[nb][0] * inv0, O[nb][1] * inv0, h0);
        uint32_t h1 = pack_hi(O[nb][2] * inv1, O[nb][3] * inv1);
        uint32_t l1 = pack_res(O[nb][2] * inv1, O[nb][3] * inv1, h1);
        *(uint32_t*)(yh + rb0 + hcol) = h0;
        *(uint32_t*)(yl + rb0 + hcol) = l0;
        *(uint32_t*)(yh + rb1 + hcol) = h1;
        *(uint32_t*)(yl + rb1 + hcol) = l1;
    }
}

// ---------------------------------------------------------------------------
extern "C" void kernel_launch(void* const* d_in, const int* in_sizes, int n_in,
                              void* d_out, int out_size)
{
    const float* x    = (const float*)d_in[0];
    const int*   am   = (const int*)  d_in[1];
    const float* Wqkv = (const float*)d_in[2];
    const float* bqkv = (const float*)d_in[3];
    const float* Wo   = (const float*)d_in[4];
    const float* bo   = (const float*)d_in[5];
    float* out = (float*)d_out;

    float* qkv;
    __half *xh, *xl, *wqh, *woh, *yh, *yl;
    __half *qh, *ql, *kh, *kl, *vh, *vl;
    int* lenp;
    cudaGetSymbolAddress((void**)&qkv, g_qkv);
    cudaGetSymbolAddress((void**)&xh, g_xh);   cudaGetSymbolAddress((void**)&xl, g_xl);
    cudaGetSymbolAddress((void**)&wqh, g_wqh);
    cudaGetSymbolAddress((void**)&woh, g_woh);
    cudaGetSymbolAddress((void**)&yh, g_yh);   cudaGetSymbolAddress((void**)&yl, g_yl);
    cudaGetSymbolAddress((void**)&qh, g_qh);   cudaGetSymbolAddress((void**)&ql, g_ql);
    cudaGetSymbolAddress((void**)&kh, g_kh);   cudaGetSymbolAddress((void**)&kl, g_kl);
    cudaGetSymbolAddress((void**)&vh, g_vh);   cudaGetSymbolAddress((void**)&vl, g_vl);
    cudaGetSymbolAddress((void**)&lenp, g_len);

    cudaFuncSetAttribute(gemm_fp16<1>, cudaFuncAttributeMaxDynamicSharedMemorySize, GEMM_SMEM);
    cudaFuncSetAttribute(gemm_fp16<2>, cudaFuncAttributeMaxDynamicSharedMemorySize, GEMM_SMEM);
    cudaFuncSetAttribute(flash_attn_tc, cudaFuncAttributeMaxDynamicSharedMemorySize, ATTN_SMEM);

    int nx = M_ * C_, nwq = C3_ * C_, nwo = C_ * C_;
    compute_len<<<B_, 256>>>(am, lenp);
    split_hl<<<nx  / 1024, 256>>>(x, xh, xl, nx);
    conv_h<<<nwq / 1024, 256>>>(Wqkv, wqh, nwq);
    conv_h<<<nwo / 1024, 256>>>(Wo,   woh, nwo);

    gemm_fp16<1><<<dim3(C3_ / 128, M_ / 128), 256, GEMM_SMEM>>>(
        xh, xl, wqh, bqkv, qkv, lenp, M_, C3_, C_);
    qkv_split<<<(int)((size_t)M_ * C3_ / 1024), 256>>>(
        qkv, lenp, qh, ql, kh, kl, vh, vl);
    flash_attn_tc<<<dim3(T_ / 128, H_, B_), 256, ATTN_SMEM>>>(
        qh, ql, kh, kl, vh, vl, lenp, yh, yl);
    gemm_fp16<2><<<dim3(C_ / 128, M_ / 128), 256, GEMM_SMEM>>>(
        yh, yl, woh, bo, out, lenp, M_, C_, C_);
}

// round 15
// speedup vs baseline: 2.6350x; 1.1375x over previous
#include <cuda_runtime.h>
#include <cuda_fp16.h>
#include <cstdint>

// Problem constants
#define B_   4
#define T_   2048
#define C_   1024
#define H_   16
#define HD_  64
#define M_   (B_ * T_)          // 8192
#define C3_  (3 * C_)           // 3072

// ---------------------------------------------------------------------------
// Scratch (device globals)
// ---------------------------------------------------------------------------
__device__ float g_qkv[(size_t)M_ * C3_];
__device__ __half g_xh [(size_t)M_  * C_], g_xl [(size_t)M_  * C_];
__device__ __half g_wqh[(size_t)C3_ * C_];
__device__ __half g_woh[(size_t)C_  * C_];
#define QKV_N ((size_t)B_ * H_ * T_ * HD_)
__device__ __half g_qh[QKV_N], g_ql[QKV_N];
__device__ __half g_kh[QKV_N];
__device__ __half g_vh[QKV_N];
__device__ __half g_yh [(size_t)M_ * C_], g_yl [(size_t)M_ * C_];
__device__ int g_len[B_];

// ---------------------------------------------------------------------------
// Helpers
// ---------------------------------------------------------------------------
__device__ __forceinline__ uint32_t smem_u32(const void* p) {
    uint32_t a;
    asm("{ .reg .u64 t; cvta.to.shared.u64 t, %1; cvt.u32.u64 %0, t; }"
        : "=r"(a) : "l"(p));
    return a;
}

#define MMA16816(C, A, b0, b1)                                                \
    asm volatile(                                                             \
        "mma.sync.aligned.m16n8k16.row.col.f32.f16.f16.f32 "                  \
        "{%0,%1,%2,%3},{%4,%5,%6,%7},{%8,%9},{%0,%1,%2,%3};"                  \
        : "+f"((C)[0]), "+f"((C)[1]), "+f"((C)[2]), "+f"((C)[3])              \
        : "r"((A)[0]), "r"((A)[1]), "r"((A)[2]), "r"((A)[3]),                 \
          "r"(b0), "r"(b1))

#define LDSM_X4(R, addr)                                                      \
    asm volatile("ldmatrix.sync.aligned.m8n8.x4.shared.b16 {%0,%1,%2,%3}, [%4];" \
        : "=r"((R)[0]), "=r"((R)[1]), "=r"((R)[2]), "=r"((R)[3]) : "r"(addr))

#define LDSM_X2(r0, r1, addr)                                                 \
    asm volatile("ldmatrix.sync.aligned.m8n8.x2.shared.b16 {%0,%1}, [%2];"    \
        : "=r"(r0), "=r"(r1) : "r"(addr))

#define LDSM_X2T(r0, r1, addr)                                                \
    asm volatile("ldmatrix.sync.aligned.m8n8.x2.trans.shared.b16 {%0,%1}, [%2];" \
        : "=r"(r0), "=r"(r1) : "r"(addr))

#define CP_ASYNC16(dst, src)                                                  \
    asm volatile("cp.async.cg.shared.global [%0], [%1], 16;"                  \
                 :: "r"(dst), "l"(src) : "memory")
#define CP_COMMIT() asm volatile("cp.async.commit_group;" ::: "memory")
#define CP_WAIT1()  asm volatile("cp.async.wait_group 1;" ::: "memory")

__device__ __forceinline__ uint32_t pack_hi(float a, float b) {
    __half2 v = __floats2half2_rn(a, b);
    return *reinterpret_cast<uint32_t*>(&v);
}
__device__ __forceinline__ uint32_t pack_res(float a, float b, uint32_t hp) {
    __half2 h = *reinterpret_cast<__half2*>(&hp);
    __half2 v = __floats2half2_rn(a - __half2float(h.x),
                                  b - __half2float(h.y));
    return *reinterpret_cast<uint32_t*>(&v);
}

// ---------------------------------------------------------------------------
// HMMA GEMM (2-term fp16, exact activation): Cout = (Ah+Al) @ Wh^T + bias
// 128x128 tile, k-chunk 16, 3-stage cp.async (Ah|Al|Wh), 2 CTAs/SM.
// MODE 1 (QKV): skip M-tiles fully beyond round_up(len,128).
// MODE 2 (proj): for such tiles write bias rows and exit.
// ---------------------------------------------------------------------------
#define GTILE_B    6144
#define GSTAGE_B   (3 * GTILE_B)
#define GEMM_SMEM  (3 * GSTAGE_B)

template <int MODE>
__global__ __launch_bounds__(256, 2) void gemm_fp16(
    const __half* __restrict__ Ah, const __half* __restrict__ Al,
    const __half* __restrict__ Wh,
    const float* __restrict__ bias, float* __restrict__ Cout,
    const int* __restrict__ lenp,
    int M, int N, int K)
{
    extern __shared__ char sm[];
    const int tid = threadIdx.x;
    const int bm = blockIdx.y * 128;
    const int bn = blockIdx.x * 128;

    if (MODE != 0) {
        const int len = lenp[bm >> 11];
        const int lim = (len + 127) & ~127;
        if ((bm & 2047) >= lim) {
            if (MODE == 2) {
                const int c4 = (tid & 31) * 4;
                const int rb = tid >> 5;
                float4 bv = *(const float4*)(bias + bn + c4);
                #pragma unroll
                for (int rr = 0; rr < 16; rr++) {
                    int row = bm + rb * 16 + rr;
                    *(float4*)(Cout + (size_t)row * N + bn + c4) = bv;
                }
            }
            return;
        }
    }

    const int warp = tid >> 5, lane = tid & 31;
    const int moff = (warp >> 1) * 32;
    const int noff = (warp & 1) * 64;

    float acc[2][8][4];
    #pragma unroll
    for (int a = 0; a < 2; a++)
        #pragma unroll
        for (int b = 0; b < 8; b++)
            #pragma unroll
            for (int c = 0; c < 4; c++) acc[a][b][c] = 0.f;

    const int r_ld = tid >> 1, half8 = (tid & 1) * 8;
    auto issue = [&](int c, int s) {
        const int k0 = c << 4;
        char* st = sm + s * GSTAGE_B;
        uint32_t d = smem_u32(st + (r_ld * 24 + half8) * 2);
        CP_ASYNC16(d,               Ah + (size_t)(bm + r_ld) * K + k0 + half8);
        CP_ASYNC16(d + GTILE_B,     Al + (size_t)(bm + r_ld) * K + k0 + half8);
        CP_ASYNC16(d + 2 * GTILE_B, Wh + (size_t)(bn + r_ld) * K + k0 + half8);
        CP_COMMIT();
    };

    const int nk = K >> 4;
    issue(0, 0);
    issue(1, 1);

    const int arow = moff + (lane & 7) + 8 * ((lane >> 3) & 1);
    const int acol = 8 * (lane >> 4);
    const int wrow_l = (lane & 7);
    const int wcol = 8 * ((lane >> 3) & 1);

    int s = 0;
    for (int c = 0; c < nk; c++) {
        CP_WAIT1();
        __syncthreads();
        if (c + 2 < nk) issue(c + 2, (s + 2 >= 3) ? s - 1 : s + 2);
        else CP_COMMIT();

        char* st = sm + s * GSTAGE_B;
        uint32_t ah[2][4], al[2][4];
        #pragma unroll
        for (int mb = 0; mb < 2; mb++) {
            LDSM_X4(ah[mb], smem_u32(st + ((arow + mb * 16) * 24 + acol) * 2));
            LDSM_X4(al[mb], smem_u32(st + GTILE_B + ((arow + mb * 16) * 24 + acol) * 2));
        }
        #pragma unroll
        for (int nb = 0; nb < 8; nb++) {
            int wr = noff + nb * 8 + wrow_l;
            uint32_t bh0, bh1;
            LDSM_X2(bh0, bh1, smem_u32(st + 2 * GTILE_B + (wr * 24 + wcol) * 2));
            #pragma unroll
            for (int mb = 0; mb < 2; mb++) {
                MMA16816(acc[mb][nb], ah[mb], bh0, bh1);
                MMA16816(acc[mb][nb], al[mb], bh0, bh1);
            }
        }
        s = (s + 1 >= 3) ? 0 : s + 1;
    }

    const int r0 = lane >> 2, c0 = (lane & 3) * 2;
    #pragma unroll
    for (int mb = 0; mb < 2; mb++)
        #pragma unroll
        for (int nb = 0; nb < 8; nb++) {
            int row = bm + moff + mb * 16 + r0;
            int col = bn + noff + nb * 8 + c0;
            float2 v0 = make_float2(acc[mb][nb][0] + bias[col],
                                    acc[mb][nb][1] + bias[col + 1]);
            *(float2*)(Cout + (size_t)row * N + col) = v0;
            float2 v1 = make_float2(acc[mb][nb][2] + bias[col],
                                    acc[mb][nb][3] + bias[col + 1]);
            *(float2*)(Cout + (size_t)(row + 8) * N + col) = v1;
        }
}

// ---------------------------------------------------------------------------
// per-batch valid length
// ---------------------------------------------------------------------------
__global__ void compute_len(const int* __restrict__ am, int* __restrict__ out) {
    __shared__ int red[8];
    int b = blockIdx.x, acc = 0;
    for (int i = threadIdx.x; i < T_; i += 256) acc += am[b * T_ + i];
    #pragma unroll
    for (int o = 16; o; o >>= 1) acc += __shfl_xor_sync(0xffffffffu, acc, o);
    if ((threadIdx.x & 31) == 0) red[threadIdx.x >> 5] = acc;
    __syncthreads();
    if (threadIdx.x == 0) {
        int v = 0;
        #pragma unroll
        for (int i = 0; i < 8; i++) v += red[i];
        out[b] = v;
    }
}

// ---------------------------------------------------------------------------
// fp32 -> fp16 hi/lo split (activations)
// ---------------------------------------------------------------------------
__global__ __launch_bounds__(256) void split_hl(
    const float* __restrict__ s, __half* __restrict__ h,
    __half* __restrict__ l, int n)
{
    int i = (blockIdx.x * 256 + threadIdx.x) * 4;
    if (i >= n) return;
    float4 v = *(const float4*)(s + i);
    uint32_t h01 = pack_hi(v.x, v.y), h23 = pack_hi(v.z, v.w);
    uint32_t l01 = pack_res(v.x, v.y, h01), l23 = pack_res(v.z, v.w, h23);
    *(uint32_t*)(h + i) = h01; *(uint32_t*)(h + i + 2) = h23;
    *(uint32_t*)(l + i) = l01; *(uint32_t*)(l + i + 2) = l23;
}

// fp32 -> fp16 (weights: hi only)
__global__ __launch_bounds__(256) void conv_h(
    const float* __restrict__ s, __half* __restrict__ h, int n)
{
    int i = (blockIdx.x * 256 + threadIdx.x) * 4;
    if (i >= n) return;
    float4 v = *(const float4*)(s + i);
    *(uint32_t*)(h + i)     = pack_hi(v.x, v.y);
    *(uint32_t*)(h + i + 2) = pack_hi(v.z, v.w);
}

// ---------------------------------------------------------------------------
// qkv fp32 [M, 3C] -> q hi/lo, k hi, v hi  fp16 [B,H,T,64]; skips dead rows
// ---------------------------------------------------------------------------
__global__ __launch_bounds__(256) void qkv_split(
    const float* __restrict__ qkv, const int* __restrict__ lenp,
    __half* __restrict__ qh, __half* __restrict__ ql,
    __half* __restrict__ kh, __half* __restrict__ vh)
{
    size_t i = ((size_t)blockIdx.x * 256 + threadIdx.x) * 4;
    int row = (int)(i / C3_), col = (int)(i % C3_);
    int b = row >> 11, t = row & 2047;
    int len = lenp[b];
    if (t >= ((len + 127) & ~127)) return;
    float4 v = *(const float4*)(qkv + i);
    int which = col >> 10;
    int hc = col & 1023;
    int head = hc >> 6, d = hc & 63;
    size_t idx = ((((size_t)b * H_) + head) * T_ + t) * HD_ + d;
    uint2 hh;
    hh.x = pack_hi(v.x, v.y); hh.y = pack_hi(v.z, v.w);
    if (which == 0) {
        uint2 ll;
        ll.x = pack_res(v.x, v.y, hh.x); ll.y = pack_res(v.z, v.w, hh.y);
        *(uint2*)(qh + idx) = hh;
        *(uint2*)(ql + idx) = ll;
    } else if (which == 1) {
        *(uint2*)(kh + idx) = hh;
    } else {
        *(uint2*)(vh + idx) = hh;
    }
}

// ---------------------------------------------------------------------------
// Tensor-core flash attention (2-term exact-activation fp16):
//   S = (Qh+Ql) Kh^T ; O = (Ph+Pl) Vh  (fp32 accum).
// Buffers hold Kh|Vh only (halved traffic). LPT order, masked-tile early
// exit, uniform depth-2 cp.async pipeline.
// ---------------------------------------------------------------------------
#define PITCH 72
#define OPB   (64 * PITCH * 2)         // 9216 bytes per 64-row operand tile
#define BUF_B (2 * OPB)                // Kh | Vh = 18432
#define ATTN_SMEM (2 * BUF_B)          // 36864

__global__ __launch_bounds__(256, 1) void flash_attn_tc(
    const __half* __restrict__ qh, const __half* __restrict__ ql,
    const __half* __restrict__ kh, const __half* __restrict__ vh,
    const int* __restrict__ lenp,
    __half* __restrict__ yh, __half* __restrict__ yl)
{
    extern __shared__ char smdyn[];

    const int b = blockIdx.z, h = blockIdx.y;
    const int qt = (int)(gridDim.x - 1 - blockIdx.x);   // LPT: heavy first
    const int q0 = qt * 128;
    const int tid = threadIdx.x;
    const int warp = tid >> 5, lane = tid & 31;
    const int len = lenp[b];
    const size_t bh = ((size_t)b * H_ + h) * T_ * HD_;

    if (q0 >= len) {
        const size_t ybase = ((size_t)b * T_ + q0) * C_ + h * HD_;
        const uint2 z = make_uint2(0u, 0u);
        #pragma unroll
        for (int t = 0; t < 8; t++) {
            int e = tid + t * 256;
            int r = e >> 4, c4 = (e & 15) * 4;
            *(uint2*)(yh + ybase + (size_t)r * C_ + c4) = z;
            *(uint2*)(yl + ybase + (size_t)r * C_ + c4) = z;
        }
        return;
    }

    const int kt_len = (len + 63) >> 6;
    const int kt_max = min(2 * qt + 1, kt_len - 1);

    // tile kt lives in buffer (kt+1)&1
    auto issue_kv = [&](int kt, int buf) {
        char* st = smdyn + buf * BUF_B;
        const size_t kbase = bh + (size_t)(kt * 64) * HD_;
        #pragma unroll
        for (int t = 0; t < 4; t++) {
            int e = tid + t * 256;            // 0..1023
            int op = e >> 9;                  // 0=Kh 1=Vh
            int idx = e & 511;
            int r = idx >> 3, c16 = idx & 7;
            const __half* src = op ? vh : kh;
            CP_ASYNC16(smem_u32(st + op * OPB + (r * PITCH + c16 * 8) * 2),
                       src + kbase + (size_t)r * HD_ + c16 * 8);
        }
        CP_COMMIT();
    };

    // stage Q hi/lo (128 rows): Qh across buf0, Ql across buf1
    {
        const size_t qbase = bh + (size_t)q0 * HD_;
        #pragma unroll
        for (int t = 0; t < 8; t++) {
            int e = tid + t * 256;            // 0..2047
            int part = e >> 10;               // 0=hi 1=lo
            int idx = e & 1023;               // 128 rows x 8 chunks
            int r = idx >> 3, c16 = idx & 7;
            const __half* src = part ? ql : qh;
            CP_ASYNC16(smem_u32(smdyn + part * BUF_B + (r * PITCH + c16 * 8) * 2),
                       src + qbase + (size_t)r * HD_ + c16 * 8);
        }
        CP_COMMIT();                           // group: Q
    }
    CP_COMMIT();                               // empty group (uniform depth)
    asm volatile("cp.async.wait_group 0;" ::: "memory");
    __syncthreads();

    uint32_t qfh[4][4], qfl[4][4];
    {
        __half* Qh = (__half*)smdyn;
        __half* Ql = (__half*)(smdyn + BUF_B);
        int row = warp * 16 + (lane & 7) + 8 * ((lane >> 3) & 1);
        #pragma unroll
        for (int ks = 0; ks < 4; ks++) {
            int col = ks * 16 + 8 * (lane >> 4);
            LDSM_X4(qfh[ks], smem_u32(Qh + row * PITCH + col));
            LDSM_X4(qfl[ks], smem_u32(Ql + row * PITCH + col));
        }
    }
    __syncthreads();                           // both buffers free
    issue_kv(0, 1);                            // kv0 -> buf1
    issue_kv(min(1, kt_max), 0);               // kv1 -> buf0 (clamped)

    float m_[2] = {-1e30f, -1e30f}, l_[2] = {0.f, 0.f};
    float O[8][4] = {};

    const int wrow_max = q0 + warp * 16 + 15;
    const int r0 = lane >> 2, cb = (lane & 3) * 2;
    const int row0 = q0 + warp * 16 + r0, row1 = row0 + 8;

    for (int kt = 0; kt <= kt_max; kt++) {
        const int k0 = kt * 64;
        CP_WAIT1();                            // tile kt resident
        __syncthreads();

        char* st = smdyn + ((kt + 1) & 1) * BUF_B;
        __half* Kh = (__half*)st;
        __half* Vh = (__half*)(st + OPB);

        if (k0 <= wrow_max) {
            // ---- S = (Qh+Ql) Kh^T ----
            float S[8][4] = {};
            {
                int krow = (lane & 7);
                int kcol8 = 8 * ((lane >> 3) & 1);
                #pragma unroll
                for (int nb = 0; nb < 8; nb++) {
                    #pragma unroll
                    for (int ks = 0; ks < 4; ks++) {
                        uint32_t bh0, bh1;
                        LDSM_X2(bh0, bh1, smem_u32(Kh + (nb * 8 + krow) * PITCH + ks * 16 + kcol8));
                        MMA16816(S[nb], qfh[ks], bh0, bh1);
                        MMA16816(S[nb], qfl[ks], bh0, bh1);
                    }
                }
            }

            // ---- mask + online softmax ----
            float ml0 = -1e30f, ml1 = -1e30f;
            #pragma unroll
            for (int nb = 0; nb < 8; nb++) {
                int c0 = k0 + nb * 8 + cb;
                S[nb][0] = (c0     <= row0 && c0     < len) ? S[nb][0] * 0.125f : -1e30f;
                S[nb][1] = (c0 + 1 <= row0 && c0 + 1 < len) ? S[nb][1] * 0.125f : -1e30f;
                S[nb][2] = (c0     <= row1 && c0     < len) ? S[nb][2] * 0.125f : -1e30f;
                S[nb][3] = (c0 + 1 <= row1 && c0 + 1 < len) ? S[nb][3] * 0.125f : -1e30f;
                ml0 = fmaxf(ml0, fmaxf(S[nb][0], S[nb][1]));
                ml1 = fmaxf(ml1, fmaxf(S[nb][2], S[nb][3]));
            }
            ml0 = fmaxf(ml0, __shfl_xor_sync(0xffffffffu, ml0, 1));
            ml0 = fmaxf(ml0, __shfl_xor_sync(0xffffffffu, ml0, 2));
            ml1 = fmaxf(ml1, __shfl_xor_sync(0xffffffffu, ml1, 1));
            ml1 = fmaxf(ml1, __shfl_xor_sync(0xffffffffu, ml1, 2));
            float mn0 = fmaxf(m_[0], ml0), mn1 = fmaxf(m_[1], ml1);
            float corr0 = __expf(m_[0] - mn0), corr1 = __expf(m_[1] - mn1);
            float ls0 = 0.f, ls1 = 0.f;
            #pragma unroll
            for (int nb = 0; nb < 8; nb++) {
                S[nb][0] = __expf(S[nb][0] - mn0); ls0 += S[nb][0];
                S[nb][1] = __expf(S[nb][1] - mn0); ls0 += S[nb][1];
                S[nb][2] = __expf(S[nb][2] - mn1); ls1 += S[nb][2];
                S[nb][3] = __expf(S[nb][3] - mn1); ls1 += S[nb][3];
            }
            ls0 += __shfl_xor_sync(0xffffffffu, ls0, 1);
            ls0 += __shfl_xor_sync(0xffffffffu, ls0, 2);
            ls1 += __shfl_xor_sync(0xffffffffu, ls1, 1);
            ls1 += __shfl_xor_sync(0xffffffffu, ls1, 2);
            l_[0] = l_[0] * corr0 + ls0;
            l_[1] = l_[1] * corr1 + ls1;
            m_[0] = mn0; m_[1] = mn1;
            #pragma unroll
            for (int nb = 0; nb < 8; nb++) {
                O[nb][0] *= corr0; O[nb][1] *= corr0;
                O[nb][2] *= corr1; O[nb][3] *= corr1;
            }

            // ---- O += (Ph+Pl) Vh ----
            {
                int vrow8 = (lane & 7) + 8 * ((lane >> 3) & 1);
                #pragma unroll
                for (int ks = 0; ks < 4; ks++) {
                    uint32_t ph[4], pl[4];
                    ph[0] = pack_hi(S[2 * ks][0], S[2 * ks][1]);
                    ph[1] = pack_hi(S[2 * ks][2], S[2 * ks][3]);
                    ph[2] = pack_hi(S[2 * ks + 1][0], S[2 * ks + 1][1]);
                    ph[3] = pack_hi(S[2 * ks + 1][2], S[2 * ks + 1][3]);
                    pl[0] = pack_res(S[2 * ks][0], S[2 * ks][1], ph[0]);
                    pl[1] = pack_res(S[2 * ks][2], S[2 * ks][3], ph[1]);
                    pl[2] = pack_res(S[2 * ks + 1][0], S[2 * ks + 1][1], ph[2]);
                    pl[3] = pack_res(S[2 * ks + 1][2], S[2 * ks + 1][3], ph[3]);
                    #pragma unroll
                    for (int nb = 0; nb < 8; nb++) {
                        uint32_t vh0, vh1;
                        LDSM_X2T(vh0, vh1, smem_u32(Vh + (ks * 16 + vrow8) * PITCH + nb * 8));
                        MMA16816(O[nb], ph, vh0, vh1);
                        MMA16816(O[nb], pl, vh0, vh1);
                    }
                }
            }
        }

        __syncthreads();                       // all warps done with buffer
        issue_kv(min(kt + 2, kt_max), (kt + 1) & 1);   // uniform, clamped
    }

    // ---- epilogue: normalize, split hi/lo, store ----
    float inv0 = (row0 < len && l_[0] > 0.f) ? (1.f / l_[0]) : 0.f;
    float inv1 = (row1 < len && l_[1] > 0.f) ? (1.f / l_[1]) : 0.f;
    size_t rb0 = ((size_t)b * T_ + row0) * C_;
    size_t rb1 = ((size_t)b * T_ + row1) * C_;
    #pragma unroll
    for (int nb = 0; nb < 8; nb++) {
        int hcol = h * HD_ + nb * 8 + cb;
        uint32_t h0 = pack_hi(O[nb][0] * inv0, O[nb][1] * inv0);
        uint32_t l0 = pack_res(O[nb][0] * inv0, O[nb][1] * inv0, h0);
        uint32_t h1 = pack_hi(O[nb][2] * inv1, O[nb][3] * inv1);
        uint32_t l1 = pack_res(O[nb][2] * inv1, O[nb][3] * inv1, h1);
        *(uint32_t*)(yh + rb0 + hcol) = h0;
        *(uint32_t*)(yl + rb0 + hcol) = l0;
        *(uint32_t*)(yh + rb1 + hcol) = h1;
        *(uint32_t*)(yl + rb1 + hcol) = l1;
    }
}

// ---------------------------------------------------------------------------
extern "C" void kernel_launch(void* const* d_in, const int* in_sizes, int n_in,
                              void* d_out, int out_size)
{
    const float* x    = (const float*)d_in[0];
    const int*   am   = (const int*)  d_in[1];
    const float* Wqkv = (const float*)d_in[2];
    const float* bqkv = (const float*)d_in[3];
    const float* Wo   = (const float*)d_in[4];
    const float* bo   = (const float*)d_in[5];
    float* out = (float*)d_out;

    float* qkv;
    __half *xh, *xl, *wqh, *woh, *yh, *yl;
    __half *qh, *ql, *kh, *vh;
    int* lenp;
    cudaGetSymbolAddress((void**)&qkv, g_qkv);
    cudaGetSymbolAddress((void**)&xh, g_xh);   cudaGetSymbolAddress((void**)&xl, g_xl);
    cudaGetSymbolAddress((void**)&wqh, g_wqh);
    cudaGetSymbolAddress((void**)&woh, g_woh);
    cudaGetSymbolAddress((void**)&yh, g_yh);   cudaGetSymbolAddress((void**)&yl, g_yl);
    cudaGetSymbolAddress((void**)&qh, g_qh);   cudaGetSymbolAddress((void**)&ql, g_ql);
    cudaGetSymbolAddress((void**)&kh, g_kh);
    cudaGetSymbolAddress((void**)&vh, g_vh);
    cudaGetSymbolAddress((void**)&lenp, g_len);

    cudaFuncSetAttribute(gemm_fp16<1>, cudaFuncAttributeMaxDynamicSharedMemorySize, GEMM_SMEM);
    cudaFuncSetAttribute(gemm_fp16<2>, cudaFuncAttributeMaxDynamicSharedMemorySize, GEMM_SMEM);
    cudaFuncSetAttribute(flash_attn_tc, cudaFuncAttributeMaxDynamicSharedMemorySize, ATTN_SMEM);

    int nx = M_ * C_, nwq = C3_ * C_, nwo = C_ * C_;
    compute_len<<<B_, 256>>>(am, lenp);
    split_hl<<<nx  / 1024, 256>>>(x, xh, xl, nx);
    conv_h<<<nwq / 1024, 256>>>(Wqkv, wqh, nwq);
    conv_h<<<nwo / 1024, 256>>>(Wo,   woh, nwo);

    gemm_fp16<1><<<dim3(C3_ / 128, M_ / 128), 256, GEMM_SMEM>>>(
        xh, xl, wqh, bqkv, qkv, lenp, M_, C3_, C_);
    qkv_split<<<(int)((size_t)M_ * C3_ / 1024), 256>>>(
        qkv, lenp, qh, ql, kh, vh);
    flash_attn_tc<<<dim3(T_ / 128, H_, B_), 256, ATTN_SMEM>>>(
        qh, ql, kh, vh, lenp, yh, yl);
    gemm_fp16<2><<<dim3(C_ / 128, M_ / 128), 256, GEMM_SMEM>>>(
        yh, yl, woh, bo, out, lenp, M_, C_, C_);
}

// round 16
// speedup vs baseline: 3.0820x; 1.1696x over previous
#include <cuda_runtime.h>
#include <cuda_fp16.h>
#include <cstdint>

// Problem constants
#define B_   4
#define T_   2048
#define C_   1024
#define H_   16
#define HD_  64
#define M_   (B_ * T_)          // 8192
#define C3_  (3 * C_)           // 3072

// ---------------------------------------------------------------------------
// Scratch (device globals)
// ---------------------------------------------------------------------------
__device__ float g_qkv[(size_t)M_ * C3_];
__device__ __half g_xh [(size_t)M_  * C_], g_xl [(size_t)M_  * C_];
__device__ __half g_wqh[(size_t)C3_ * C_];
__device__ __half g_woh[(size_t)C_  * C_];
#define QKV_N ((size_t)B_ * H_ * T_ * HD_)
__device__ __half g_qh[QKV_N];
__device__ __half g_kh[QKV_N];
__device__ __half g_vh[QKV_N];
__device__ __half g_yh [(size_t)M_ * C_];
__device__ int g_len[B_];

// ---------------------------------------------------------------------------
// Helpers
// ---------------------------------------------------------------------------
__device__ __forceinline__ uint32_t smem_u32(const void* p) {
    uint32_t a;
    asm("{ .reg .u64 t; cvta.to.shared.u64 t, %1; cvt.u32.u64 %0, t; }"
        : "=r"(a) : "l"(p));
    return a;
}

#define MMA16816(C, A, b0, b1)                                                \
    asm volatile(                                                             \
        "mma.sync.aligned.m16n8k16.row.col.f32.f16.f16.f32 "                  \
        "{%0,%1,%2,%3},{%4,%5,%6,%7},{%8,%9},{%0,%1,%2,%3};"                  \
        : "+f"((C)[0]), "+f"((C)[1]), "+f"((C)[2]), "+f"((C)[3])              \
        : "r"((A)[0]), "r"((A)[1]), "r"((A)[2]), "r"((A)[3]),                 \
          "r"(b0), "r"(b1))

#define LDSM_X4(R, addr)                                                      \
    asm volatile("ldmatrix.sync.aligned.m8n8.x4.shared.b16 {%0,%1,%2,%3}, [%4];" \
        : "=r"((R)[0]), "=r"((R)[1]), "=r"((R)[2]), "=r"((R)[3]) : "r"(addr))

#define LDSM_X2(r0, r1, addr)                                                 \
    asm volatile("ldmatrix.sync.aligned.m8n8.x2.shared.b16 {%0,%1}, [%2];"    \
        : "=r"(r0), "=r"(r1) : "r"(addr))

#define LDSM_X2T(r0, r1, addr)                                                \
    asm volatile("ldmatrix.sync.aligned.m8n8.x2.trans.shared.b16 {%0,%1}, [%2];" \
        : "=r"(r0), "=r"(r1) : "r"(addr))

#define CP_ASYNC16(dst, src)                                                  \
    asm volatile("cp.async.cg.shared.global [%0], [%1], 16;"                  \
                 :: "r"(dst), "l"(src) : "memory")
#define CP_COMMIT() asm volatile("cp.async.commit_group;" ::: "memory")
#define CP_WAIT1()  asm volatile("cp.async.wait_group 1;" ::: "memory")

__device__ __forceinline__ uint32_t pack_hi(float a, float b) {
    __half2 v = __floats2half2_rn(a, b);
    return *reinterpret_cast<uint32_t*>(&v);
}
__device__ __forceinline__ uint32_t pack_res(float a, float b, uint32_t hp) {
    __half2 h = *reinterpret_cast<__half2*>(&hp);
    __half2 v = __floats2half2_rn(a - __half2float(h.x),
                                  b - __half2float(h.y));
    return *reinterpret_cast<uint32_t*>(&v);
}

// ---------------------------------------------------------------------------
// HMMA GEMM fp16: Cout = A @ Wh^T + bias
// TERMS=2: A = Ah+Al (exact activation). TERMS=1: A = Ah only.
// 128x128 tile, k-chunk 16, 3-stage cp.async, 2 CTAs/SM.
// MODE 1 (QKV): skip M-tiles fully beyond round_up(len,128).
// MODE 2 (proj): for such tiles write bias rows and exit.
// ---------------------------------------------------------------------------
#define GTILE_B    6144
#define GEMM_SMEM  (9 * GTILE_B)   // max: 3 stages x 3 tiles

template <int MODE, int TERMS>
__global__ __launch_bounds__(256, 2) void gemm_fp16(
    const __half* __restrict__ Ah, const __half* __restrict__ Al,
    const __half* __restrict__ Wh,
    const float* __restrict__ bias, float* __restrict__ Cout,
    const int* __restrict__ lenp,
    int M, int N, int K)
{
    extern __shared__ char sm[];
    const int tid = threadIdx.x;
    const int bm = blockIdx.y * 128;
    const int bn = blockIdx.x * 128;
    constexpr int NT = TERMS + 1;              // tiles per stage
    constexpr int STG = NT * GTILE_B;

    if (MODE != 0) {
        const int len = lenp[bm >> 11];
        const int lim = (len + 127) & ~127;
        if ((bm & 2047) >= lim) {
            if (MODE == 2) {
                const int c4 = (tid & 31) * 4;
                const int rb = tid >> 5;
                float4 bv = *(const float4*)(bias + bn + c4);
                #pragma unroll
                for (int rr = 0; rr < 16; rr++) {
                    int row = bm + rb * 16 + rr;
                    *(float4*)(Cout + (size_t)row * N + bn + c4) = bv;
                }
            }
            return;
        }
    }

    const int warp = tid >> 5, lane = tid & 31;
    const int moff = (warp >> 1) * 32;
    const int noff = (warp & 1) * 64;

    float acc[2][8][4];
    #pragma unroll
    for (int a = 0; a < 2; a++)
        #pragma unroll
        for (int b = 0; b < 8; b++)
            #pragma unroll
            for (int c = 0; c < 4; c++) acc[a][b][c] = 0.f;

    const int r_ld = tid >> 1, half8 = (tid & 1) * 8;
    auto issue = [&](int c, int s) {
        const int k0 = c << 4;
        char* st = sm + s * STG;
        uint32_t d = smem_u32(st + (r_ld * 24 + half8) * 2);
        CP_ASYNC16(d, Ah + (size_t)(bm + r_ld) * K + k0 + half8);
        if (TERMS == 2)
            CP_ASYNC16(d + GTILE_B, Al + (size_t)(bm + r_ld) * K + k0 + half8);
        CP_ASYNC16(d + TERMS * GTILE_B, Wh + (size_t)(bn + r_ld) * K + k0 + half8);
        CP_COMMIT();
    };

    const int nk = K >> 4;
    issue(0, 0);
    issue(1, 1);

    const int arow = moff + (lane & 7) + 8 * ((lane >> 3) & 1);
    const int acol = 8 * (lane >> 4);
    const int wrow_l = (lane & 7);
    const int wcol = 8 * ((lane >> 3) & 1);

    int s = 0;
    for (int c = 0; c < nk; c++) {
        CP_WAIT1();
        __syncthreads();
        if (c + 2 < nk) issue(c + 2, (s + 2 >= 3) ? s - 1 : s + 2);
        else CP_COMMIT();

        char* st = sm + s * STG;
        uint32_t ah[2][4], al[2][4];
        #pragma unroll
        for (int mb = 0; mb < 2; mb++) {
            LDSM_X4(ah[mb], smem_u32(st + ((arow + mb * 16) * 24 + acol) * 2));
            if (TERMS == 2)
                LDSM_X4(al[mb], smem_u32(st + GTILE_B + ((arow + mb * 16) * 24 + acol) * 2));
        }
        #pragma unroll
        for (int nb = 0; nb < 8; nb++) {
            int wr = noff + nb * 8 + wrow_l;
            uint32_t bh0, bh1;
            LDSM_X2(bh0, bh1, smem_u32(st + TERMS * GTILE_B + (wr * 24 + wcol) * 2));
            #pragma unroll
            for (int mb = 0; mb < 2; mb++) {
                MMA16816(acc[mb][nb], ah[mb], bh0, bh1);
                if (TERMS == 2) MMA16816(acc[mb][nb], al[mb], bh0, bh1);
            }
        }
        s = (s + 1 >= 3) ? 0 : s + 1;
    }

    const int r0 = lane >> 2, c0 = (lane & 3) * 2;
    #pragma unroll
    for (int mb = 0; mb < 2; mb++)
        #pragma unroll
        for (int nb = 0; nb < 8; nb++) {
            int row = bm + moff + mb * 16 + r0;
            int col = bn + noff + nb * 8 + c0;
            float2 v0 = make_float2(acc[mb][nb][0] + bias[col],
                                    acc[mb][nb][1] + bias[col + 1]);
            *(float2*)(Cout + (size_t)row * N + col) = v0;
            float2 v1 = make_float2(acc[mb][nb][2] + bias[col],
                                    acc[mb][nb][3] + bias[col + 1]);
            *(float2*)(Cout + (size_t)(row + 8) * N + col) = v1;
        }
}

// ---------------------------------------------------------------------------
// per-batch valid length
// ---------------------------------------------------------------------------
__global__ void compute_len(const int* __restrict__ am, int* __restrict__ out) {
    __shared__ int red[8];
    int b = blockIdx.x, acc = 0;
    for (int i = threadIdx.x; i < T_; i += 256) acc += am[b * T_ + i];
    #pragma unroll
    for (int o = 16; o; o >>= 1) acc += __shfl_xor_sync(0xffffffffu, acc, o);
    if ((threadIdx.x & 31) == 0) red[threadIdx.x >> 5] = acc;
    __syncthreads();
    if (threadIdx.x == 0) {
        int v = 0;
        #pragma unroll
        for (int i = 0; i < 8; i++) v += red[i];
        out[b] = v;
    }
}

// ---------------------------------------------------------------------------
// fp32 -> fp16 hi/lo split (x)
// ---------------------------------------------------------------------------
__global__ __launch_bounds__(256) void split_hl(
    const float* __restrict__ s, __half* __restrict__ h,
    __half* __restrict__ l, int n)
{
    int i = (blockIdx.x * 256 + threadIdx.x) * 4;
    if (i >= n) return;
    float4 v = *(const float4*)(s + i);
    uint32_t h01 = pack_hi(v.x, v.y), h23 = pack_hi(v.z, v.w);
    uint32_t l01 = pack_res(v.x, v.y, h01), l23 = pack_res(v.z, v.w, h23);
    *(uint32_t*)(h + i) = h01; *(uint32_t*)(h + i + 2) = h23;
    *(uint32_t*)(l + i) = l01; *(uint32_t*)(l + i + 2) = l23;
}

// fp32 -> fp16 (weights)
__global__ __launch_bounds__(256) void conv_h(
    const float* __restrict__ s, __half* __restrict__ h, int n)
{
    int i = (blockIdx.x * 256 + threadIdx.x) * 4;
    if (i >= n) return;
    float4 v = *(const float4*)(s + i);
    *(uint32_t*)(h + i)     = pack_hi(v.x, v.y);
    *(uint32_t*)(h + i + 2) = pack_hi(v.z, v.w);
}

// ---------------------------------------------------------------------------
// qkv fp32 [M, 3C] -> q/k/v fp16 [B,H,T,64]; skips dead rows
// ---------------------------------------------------------------------------
__global__ __launch_bounds__(256) void qkv_split(
    const float* __restrict__ qkv, const int* __restrict__ lenp,
    __half* __restrict__ qh, __half* __restrict__ kh, __half* __restrict__ vh)
{
    size_t i = ((size_t)blockIdx.x * 256 + threadIdx.x) * 4;
    int row = (int)(i / C3_), col = (int)(i % C3_);
    int b = row >> 11, t = row & 2047;
    int len = lenp[b];
    if (t >= ((len + 127) & ~127)) return;
    float4 v = *(const float4*)(qkv + i);
    int which = col >> 10;
    int hc = col & 1023;
    int head = hc >> 6, d = hc & 63;
    size_t idx = ((((size_t)b * H_) + head) * T_ + t) * HD_ + d;
    __half* O = (which == 0) ? qh : (which == 1) ? kh : vh;
    uint2 hh;
    hh.x = pack_hi(v.x, v.y); hh.y = pack_hi(v.z, v.w);
    *(uint2*)(O + idx) = hh;
}

// ---------------------------------------------------------------------------
// Pure-fp16 tensor-core flash attention (fp32 accumulate):
//   S = Qh Kh^T ; O += Ph Vh.
// LPT order, masked-tile early exit, uniform depth-2 cp.async pipeline.
// ---------------------------------------------------------------------------
#define PITCH 72
#define OPB   (64 * PITCH * 2)         // 9216 per 64-row operand
#define BUF_B (2 * OPB)                // Kh | Vh = 18432
#define ATTN_SMEM (2 * BUF_B)          // 36864

__global__ __launch_bounds__(256, 1) void flash_attn_tc(
    const __half* __restrict__ qh, const __half* __restrict__ kh,
    const __half* __restrict__ vh,
    const int* __restrict__ lenp, __half* __restrict__ yh)
{
    extern __shared__ char smdyn[];

    const int b = blockIdx.z, h = blockIdx.y;
    const int qt = (int)(gridDim.x - 1 - blockIdx.x);   // LPT: heavy first
    const int q0 = qt * 128;
    const int tid = threadIdx.x;
    const int warp = tid >> 5, lane = tid & 31;
    const int len = lenp[b];
    const size_t bh = ((size_t)b * H_ + h) * T_ * HD_;

    if (q0 >= len) {
        const size_t ybase = ((size_t)b * T_ + q0) * C_ + h * HD_;
        const uint2 z = make_uint2(0u, 0u);
        #pragma unroll
        for (int t = 0; t < 4; t++) {
            int e = tid + t * 256;            // 1024 uint2 slots = 128 rows
            int r = e >> 3, c4 = (e & 7) * 8;
            *(uint2*)(yh + ybase + (size_t)r * C_ + c4) = z;
            *(uint2*)(yh + ybase + (size_t)r * C_ + c4 + 4) = z;
        }
        return;
    }

    const int kt_len = (len + 63) >> 6;
    const int kt_max = min(2 * qt + 1, kt_len - 1);

    auto issue_kv = [&](int kt, int buf) {
        char* st = smdyn + buf * BUF_B;
        const size_t kbase = bh + (size_t)(kt * 64) * HD_;
        #pragma unroll
        for (int t = 0; t < 4; t++) {
            int e = tid + t * 256;            // 0..1023
            int op = e >> 9;                  // 0=Kh 1=Vh
            int idx = e & 511;
            int r = idx >> 3, c16 = idx & 7;
            const __half* src = op ? vh : kh;
            CP_ASYNC16(smem_u32(st + op * OPB + (r * PITCH + c16 * 8) * 2),
                       src + kbase + (size_t)r * HD_ + c16 * 8);
        }
        CP_COMMIT();
    };

    // stage Qh (128 rows) into buf0
    {
        const size_t qbase = bh + (size_t)q0 * HD_;
        #pragma unroll
        for (int t = 0; t < 4; t++) {
            int e = tid + t * 256;            // 0..1023
            int r = e >> 3, c16 = e & 7;
            CP_ASYNC16(smem_u32(smdyn + (r * PITCH + c16 * 8) * 2),
                       qh + qbase + (size_t)r * HD_ + c16 * 8);
        }
        CP_COMMIT();                           // group: Q
    }
    issue_kv(0, 1);                            // group: kv0 -> buf1
    CP_WAIT1();                                // Q arrived
    __syncthreads();

    uint32_t qf[4][4];
    {
        __half* Qh = (__half*)smdyn;
        int row = warp * 16 + (lane & 7) + 8 * ((lane >> 3) & 1);
        #pragma unroll
        for (int ks = 0; ks < 4; ks++) {
            int col = ks * 16 + 8 * (lane >> 4);
            LDSM_X4(qf[ks], smem_u32(Qh + row * PITCH + col));
        }
    }
    __syncthreads();                           // buf0 free
    issue_kv(min(1, kt_max), 0);               // kv1 -> buf0 (clamped)

    float m_[2] = {-1e30f, -1e30f}, l_[2] = {0.f, 0.f};
    float O[8][4] = {};

    const int wrow_max = q0 + warp * 16 + 15;
    const int r0 = lane >> 2, cb = (lane & 3) * 2;
    const int row0 = q0 + warp * 16 + r0, row1 = row0 + 8;

    for (int kt = 0; kt <= kt_max; kt++) {
        const int k0 = kt * 64;
        CP_WAIT1();                            // tile kt resident
        __syncthreads();

        char* st = smdyn + ((kt + 1) & 1) * BUF_B;
        __half* Kh = (__half*)st;
        __half* Vh = (__half*)(st + OPB);

        if (k0 <= wrow_max) {
            // ---- S = Qh Kh^T ----
            float S[8][4] = {};
            {
                int krow = (lane & 7);
                int kcol8 = 8 * ((lane >> 3) & 1);
                #pragma unroll
                for (int nb = 0; nb < 8; nb++) {
                    #pragma unroll
                    for (int ks = 0; ks < 4; ks++) {
                        uint32_t bh0, bh1;
                        LDSM_X2(bh0, bh1, smem_u32(Kh + (nb * 8 + krow) * PITCH + ks * 16 + kcol8));
                        MMA16816(S[nb], qf[ks], bh0, bh1);
                    }
                }
            }

            // ---- mask + online softmax ----
            float ml0 = -1e30f, ml1 = -1e30f;
            #pragma unroll
            for (int nb = 0; nb < 8; nb++) {
                int c0 = k0 + nb * 8 + cb;
                S[nb][0] = (c0     <= row0 && c0     < len) ? S[nb][0] * 0.125f : -1e30f;
                S[nb][1] = (c0 + 1 <= row0 && c0 + 1 < len) ? S[nb][1] * 0.125f : -1e30f;
                S[nb][2] = (c0     <= row1 && c0     < len) ? S[nb][2] * 0.125f : -1e30f;
                S[nb][3] = (c0 + 1 <= row1 && c0 + 1 < len) ? S[nb][3] * 0.125f : -1e30f;
                ml0 = fmaxf(ml0, fmaxf(S[nb][0], S[nb][1]));
                ml1 = fmaxf(ml1, fmaxf(S[nb][2], S[nb][3]));
            }
            ml0 = fmaxf(ml0, __shfl_xor_sync(0xffffffffu, ml0, 1));
            ml0 = fmaxf(ml0, __shfl_xor_sync(0xffffffffu, ml0, 2));
            ml1 = fmaxf(ml1, __shfl_xor_sync(0xffffffffu, ml1, 1));
            ml1 = fmaxf(ml1, __shfl_xor_sync(0xffffffffu, ml1, 2));
            float mn0 = fmaxf(m_[0], ml0), mn1 = fmaxf(m_[1], ml1);
            float corr0 = __expf(m_[0] - mn0), corr1 = __expf(m_[1] - mn1);
            float ls0 = 0.f, ls1 = 0.f;
            #pragma unroll
            for (int nb = 0; nb < 8; nb++) {
                S[nb][0] = __expf(S[nb][0] - mn0); ls0 += S[nb][0];
                S[nb][1] = __expf(S[nb][1] - mn0); ls0 += S[nb][1];
                S[nb][2] = __expf(S[nb][2] - mn1); ls1 += S[nb][2];
                S[nb][3] = __expf(S[nb][3] - mn1); ls1 += S[nb][3];
            }
            ls0 += __shfl_xor_sync(0xffffffffu, ls0, 1);
            ls0 += __shfl_xor_sync(0xffffffffu, ls0, 2);
            ls1 += __shfl_xor_sync(0xffffffffu, ls1, 1);
            ls1 += __shfl_xor_sync(0xffffffffu, ls1, 2);
            l_[0] = l_[0] * corr0 + ls0;
            l_[1] = l_[1] * corr1 + ls1;
            m_[0] = mn0; m_[1] = mn1;
            #pragma unroll
            for (int nb = 0; nb < 8; nb++) {
                O[nb][0] *= corr0; O[nb][1] *= corr0;
                O[nb][2] *= corr1; O[nb][3] *= corr1;
            }

            // ---- O += Ph Vh ----
            {
                int vrow8 = (lane & 7) + 8 * ((lane >> 3) & 1);
                #pragma unroll
                for (int ks = 0; ks < 4; ks++) {
                    uint32_t ph[4];
                    ph[0] = pack_hi(S[2 * ks][0], S[2 * ks][1]);
                    ph[1] = pack_hi(S[2 * ks][2], S[2 * ks][3]);
                    ph[2] = pack_hi(S[2 * ks + 1][0], S[2 * ks + 1][1]);
                    ph[3] = pack_hi(S[2 * ks + 1][2], S[2 * ks + 1][3]);
                    #pragma unroll
                    for (int nb = 0; nb < 8; nb++) {
                        uint32_t vh0, vh1;
                        LDSM_X2T(vh0, vh1, smem_u32(Vh + (ks * 16 + vrow8) * PITCH + nb * 8));
                        MMA16816(O[nb], ph, vh0, vh1);
                    }
                }
            }
        }

        __syncthreads();
        issue_kv(min(kt + 2, kt_max), (kt + 1) & 1);   // uniform, clamped
    }

    // ---- epilogue: normalize, store fp16 y ----
    float inv0 = (row0 < len && l_[0] > 0.f) ? (1.f / l_[0]) : 0.f;
    float inv1 = (row1 < len && l_[1] > 0.f) ? (1.f / l_[1]) : 0.f;
    size_t rb0 = ((size_t)b * T_ + row0) * C_;
    size_t rb1 = ((size_t)b * T_ + row1) * C_;
    #pragma unroll
    for (int nb = 0; nb < 8; nb++) {
        int hcol = h * HD_ + nb * 8 + cb;
        *(uint32_t*)(yh + rb0 + hcol) = pack_hi(O[nb][0] * inv0, O[nb][1] * inv0);
        *(uint32_t*)(yh + rb1 + hcol) = pack_hi(O[nb][2] * inv1, O[nb][3] * inv1);
    }
}

// ---------------------------------------------------------------------------
extern "C" void kernel_launch(void* const* d_in, const int* in_sizes, int n_in,
                              void* d_out, int out_size)
{
    const float* x    = (const float*)d_in[0];
    const int*   am   = (const int*)  d_in[1];
    const float* Wqkv = (const float*)d_in[2];
    const float* bqkv = (const float*)d_in[3];
    const float* Wo   = (const float*)d_in[4];
    const float* bo   = (const float*)d_in[5];
    float* out = (float*)d_out;

    float* qkv;
    __half *xh, *xl, *wqh, *woh, *yh;
    __half *qh, *kh, *vh;
    int* lenp;
    cudaGetSymbolAddress((void**)&qkv, g_qkv);
    cudaGetSymbolAddress((void**)&xh, g_xh);   cudaGetSymbolAddress((void**)&xl, g_xl);
    cudaGetSymbolAddress((void**)&wqh, g_wqh);
    cudaGetSymbolAddress((void**)&woh, g_woh);
    cudaGetSymbolAddress((void**)&yh, g_yh);
    cudaGetSymbolAddress((void**)&qh, g_qh);
    cudaGetSymbolAddress((void**)&kh, g_kh);
    cudaGetSymbolAddress((void**)&vh, g_vh);
    cudaGetSymbolAddress((void**)&lenp, g_len);

    cudaFuncSetAttribute((const void*)gemm_fp16<1, 2>,
                         cudaFuncAttributeMaxDynamicSharedMemorySize, GEMM_SMEM);
    cudaFuncSetAttribute((const void*)gemm_fp16<2, 1>,
                         cudaFuncAttributeMaxDynamicSharedMemorySize, GEMM_SMEM);
    cudaFuncSetAttribute(flash_attn_tc, cudaFuncAttributeMaxDynamicSharedMemorySize, ATTN_SMEM);

    int nx = M_ * C_, nwq = C3_ * C_, nwo = C_ * C_;
    compute_len<<<B_, 256>>>(am, lenp);
    split_hl<<<nx  / 1024, 256>>>(x, xh, xl, nx);
    conv_h<<<nwq / 1024, 256>>>(Wqkv, wqh, nwq);
    conv_h<<<nwo / 1024, 256>>>(Wo,   woh, nwo);

    gemm_fp16<1, 2><<<dim3(C3_ / 128, M_ / 128), 256, GEMM_SMEM>>>(
        xh, xl, wqh, bqkv, qkv, lenp, M_, C3_, C_);
    qkv_split<<<(int)((size_t)M_ * C3_ / 1024), 256>>>(
        qkv, lenp, qh, kh, vh);
    flash_attn_tc<<<dim3(T_ / 128, H_, B_), 256, ATTN_SMEM>>>(
        qh, kh, vh, lenp, yh);
    gemm_fp16<2, 1><<<dim3(C_ / 128, M_ / 128), 256, GEMM_SMEM>>>(
        yh, nullptr, woh, bo, out, lenp, M_, C_, C_);
}

// round 17
// speedup vs baseline: 3.7756x; 1.2250x over previous
#include <cuda_runtime.h>
#include <cuda_fp16.h>
#include <cstdint>

// Problem constants
#define B_   4
#define T_   2048
#define C_   1024
#define H_   16
#define HD_  64
#define M_   (B_ * T_)          // 8192
#define C3_  (3 * C_)           // 3072

// ---------------------------------------------------------------------------
// Scratch (device globals)
// ---------------------------------------------------------------------------
__device__ __half g_qkv16[(size_t)M_ * C3_];
__device__ __half g_xh [(size_t)M_  * C_];
__device__ __half g_wqh[(size_t)C3_ * C_];
__device__ __half g_woh[(size_t)C_  * C_];
#define QKV_N ((size_t)B_ * H_ * T_ * HD_)
__device__ __half g_qh[QKV_N];
__device__ __half g_kh[QKV_N];
__device__ __half g_vh[QKV_N];
__device__ __half g_yh [(size_t)M_ * C_];
__device__ int g_len[B_];

// ---------------------------------------------------------------------------
// Helpers
// ---------------------------------------------------------------------------
__device__ __forceinline__ uint32_t smem_u32(const void* p) {
    uint32_t a;
    asm("{ .reg .u64 t; cvta.to.shared.u64 t, %1; cvt.u32.u64 %0, t; }"
        : "=r"(a) : "l"(p));
    return a;
}

#define MMA16816(C, A, b0, b1)                                                \
    asm volatile(                                                             \
        "mma.sync.aligned.m16n8k16.row.col.f32.f16.f16.f32 "                  \
        "{%0,%1,%2,%3},{%4,%5,%6,%7},{%8,%9},{%0,%1,%2,%3};"                  \
        : "+f"((C)[0]), "+f"((C)[1]), "+f"((C)[2]), "+f"((C)[3])              \
        : "r"((A)[0]), "r"((A)[1]), "r"((A)[2]), "r"((A)[3]),                 \
          "r"(b0), "r"(b1))

#define LDSM_X4(R, addr)                                                      \
    asm volatile("ldmatrix.sync.aligned.m8n8.x4.shared.b16 {%0,%1,%2,%3}, [%4];" \
        : "=r"((R)[0]), "=r"((R)[1]), "=r"((R)[2]), "=r"((R)[3]) : "r"(addr))

#define LDSM_X2(r0, r1, addr)                                                 \
    asm volatile("ldmatrix.sync.aligned.m8n8.x2.shared.b16 {%0,%1}, [%2];"    \
        : "=r"(r0), "=r"(r1) : "r"(addr))

#define LDSM_X2T(r0, r1, addr)                                                \
    asm volatile("ldmatrix.sync.aligned.m8n8.x2.trans.shared.b16 {%0,%1}, [%2];" \
        : "=r"(r0), "=r"(r1) : "r"(addr))

#define CP_ASYNC16(dst, src)                                                  \
    asm volatile("cp.async.cg.shared.global [%0], [%1], 16;"                  \
                 :: "r"(dst), "l"(src) : "memory")
#define CP_COMMIT() asm volatile("cp.async.commit_group;" ::: "memory")
#define CP_WAIT1()  asm volatile("cp.async.wait_group 1;" ::: "memory")

__device__ __forceinline__ uint32_t pack_hi(float a, float b) {
    __half2 v = __floats2half2_rn(a, b);
    return *reinterpret_cast<uint32_t*>(&v);
}

// ---------------------------------------------------------------------------
// HMMA GEMM fp16 single-A-term: C = Ah @ Wh^T + bias
// MODE 1 (QKV): fp16 output; skip M-tiles fully beyond round_up(len,128).
// MODE 2 (proj): fp32 output; dead tiles write bias rows and exit.
// 128x128 tile, k-chunk 16, 3-stage cp.async (Ah|Wh), 2 CTAs/SM.
// ---------------------------------------------------------------------------
#define GTILE_B    6144
#define GSTAGE_B   (2 * GTILE_B)
#define GEMM_SMEM  (3 * GSTAGE_B)      // 36864

template <int MODE>
__global__ __launch_bounds__(256, 2) void gemm_fp16(
    const __half* __restrict__ Ah, const __half* __restrict__ Wh,
    const float* __restrict__ bias,
    float* __restrict__ Cf, __half* __restrict__ Ch,
    const int* __restrict__ lenp,
    int M, int N, int K)
{
    extern __shared__ char sm[];
    const int tid = threadIdx.x;
    const int bm = blockIdx.y * 128;
    const int bn = blockIdx.x * 128;

    {
        const int len = lenp[bm >> 11];
        const int lim = (len + 127) & ~127;
        if ((bm & 2047) >= lim) {
            if (MODE == 2) {
                const int c4 = (tid & 31) * 4;
                const int rb = tid >> 5;
                float4 bv = *(const float4*)(bias + bn + c4);
                #pragma unroll
                for (int rr = 0; rr < 16; rr++) {
                    int row = bm + rb * 16 + rr;
                    *(float4*)(Cf + (size_t)row * N + bn + c4) = bv;
                }
            }
            return;
        }
    }

    const int warp = tid >> 5, lane = tid & 31;
    const int moff = (warp >> 1) * 32;
    const int noff = (warp & 1) * 64;

    float acc[2][8][4];
    #pragma unroll
    for (int a = 0; a < 2; a++)
        #pragma unroll
        for (int b = 0; b < 8; b++)
            #pragma unroll
            for (int c = 0; c < 4; c++) acc[a][b][c] = 0.f;

    const int r_ld = tid >> 1, half8 = (tid & 1) * 8;
    auto issue = [&](int c, int s) {
        const int k0 = c << 4;
        char* st = sm + s * GSTAGE_B;
        uint32_t d = smem_u32(st + (r_ld * 24 + half8) * 2);
        CP_ASYNC16(d,           Ah + (size_t)(bm + r_ld) * K + k0 + half8);
        CP_ASYNC16(d + GTILE_B, Wh + (size_t)(bn + r_ld) * K + k0 + half8);
        CP_COMMIT();
    };

    const int nk = K >> 4;
    issue(0, 0);
    issue(1, 1);

    const int arow = moff + (lane & 7) + 8 * ((lane >> 3) & 1);
    const int acol = 8 * (lane >> 4);
    const int wrow_l = (lane & 7);
    const int wcol = 8 * ((lane >> 3) & 1);

    int s = 0;
    for (int c = 0; c < nk; c++) {
        CP_WAIT1();
        __syncthreads();
        if (c + 2 < nk) issue(c + 2, (s + 2 >= 3) ? s - 1 : s + 2);
        else CP_COMMIT();

        char* st = sm + s * GSTAGE_B;
        uint32_t ah[2][4];
        #pragma unroll
        for (int mb = 0; mb < 2; mb++)
            LDSM_X4(ah[mb], smem_u32(st + ((arow + mb * 16) * 24 + acol) * 2));
        #pragma unroll
        for (int nb = 0; nb < 8; nb++) {
            int wr = noff + nb * 8 + wrow_l;
            uint32_t bh0, bh1;
            LDSM_X2(bh0, bh1, smem_u32(st + GTILE_B + (wr * 24 + wcol) * 2));
            #pragma unroll
            for (int mb = 0; mb < 2; mb++)
                MMA16816(acc[mb][nb], ah[mb], bh0, bh1);
        }
        s = (s + 1 >= 3) ? 0 : s + 1;
    }

    const int r0 = lane >> 2, c0 = (lane & 3) * 2;
    #pragma unroll
    for (int mb = 0; mb < 2; mb++)
        #pragma unroll
        for (int nb = 0; nb < 8; nb++) {
            int row = bm + moff + mb * 16 + r0;
            int col = bn + noff + nb * 8 + c0;
            float b0v = bias[col], b1v = bias[col + 1];
            if (MODE == 1) {
                *(uint32_t*)(Ch + (size_t)row * N + col) =
                    pack_hi(acc[mb][nb][0] + b0v, acc[mb][nb][1] + b1v);
                *(uint32_t*)(Ch + (size_t)(row + 8) * N + col) =
                    pack_hi(acc[mb][nb][2] + b0v, acc[mb][nb][3] + b1v);
            } else {
                float2 v0 = make_float2(acc[mb][nb][0] + b0v, acc[mb][nb][1] + b1v);
                *(float2*)(Cf + (size_t)row * N + col) = v0;
                float2 v1 = make_float2(acc[mb][nb][2] + b0v, acc[mb][nb][3] + b1v);
                *(float2*)(Cf + (size_t)(row + 8) * N + col) = v1;
            }
        }
}

// ---------------------------------------------------------------------------
// per-batch valid length
// ---------------------------------------------------------------------------
__global__ void compute_len(const int* __restrict__ am, int* __restrict__ out) {
    __shared__ int red[8];
    int b = blockIdx.x, acc = 0;
    for (int i = threadIdx.x; i < T_; i += 256) acc += am[b * T_ + i];
    #pragma unroll
    for (int o = 16; o; o >>= 1) acc += __shfl_xor_sync(0xffffffffu, acc, o);
    if ((threadIdx.x & 31) == 0) red[threadIdx.x >> 5] = acc;
    __syncthreads();
    if (threadIdx.x == 0) {
        int v = 0;
        #pragma unroll
        for (int i = 0; i < 8; i++) v += red[i];
        out[b] = v;
    }
}

// ---------------------------------------------------------------------------
// fp32 -> fp16
// ---------------------------------------------------------------------------
__global__ __launch_bounds__(256) void conv_h(
    const float* __restrict__ s, __half* __restrict__ h, int n)
{
    int i = (blockIdx.x * 256 + threadIdx.x) * 4;
    if (i >= n) return;
    float4 v = *(const float4*)(s + i);
    *(uint32_t*)(h + i)     = pack_hi(v.x, v.y);
    *(uint32_t*)(h + i + 2) = pack_hi(v.z, v.w);
}

// ---------------------------------------------------------------------------
// qkv fp16 [M, 3C] -> q/k/v fp16 [B,H,T,64] (pure relayout); skips dead rows
// ---------------------------------------------------------------------------
__global__ __launch_bounds__(256) void qkv_split(
    const __half* __restrict__ qkv, const int* __restrict__ lenp,
    __half* __restrict__ qh, __half* __restrict__ kh, __half* __restrict__ vh)
{
    size_t i = ((size_t)blockIdx.x * 256 + threadIdx.x) * 8;   // 8 halves
    int row = (int)(i / C3_), col = (int)(i % C3_);
    int b = row >> 11, t = row & 2047;
    int len = lenp[b];
    if (t >= ((len + 127) & ~127)) return;
    uint4 v = *(const uint4*)(qkv + i);
    int which = col >> 10;
    int hc = col & 1023;
    int head = hc >> 6, d = hc & 63;
    size_t idx = ((((size_t)b * H_) + head) * T_ + t) * HD_ + d;
    __half* O = (which == 0) ? qh : (which == 1) ? kh : vh;
    *(uint4*)(O + idx) = v;
}

// ---------------------------------------------------------------------------
// Pure-fp16 tensor-core flash attention (fp32 accumulate):
//   S = Qh Kh^T ; O += Ph Vh.
// LPT order, masked-tile early exit, uniform depth-2 cp.async pipeline.
// ---------------------------------------------------------------------------
#define PITCH 72
#define OPB   (64 * PITCH * 2)
#define BUF_B (2 * OPB)
#define ATTN_SMEM (2 * BUF_B)

__global__ __launch_bounds__(256, 1) void flash_attn_tc(
    const __half* __restrict__ qh, const __half* __restrict__ kh,
    const __half* __restrict__ vh,
    const int* __restrict__ lenp, __half* __restrict__ yh)
{
    extern __shared__ char smdyn[];

    const int b = blockIdx.z, h = blockIdx.y;
    const int qt = (int)(gridDim.x - 1 - blockIdx.x);   // LPT: heavy first
    const int q0 = qt * 128;
    const int tid = threadIdx.x;
    const int warp = tid >> 5, lane = tid & 31;
    const int len = lenp[b];
    const size_t bh = ((size_t)b * H_ + h) * T_ * HD_;

    if (q0 >= len) {
        const size_t ybase = ((size_t)b * T_ + q0) * C_ + h * HD_;
        const uint2 z = make_uint2(0u, 0u);
        #pragma unroll
        for (int t = 0; t < 4; t++) {
            int e = tid + t * 256;
            int r = e >> 3, c4 = (e & 7) * 8;
            *(uint2*)(yh + ybase + (size_t)r * C_ + c4) = z;
            *(uint2*)(yh + ybase + (size_t)r * C_ + c4 + 4) = z;
        }
        return;
    }

    const int kt_len = (len + 63) >> 6;
    const int kt_max = min(2 * qt + 1, kt_len - 1);

    auto issue_kv = [&](int kt, int buf) {
        char* st = smdyn + buf * BUF_B;
        const size_t kbase = bh + (size_t)(kt * 64) * HD_;
        #pragma unroll
        for (int t = 0; t < 4; t++) {
            int e = tid + t * 256;
            int op = e >> 9;
            int idx = e & 511;
            int r = idx >> 3, c16 = idx & 7;
            const __half* src = op ? vh : kh;
            CP_ASYNC16(smem_u32(st + op * OPB + (r * PITCH + c16 * 8) * 2),
                       src + kbase + (size_t)r * HD_ + c16 * 8);
        }
        CP_COMMIT();
    };

    {
        const size_t qbase = bh + (size_t)q0 * HD_;
        #pragma unroll
        for (int t = 0; t < 4; t++) {
            int e = tid + t * 256;
            int r = e >> 3, c16 = e & 7;
            CP_ASYNC16(smem_u32(smdyn + (r * PITCH + c16 * 8) * 2),
                       qh + qbase + (size_t)r * HD_ + c16 * 8);
        }
        CP_COMMIT();
    }
    issue_kv(0, 1);
    CP_WAIT1();
    __syncthreads();

    uint32_t qf[4][4];
    {
        __half* Qh = (__half*)smdyn;
        int row = warp * 16 + (lane & 7) + 8 * ((lane >> 3) & 1);
        #pragma unroll
        for (int ks = 0; ks < 4; ks++) {
            int col = ks * 16 + 8 * (lane >> 4);
            LDSM_X4(qf[ks], smem_u32(Qh + row * PITCH + col));
        }
    }
    __syncthreads();
    issue_kv(min(1, kt_max), 0);

    float m_[2] = {-1e30f, -1e30f}, l_[2] = {0.f, 0.f};
    float O[8][4] = {};

    const int wrow_max = q0 + warp * 16 + 15;
    const int r0 = lane >> 2, cb = (lane & 3) * 2;
    const int row0 = q0 + warp * 16 + r0, row1 = row0 + 8;

    for (int kt = 0; kt <= kt_max; kt++) {
        const int k0 = kt * 64;
        CP_WAIT1();
        __syncthreads();

        char* st = smdyn + ((kt + 1) & 1) * BUF_B;
        __half* Kh = (__half*)st;
        __half* Vh = (__half*)(st + OPB);

        if (k0 <= wrow_max) {
            float S[8][4] = {};
            {
                int krow = (lane & 7);
                int kcol8 = 8 * ((lane >> 3) & 1);
                #pragma unroll
                for (int nb = 0; nb < 8; nb++) {
                    #pragma unroll
                    for (int ks = 0; ks < 4; ks++) {
                        uint32_t bh0, bh1;
                        LDSM_X2(bh0, bh1, smem_u32(Kh + (nb * 8 + krow) * PITCH + ks * 16 + kcol8));
                        MMA16816(S[nb], qf[ks], bh0, bh1);
                    }
                }
            }

            float ml0 = -1e30f, ml1 = -1e30f;
            #pragma unroll
            for (int nb = 0; nb < 8; nb++) {
                int c0 = k0 + nb * 8 + cb;
                S[nb][0] = (c0     <= row0 && c0     < len) ? S[nb][0] * 0.125f : -1e30f;
                S[nb][1] = (c0 + 1 <= row0 && c0 + 1 < len) ? S[nb][1] * 0.125f : -1e30f;
                S[nb][2] = (c0     <= row1 && c0     < len) ? S[nb][2] * 0.125f : -1e30f;
                S[nb][3] = (c0 + 1 <= row1 && c0 + 1 < len) ? S[nb][3] * 0.125f : -1e30f;
                ml0 = fmaxf(ml0, fmaxf(S[nb][0], S[nb][1]));
                ml1 = fmaxf(ml1, fmaxf(S[nb][2], S[nb][3]));
            }
            ml0 = fmaxf(ml0, __shfl_xor_sync(0xffffffffu, ml0, 1));
            ml0 = fmaxf(ml0, __shfl_xor_sync(0xffffffffu, ml0, 2));
            ml1 = fmaxf(ml1, __shfl_xor_sync(0xffffffffu, ml1, 1));
            ml1 = fmaxf(ml1, __shfl_xor_sync(0xffffffffu, ml1, 2));
            float mn0 = fmaxf(m_[0], ml0), mn1 = fmaxf(m_[1], ml1);
            float corr0 = __expf(m_[0] - mn0), corr1 = __expf(m_[1] - mn1);
            float ls0 = 0.f, ls1 = 0.f;
            #pragma unroll
            for (int nb = 0; nb < 8; nb++) {
                S[nb][0] = __expf(S[nb][0] - mn0); ls0 += S[nb][0];
                S[nb][1] = __expf(S[nb][1] - mn0); ls0 += S[nb][1];
                S[nb][2] = __expf(S[nb][2] - mn1); ls1 += S[nb][2];
                S[nb][3] = __expf(S[nb][3] - mn1); ls1 += S[nb][3];
            }
            ls0 += __shfl_xor_sync(0xffffffffu, ls0, 1);
            ls0 += __shfl_xor_sync(0xffffffffu, ls0, 2);
            ls1 += __shfl_xor_sync(0xffffffffu, ls1, 1);
            ls1 += __shfl_xor_sync(0xffffffffu, ls1, 2);
            l_[0] = l_[0] * corr0 + ls0;
            l_[1] = l_[1] * corr1 + ls1;
            m_[0] = mn0; m_[1] = mn1;
            #pragma unroll
            for (int nb = 0; nb < 8; nb++) {
                O[nb][0] *= corr0; O[nb][1] *= corr0;
                O[nb][2] *= corr1; O[nb][3] *= corr1;
            }

            {
                int vrow8 = (lane & 7) + 8 * ((lane >> 3) & 1);
                #pragma unroll
                for (int ks = 0; ks < 4; ks++) {
                    uint32_t ph[4];
                    ph[0] = pack_hi(S[2 * ks][0], S[2 * ks][1]);
                    ph[1] = pack_hi(S[2 * ks][2], S[2 * ks][3]);
                    ph[2] = pack_hi(S[2 * ks + 1][0], S[2 * ks + 1][1]);
                    ph[3] = pack_hi(S[2 * ks + 1][2], S[2 * ks + 1][3]);
                    #pragma unroll
                    for (int nb = 0; nb < 8; nb++) {
                        uint32_t vh0, vh1;
                        LDSM_X2T(vh0, vh1, smem_u32(Vh + (ks * 16 + vrow8) * PITCH + nb * 8));
                        MMA16816(O[nb], ph, vh0, vh1);
                    }
                }
            }
        }

        __syncthreads();
        issue_kv(min(kt + 2, kt_max), (kt + 1) & 1);
    }

    float inv0 = (row0 < len && l_[0] > 0.f) ? (1.f / l_[0]) : 0.f;
    float inv1 = (row1 < len && l_[1] > 0.f) ? (1.f / l_[1]) : 0.f;
    size_t rb0 = ((size_t)b * T_ + row0) * C_;
    size_t rb1 = ((size_t)b * T_ + row1) * C_;
    #pragma unroll
    for (int nb = 0; nb < 8; nb++) {
        int hcol = h * HD_ + nb * 8 + cb;
        *(uint32_t*)(yh + rb0 + hcol) = pack_hi(O[nb][0] * inv0, O[nb][1] * inv0);
        *(uint32_t*)(yh + rb1 + hcol) = pack_hi(O[nb][2] * inv1, O[nb][3] * inv1);
    }
}

// ---------------------------------------------------------------------------
extern "C" void kernel_launch(void* const* d_in, const int* in_sizes, int n_in,
                              void* d_out, int out_size)
{
    const float* x    = (const float*)d_in[0];
    const int*   am   = (const int*)  d_in[1];
    const float* Wqkv = (const float*)d_in[2];
    const float* bqkv = (const float*)d_in[3];
    const float* Wo   = (const float*)d_in[4];
    const float* bo   = (const float*)d_in[5];
    float* out = (float*)d_out;

    __half *qkv16, *xh, *wqh, *woh, *yh, *qh, *kh, *vh;
    int* lenp;
    cudaGetSymbolAddress((void**)&qkv16, g_qkv16);
    cudaGetSymbolAddress((void**)&xh, g_xh);
    cudaGetSymbolAddress((void**)&wqh, g_wqh);
    cudaGetSymbolAddress((void**)&woh, g_woh);
    cudaGetSymbolAddress((void**)&yh, g_yh);
    cudaGetSymbolAddress((void**)&qh, g_qh);
    cudaGetSymbolAddress((void**)&kh, g_kh);
    cudaGetSymbolAddress((void**)&vh, g_vh);
    cudaGetSymbolAddress((void**)&lenp, g_len);

    cudaFuncSetAttribute((const void*)gemm_fp16<1>,
                         cudaFuncAttributeMaxDynamicSharedMemorySize, GEMM_SMEM);
    cudaFuncSetAttribute((const void*)gemm_fp16<2>,
                         cudaFuncAttributeMaxDynamicSharedMemorySize, GEMM_SMEM);
    cudaFuncSetAttribute(flash_attn_tc, cudaFuncAttributeMaxDynamicSharedMemorySize, ATTN_SMEM);

    int nx = M_ * C_, nwq = C3_ * C_, nwo = C_ * C_;
    compute_len<<<B_, 256>>>(am, lenp);
    conv_h<<<nx  / 1024, 256>>>(x,    xh,  nx);
    conv_h<<<nwq / 1024, 256>>>(Wqkv, wqh, nwq);
    conv_h<<<nwo / 1024, 256>>>(Wo,   woh, nwo);

    gemm_fp16<1><<<dim3(C3_ / 128, M_ / 128), 256, GEMM_SMEM>>>(
        xh, wqh, bqkv, nullptr, qkv16, lenp, M_, C3_, C_);
    qkv_split<<<(int)((size_t)M_ * C3_ / 2048), 256>>>(
        qkv16, lenp, qh, kh, vh);
    flash_attn_tc<<<dim3(T_ / 128, H_, B_), 256, ATTN_SMEM>>>(
        qh, kh, vh, lenp, yh);
    gemm_fp16<2><<<dim3(C_ / 128, M_ / 128), 256, GEMM_SMEM>>>(
        yh, woh, bo, out, nullptr, lenp, M_, C_, C_);
}